// round 9
// baseline (speedup 1.0000x reference)
#include <cuda_runtime.h>
#include <cuda_bf16.h>
#include <math.h>

#define B_    8
#define TS    2
#define SEQ   720
#define SEQP  736
#define ENC   862
#define MARKD 4
#define NTOK  866
#define D     256
#define NH    8
#define EH    32
#define DFF   512
#define DB    720
#define LAYERS 2
#define EPS   1e-5f
#define MROWS (B_*NTOK)   // 6928
#define MD    ((size_t)MROWS*D)
#define XN    ((size_t)MROWS*SEQP)

typedef __nv_bfloat16 bf16;

// ---------------- fp32 scratch ----------------
__device__ float g_mean[B_*ENC], g_std[B_*ENC];
__device__ float g_h[MD], g_xatt[MD], g_xln[MD], g_hh[MD];
__device__ float g_out[(size_t)MROWS*DB];

// ---------------- bf16 hi/lo planes (lo at +n) ----------------
__device__ __align__(16) bf16 p_xin[2*XN];
__device__ __align__(16) bf16 p_h  [2*MD];
__device__ __align__(16) bf16 p_qkv[2*3*MD];
__device__ __align__(16) bf16 p_att[2*MD];
__device__ __align__(16) bf16 p_xln[2*MD];
__device__ __align__(16) bf16 p_y1 [2*(size_t)MROWS*DFF];
__device__ __align__(16) bf16 p_xs [2*MD];
__device__ __align__(16) bf16 p_xatt[2*MD];
__device__ __align__(16) bf16 p_y  [2*MD];
// weights
__device__ __align__(16) bf16 p_embW[2*256*SEQP];
__device__ __align__(16) bf16 p_Wq[2*LAYERS*D*D], p_Wk[2*LAYERS*D*D], p_Wv[2*LAYERS*D*D];
__device__ __align__(16) bf16 p_Wo[2*LAYERS*D*D], p_W3[2*LAYERS*D*D], p_W4[2*LAYERS*D*D];
__device__ __align__(16) bf16 p_W1[2*LAYERS*DFF*D], p_W2[2*LAYERS*D*DFF];
__device__ __align__(16) bf16 p_W5[2*LAYERS*DB*2*D], p_W6[2*LAYERS*DB*2*D];

// ---------------- helpers ----------------
__device__ __forceinline__ void splitv(float x, bf16& h, bf16& l){
    h = __float2bfloat16(x);
    l = __float2bfloat16(x - __bfloat162float(h));
}
__device__ __forceinline__ unsigned pack2u(bf16 a, bf16 b){
    __nv_bfloat162 t = __halves2bfloat162(a, b);
    return *(unsigned*)&t;
}
__device__ __forceinline__ void mma_bf16(float c[4], const unsigned a[4], const unsigned b[2]){
    asm volatile("mma.sync.aligned.m16n8k16.row.col.f32.bf16.bf16.f32 "
                 "{%0,%1,%2,%3}, {%4,%5,%6,%7}, {%8,%9}, {%0,%1,%2,%3};\n"
                 : "+f"(c[0]), "+f"(c[1]), "+f"(c[2]), "+f"(c[3])
                 : "r"(a[0]), "r"(a[1]), "r"(a[2]), "r"(a[3]),
                   "r"(b[0]), "r"(b[1]));
}
__device__ __forceinline__ void ldsm_x4(unsigned r[4], unsigned addr){
    asm volatile("ldmatrix.sync.aligned.m8n8.x4.shared.b16 {%0,%1,%2,%3}, [%4];\n"
                 : "=r"(r[0]), "=r"(r[1]), "=r"(r[2]), "=r"(r[3]) : "r"(addr));
}
__device__ __forceinline__ void ldsm_x4t(unsigned r[4], unsigned addr){
    asm volatile("ldmatrix.sync.aligned.m8n8.x4.trans.shared.b16 {%0,%1,%2,%3}, [%4];\n"
                 : "=r"(r[0]), "=r"(r[1]), "=r"(r[2]), "=r"(r[3]) : "r"(addr));
}
__device__ __forceinline__ void cp16(unsigned dst, const void* src, bool p){
    int sz = p ? 16 : 0;
    asm volatile("cp.async.cg.shared.global [%0], [%1], 16, %2;\n"
                 :: "r"(dst), "l"(src), "r"(sz));
}
__device__ __forceinline__ void cpcommit(){ asm volatile("cp.async.commit_group;\n"); }
template<int N> __device__ __forceinline__ void cpwait(){
    asm volatile("cp.async.wait_group %0;\n" :: "n"(N));
}
__device__ __forceinline__ float gelu_f(float x){
    return 0.5f*x*(1.f + erff(x*0.70710678118654752f));
}
__device__ __forceinline__ float sigmoid_f(float x){
    return 1.f/(1.f + expf(-x));
}
// reduce (a, b) simultaneously across block
__device__ __forceinline__ float2 blockReduce2(float a, float b){
    __shared__ float2 sh[33];
    int lane = threadIdx.x & 31, wid = threadIdx.x >> 5;
    __syncthreads();
    #pragma unroll
    for (int o = 16; o; o >>= 1){
        a += __shfl_down_sync(0xffffffffu, a, o);
        b += __shfl_down_sync(0xffffffffu, b, o);
    }
    if (lane == 0) sh[wid] = make_float2(a, b);
    __syncthreads();
    if (wid == 0){
        int nw = blockDim.x >> 5;
        float2 v = (lane < nw) ? sh[lane] : make_float2(0.f, 0.f);
        a = v.x; b = v.y;
        #pragma unroll
        for (int o = 16; o; o >>= 1){
            a += __shfl_down_sync(0xffffffffu, a, o);
            b += __shfl_down_sync(0xffffffffu, b, o);
        }
        if (lane == 0) sh[32] = make_float2(a, b);
    }
    __syncthreads();
    return sh[32];
}

// ---------------- weight split (batched) ----------------
struct WSArgs { const float* s[10]; bf16* h[10]; bf16* l[10]; int n[10]; };
__global__ void wsplit_all(WSArgs w){
    int z = blockIdx.y;
    int n = w.n[z];
    const float* src = w.s[z];
    bf16* hh = w.h[z]; bf16* ll = w.l[z];
    for (int i = blockIdx.x*blockDim.x + threadIdx.x; i < n; i += gridDim.x*blockDim.x)
        splitv(src[i], hh[i], ll[i]);
}
__global__ void wsplit_pad(const float* __restrict__ s, bf16* __restrict__ h,
                           bf16* __restrict__ l, int rows, int K, int Kp){
    size_t i = (size_t)blockIdx.x*blockDim.x + threadIdx.x;
    size_t total = (size_t)rows*Kp;
    if (i >= total) return;
    int c = (int)(i % Kp); int r = (int)(i / Kp);
    float v = (c < K) ? s[(size_t)r*K + c] : 0.f;
    splitv(v, h[i], l[i]);
}

// ---------------- input standardization ----------------
__global__ void stats_kernel(const float* __restrict__ mbx, int t){
    int b = blockIdx.y;
    int n = blockIdx.x * blockDim.x + threadIdx.x;
    if (n >= ENC) return;
    const float* base = mbx + ((size_t)(b*TS + t)*SEQ)*ENC + n;
    float s = 0.f, ss = 0.f;
    for (int i = 0; i < SEQ; i++){
        float v = base[(size_t)i*ENC];
        s += v; ss += v*v;
    }
    float m = s * (1.f/SEQ);
    float var = ss * (1.f/SEQ) - m*m;
    g_mean[b*ENC + n] = m;
    g_std [b*ENC + n] = sqrtf(var + EPS);
}

// transposed tiled build of xin planes: read coalesced over n, write over s
__global__ __launch_bounds__(256) void xin_kernel(const float* __restrict__ mbx,
                                                  const float* __restrict__ mbxm, int t){
    __shared__ float tile[32][33];
    const int b = blockIdx.z;
    const int s0 = blockIdx.x*32, n0 = blockIdx.y*32;
    const int tx = threadIdx.x & 31, ty = threadIdx.x >> 5;
    #pragma unroll
    for (int i = 0; i < 4; i++){
        int s = s0 + ty + i*8, n = n0 + tx;
        float v = 0.f;
        if (s < SEQ && n < NTOK){
            if (n < ENC){
                v = mbx[((size_t)(b*TS + t)*SEQ + s)*ENC + n];
                v = (v - g_mean[b*ENC + n]) / g_std[b*ENC + n];
            } else {
                v = mbxm[((size_t)(b*TS + t)*SEQ + s)*MARKD + (n - ENC)];
            }
        }
        tile[ty + i*8][tx] = v;
    }
    __syncthreads();
    #pragma unroll
    for (int i = 0; i < 4; i++){
        int n = n0 + ty + i*8, s = s0 + tx;
        if (n < NTOK && s < SEQP){
            size_t idx = ((size_t)b*NTOK + n)*SEQP + s;
            splitv(tile[tx][ty + i*8], p_xin[idx], p_xin[XN + idx]);
        }
    }
}

// =============== MMA GEMM: C = A @ W^T + bias (bf16 planes, cp.async) =====
// ACT 0: plain; 1: gelu; 2: emit y planes + (xsub - y) planes
struct GemmArgs {
    const bf16 *aH[3], *aL[3], *wH[3], *wL[3];
    const float* bias[3];
    float* C[3];
    bf16 *cH[3], *cL[3];
    const float* xsub[3];
    bf16 *c2H[3], *c2L[3];
};

template<int ACT>
__global__ __launch_bounds__(256)
void mma_gemm(GemmArgs p, int M, int N, int K, int tilesN, int tpz, int nTiles){
    extern __shared__ __align__(16) char smraw[];
    bf16* sAh = (bf16*)smraw;            // [2][128][40]
    bf16* sAl = sAh + 2*128*40;
    bf16* sBh = sAl + 2*128*40;          // [2][64][40]
    bf16* sBl = sBh + 2*64*40;
    const unsigned aHiB = (unsigned)__cvta_generic_to_shared(sAh);
    const unsigned aLoB = (unsigned)__cvta_generic_to_shared(sAl);
    const unsigned bHiB = (unsigned)__cvta_generic_to_shared(sBh);
    const unsigned bLoB = (unsigned)__cvta_generic_to_shared(sBl);

    const int tid = threadIdx.x;
    const int lane = tid & 31, w = tid >> 5;
    const int wm = (w >> 1)*32, wn = (w & 1)*32;
    const int t4 = lane >> 3, lr = lane & 7;
    const int ldr = tid >> 2, ldc = (tid & 3)*8;

    for (int t = blockIdx.x; t < nTiles; t += gridDim.x){
        const int z  = t / tpz;
        const int rr = t - z*tpz;
        const int bm = (rr / tilesN)*128, bn = (rr % tilesN)*64;
        const bf16* __restrict__ aHp = p.aH[z];
        const bf16* __restrict__ aLp = p.aL[z];
        const bf16* __restrict__ wHp = p.wH[z];
        const bf16* __restrict__ wLp = p.wL[z];
        const float* __restrict__ bias = p.bias[z];
        float* Cp = p.C[z];
        bf16* cHp = p.cH[z];
        bf16* cLp = p.cL[z];

        float acc[2][4][4];
        #pragma unroll
        for (int i = 0; i < 2; i++)
            #pragma unroll
            for (int j = 0; j < 4; j++)
                #pragma unroll
                for (int q = 0; q < 4; q++) acc[i][j][q] = 0.f;

        auto loadst = [&](int s, int k0){
            #pragma unroll
            for (int rep = 0; rep < 2; rep++){
                int r = ldr + rep*64;
                int gm = bm + r;
                bool pr = gm < M;
                size_t so = (size_t)(pr ? gm : 0)*K + k0 + ldc;
                unsigned doff = (unsigned)(((s*128 + r)*40 + ldc)*2);
                cp16(aHiB + doff, aHp + so, pr);
                cp16(aLoB + doff, aLp + so, pr);
            }
            {
                int gn = bn + ldr;
                bool pn = gn < N;
                size_t so = (size_t)(pn ? gn : 0)*K + k0 + ldc;
                unsigned doff = (unsigned)(((s*64 + ldr)*40 + ldc)*2);
                cp16(bHiB + doff, wHp + so, pn);
                cp16(bLoB + doff, wLp + so, pn);
            }
            cpcommit();
        };

        loadst(0, 0);
        int buf = 0;
        const int KT = K >> 5;
        for (int kt = 0; kt < KT; kt++){
            if (kt + 1 < KT){ loadst(buf ^ 1, (kt+1)*32); cpwait<1>(); }
            else cpwait<0>();
            __syncthreads();

            #pragma unroll
            for (int kh = 0; kh < 32; kh += 16){
                unsigned ah[2][4], al[2][4], bh[4][2], bl[4][2];
                #pragma unroll
                for (int mt = 0; mt < 2; mt++){
                    int arow = wm + mt*16 + (t4 & 1)*8 + lr;
                    unsigned off = (unsigned)((((buf*128) + arow)*40 + kh + (t4 >> 1)*8)*2);
                    ldsm_x4(ah[mt], aHiB + off);
                    ldsm_x4(al[mt], aLoB + off);
                }
                #pragma unroll
                for (int pr2 = 0; pr2 < 2; pr2++){
                    int brow = wn + pr2*16 + (t4 >> 1)*8 + lr;
                    unsigned off = (unsigned)((((buf*64) + brow)*40 + kh + (t4 & 1)*8)*2);
                    unsigned th[4], tl[4];
                    ldsm_x4(th, bHiB + off);
                    ldsm_x4(tl, bLoB + off);
                    bh[pr2*2][0] = th[0]; bh[pr2*2][1] = th[1];
                    bh[pr2*2+1][0] = th[2]; bh[pr2*2+1][1] = th[3];
                    bl[pr2*2][0] = tl[0]; bl[pr2*2][1] = tl[1];
                    bl[pr2*2+1][0] = tl[2]; bl[pr2*2+1][1] = tl[3];
                }
                #pragma unroll
                for (int mt = 0; mt < 2; mt++)
                    #pragma unroll
                    for (int nt = 0; nt < 4; nt++){
                        mma_bf16(acc[mt][nt], ah[mt], bh[nt]);
                        mma_bf16(acc[mt][nt], ah[mt], bl[nt]);
                        mma_bf16(acc[mt][nt], al[mt], bh[nt]);
                    }
            }
            __syncthreads();
            buf ^= 1;
        }

        #pragma unroll
        for (int mt = 0; mt < 2; mt++)
            #pragma unroll
            for (int nt = 0; nt < 4; nt++){
                int row0 = bm + wm + mt*16 + (lane >> 2);
                int col  = bn + wn + nt*8 + (lane & 3)*2;
                if (col >= N) continue;
                float b0 = bias[col], b1 = bias[col + 1];
                float v0 = acc[mt][nt][0] + b0, v1 = acc[mt][nt][1] + b1;
                float v2 = acc[mt][nt][2] + b0, v3 = acc[mt][nt][3] + b1;
                if (ACT == 1){
                    v0 = gelu_f(v0); v1 = gelu_f(v1);
                    v2 = gelu_f(v2); v3 = gelu_f(v3);
                }
                if (row0 < M){
                    size_t ix = (size_t)row0*N + col;
                    if (Cp){ Cp[ix] = v0; Cp[ix + 1] = v1; }
                    if (cHp){
                        bf16 h0,l0,h1,l1; splitv(v0,h0,l0); splitv(v1,h1,l1);
                        *(__nv_bfloat162*)(cHp + ix) = __halves2bfloat162(h0,h1);
                        *(__nv_bfloat162*)(cLp + ix) = __halves2bfloat162(l0,l1);
                    }
                    if (ACT == 2){
                        float x0 = p.xsub[z][ix], x1 = p.xsub[z][ix + 1];
                        bf16 h0,l0,h1,l1; splitv(x0 - v0,h0,l0); splitv(x1 - v1,h1,l1);
                        *(__nv_bfloat162*)(p.c2H[z] + ix) = __halves2bfloat162(h0,h1);
                        *(__nv_bfloat162*)(p.c2L[z] + ix) = __halves2bfloat162(l0,l1);
                    }
                }
                if (row0 + 8 < M){
                    size_t ix = (size_t)(row0+8)*N + col;
                    if (Cp){ Cp[ix] = v2; Cp[ix + 1] = v3; }
                    if (cHp){
                        bf16 h2,l2,h3,l3; splitv(v2,h2,l2); splitv(v3,h3,l3);
                        *(__nv_bfloat162*)(cHp + ix) = __halves2bfloat162(h2,h3);
                        *(__nv_bfloat162*)(cLp + ix) = __halves2bfloat162(l2,l3);
                    }
                    if (ACT == 2){
                        float x2 = p.xsub[z][ix], x3 = p.xsub[z][ix + 1];
                        bf16 h2,l2,h3,l3; splitv(x2 - v2,h2,l2); splitv(x3 - v3,h3,l3);
                        *(__nv_bfloat162*)(p.c2H[z] + ix) = __halves2bfloat162(h2,h3);
                        *(__nv_bfloat162*)(p.c2L[z] + ix) = __halves2bfloat162(l2,l3);
                    }
                }
            }
    }
}

// =============== fused dual GEMM (BM=128): o = sig(A W1^T+b1)*(A W2^T+b2) ==
// A source switches at kSplit (concat fusion).
// MODE 0: Cout = o ;  MODE 1: Cout = sub ? (o - Cout) : o
struct Gemm2Args {
    const bf16 *a0H, *a0L, *a1H, *a1L;
    int kSplit, aStride;
    const bf16 *w1H, *w1L, *w2H, *w2L;
    const float *b1, *b2;
    float* Cout;
    int sub;
};

template<int MODE>
__global__ __launch_bounds__(256)
void mma_gemm2(Gemm2Args p, int M, int N, int K, int tilesN, int nTiles){
    extern __shared__ __align__(16) char smraw[];
    bf16* sm = (bf16*)smraw;
    const unsigned smB = (unsigned)__cvta_generic_to_shared(sm);
    // elements: A(stage s, plane q): (s*2+q)*5120 (128x40 each)
    //           B: 20480 + (s*4 + g*2 + q)*2560 (64x40 each)
    const int tid = threadIdx.x;
    const int lane = tid & 31, w = tid >> 5;
    const int wm = (w >> 1)*32, wn = (w & 1)*32;
    const int t4 = lane >> 3, lr = lane & 7;
    const int ldr = tid >> 2, ldc = (tid & 3)*8;

    for (int t = blockIdx.x; t < nTiles; t += gridDim.x){
        const int bm = (t / tilesN)*128, bn = (t % tilesN)*64;

        float acc[2][2][4][4];
        #pragma unroll
        for (int g = 0; g < 2; g++)
            #pragma unroll
            for (int mt = 0; mt < 2; mt++)
                #pragma unroll
                for (int j = 0; j < 4; j++)
                    #pragma unroll
                    for (int q = 0; q < 4; q++) acc[g][mt][j][q] = 0.f;

        auto loadst = [&](int s, int k0){
            const bf16* aH = (k0 < p.kSplit) ? p.a0H : p.a1H;
            const bf16* aL = (k0 < p.kSplit) ? p.a0L : p.a1L;
            int kk = (k0 < p.kSplit) ? k0 : k0 - p.kSplit;
            #pragma unroll
            for (int rep = 0; rep < 2; rep++){
                int r = ldr + rep*64;
                int gm = bm + r;
                bool pr = gm < M;
                size_t soA = (size_t)(pr ? gm : 0)*p.aStride + kk + ldc;
                unsigned dA = (unsigned)((s*2*5120 + r*40 + ldc)*2);
                cp16(smB + dA,            aH + soA, pr);
                cp16(smB + dA + 5120*2,   aL + soA, pr);
            }
            {
                int gn = bn + ldr;
                bool pn = gn < N;
                size_t soB = (size_t)(pn ? gn : 0)*K + k0 + ldc;
                unsigned dB = (unsigned)(((20480 + s*4*2560) + ldr*40 + ldc)*2);
                cp16(smB + dB,             p.w1H + soB, pn);
                cp16(smB + dB + 2560*2,    p.w1L + soB, pn);
                cp16(smB + dB + 2*2560*2,  p.w2H + soB, pn);
                cp16(smB + dB + 3*2560*2,  p.w2L + soB, pn);
            }
            cpcommit();
        };

        loadst(0, 0);
        int buf = 0;
        const int KT = K >> 5;
        for (int kt = 0; kt < KT; kt++){
            if (kt + 1 < KT){ loadst(buf ^ 1, (kt+1)*32); cpwait<1>(); }
            else cpwait<0>();
            __syncthreads();

            #pragma unroll
            for (int kh = 0; kh < 32; kh += 16){
                unsigned ah[2][4], al[2][4];
                #pragma unroll
                for (int mt = 0; mt < 2; mt++){
                    int arow = wm + mt*16 + (t4 & 1)*8 + lr;
                    unsigned off = (unsigned)((buf*2*5120 + arow*40 + kh + (t4 >> 1)*8)*2);
                    ldsm_x4(ah[mt], smB + off);
                    ldsm_x4(al[mt], smB + off + 5120*2);
                }
                #pragma unroll
                for (int g = 0; g < 2; g++){
                    #pragma unroll
                    for (int pr2 = 0; pr2 < 2; pr2++){
                        int brow = wn + pr2*16 + (t4 >> 1)*8 + lr;
                        unsigned off = (unsigned)(((20480 + buf*4*2560 + g*2*2560)
                                                   + brow*40 + kh + (t4 & 1)*8)*2);
                        unsigned th[4], tl[4];
                        ldsm_x4(th, smB + off);
                        ldsm_x4(tl, smB + off + 2560*2);
                        unsigned bh0[2] = {th[0], th[1]}, bh1[2] = {th[2], th[3]};
                        unsigned bl0[2] = {tl[0], tl[1]}, bl1[2] = {tl[2], tl[3]};
                        #pragma unroll
                        for (int mt = 0; mt < 2; mt++){
                            mma_bf16(acc[g][mt][2*pr2],   ah[mt], bh0);
                            mma_bf16(acc[g][mt][2*pr2],   ah[mt], bl0);
                            mma_bf16(acc[g][mt][2*pr2],   al[mt], bh0);
                            mma_bf16(acc[g][mt][2*pr2+1], ah[mt], bh1);
                            mma_bf16(acc[g][mt][2*pr2+1], ah[mt], bl1);
                            mma_bf16(acc[g][mt][2*pr2+1], al[mt], bh1);
                        }
                    }
                }
            }
            __syncthreads();
            buf ^= 1;
        }

        #pragma unroll
        for (int mt = 0; mt < 2; mt++)
            #pragma unroll
            for (int nt = 0; nt < 4; nt++){
                int row0 = bm + wm + mt*16 + (lane >> 2);
                int col  = bn + wn + nt*8 + (lane & 3)*2;
                if (col >= N) continue;
                float b10 = p.b1[col], b11 = p.b1[col + 1];
                float b20 = p.b2[col], b21 = p.b2[col + 1];
                float o0 = sigmoid_f(acc[0][mt][nt][0] + b10)*(acc[1][mt][nt][0] + b20);
                float o1 = sigmoid_f(acc[0][mt][nt][1] + b11)*(acc[1][mt][nt][1] + b21);
                float o2 = sigmoid_f(acc[0][mt][nt][2] + b10)*(acc[1][mt][nt][2] + b20);
                float o3 = sigmoid_f(acc[0][mt][nt][3] + b11)*(acc[1][mt][nt][3] + b21);
                if (row0 < M){
                    size_t ix = (size_t)row0*N + col;
                    if (MODE == 1 && p.sub){
                        p.Cout[ix]     = o0 - p.Cout[ix];
                        p.Cout[ix + 1] = o1 - p.Cout[ix + 1];
                    } else {
                        p.Cout[ix] = o0; p.Cout[ix + 1] = o1;
                    }
                }
                if (row0 + 8 < M){
                    size_t ix = (size_t)(row0+8)*N + col;
                    if (MODE == 1 && p.sub){
                        p.Cout[ix]     = o2 - p.Cout[ix];
                        p.Cout[ix + 1] = o3 - p.Cout[ix + 1];
                    } else {
                        p.Cout[ix] = o2; p.Cout[ix + 1] = o3;
                    }
                }
            }
    }
}

// =============== flash attention ==========================================
__global__ __launch_bounds__(256) void flash_attn(){
    __shared__ __align__(16) bf16 sm[20480];   // 40 KB
    const unsigned smB = (unsigned)__cvta_generic_to_shared(sm);
    const int bh = blockIdx.y;
    const int b = bh >> 3, h = bh & 7;
    const int i0 = blockIdx.x * 128;
    const bf16* qH = p_qkv +           (size_t)b*NTOK*D + h*EH;
    const bf16* qL = qH + 3*MD;
    const bf16* kH = p_qkv +    MD +   (size_t)b*NTOK*D + h*EH;
    const bf16* kL = kH + 3*MD;
    const bf16* vH = p_qkv +  2*MD +   (size_t)b*NTOK*D + h*EH;
    const bf16* vL = vH + 3*MD;

    const int tid = threadIdx.x, lane = tid & 31, w = tid >> 5;
    const int t4 = lane >> 3, lr = lane & 7;

    {
        int row = tid >> 1, c = (tid & 1)*16;
        int gi = i0 + row;
        bool ok = gi < NTOK;
        size_t so = (size_t)(ok ? gi : 0)*D + c;
        const float4 z4 = make_float4(0.f,0.f,0.f,0.f);
        float4 f0 = ok ? *(const float4*)(qH + so)     : z4;
        float4 f1 = ok ? *(const float4*)(qH + so + 8) : z4;
        *(float4*)&sm[row*40 + c]     = f0;
        *(float4*)&sm[row*40 + c + 8] = f1;
        f0 = ok ? *(const float4*)(qL + so)     : z4;
        f1 = ok ? *(const float4*)(qL + so + 8) : z4;
        *(float4*)&sm[5120 + row*40 + c]     = f0;
        *(float4*)&sm[5120 + row*40 + c + 8] = f1;
    }
    __syncthreads();
    unsigned qh[2][4], ql[2][4];
    #pragma unroll
    for (int kc = 0; kc < 2; kc++){
        int row = w*16 + (t4 & 1)*8 + lr;
        int col = kc*16 + (t4 >> 1)*8;
        ldsm_x4(qh[kc], smB + (unsigned)((row*40 + col)*2));
        ldsm_x4(ql[kc], smB + (unsigned)((5120 + row*40 + col)*2));
    }
    __syncthreads();

    const int ldr = tid >> 2, ldc = (tid & 3)*8;
    auto loadkv = [&](int s, int j0){
        int gj = j0 + ldr;
        bool ok = gj < NTOK;
        size_t so = (size_t)(ok ? gj : 0)*D + ldc;
        unsigned doff = (unsigned)(s*5120 + (ldr*40 + ldc)*2);
        cp16(smB + doff,         kH + so, ok);
        cp16(smB + 10240 + doff, kL + so, ok);
        cp16(smB + 20480 + doff, vH + so, ok);
        cp16(smB + 30720 + doff, vL + so, ok);
        cpcommit();
    };

    float o[4][4];
    #pragma unroll
    for (int j = 0; j < 4; j++)
        #pragma unroll
        for (int q = 0; q < 4; q++) o[j][q] = 0.f;
    float m0 = -1e30f, m1 = -1e30f, l0 = 0.f, l1 = 0.f;
    const float scale = 0.17677669529663688f;

    loadkv(0, 0);
    int buf = 0;
    const int NJT = 14;
    for (int jt = 0; jt < NJT; jt++){
        const int j0 = jt*64;
        if (jt + 1 < NJT){ loadkv(buf ^ 1, (jt+1)*64); cpwait<1>(); }
        else cpwait<0>();
        __syncthreads();

        float s[8][4];
        #pragma unroll
        for (int nt = 0; nt < 8; nt++)
            #pragma unroll
            for (int q = 0; q < 4; q++) s[nt][q] = 0.f;

        #pragma unroll
        for (int kc = 0; kc < 2; kc++){
            #pragma unroll
            for (int pr = 0; pr < 4; pr++){
                int brow = pr*16 + (t4 >> 1)*8 + lr;
                int col  = kc*16 + (t4 & 1)*8;
                unsigned off = (unsigned)(buf*5120 + (brow*40 + col)*2);
                unsigned th[4], tl[4];
                ldsm_x4(th, smB + off);
                ldsm_x4(tl, smB + 10240 + off);
                unsigned bh0[2] = {th[0], th[1]}, bh1[2] = {th[2], th[3]};
                unsigned bl0[2] = {tl[0], tl[1]}, bl1[2] = {tl[2], tl[3]};
                mma_bf16(s[2*pr],   qh[kc], bh0);
                mma_bf16(s[2*pr],   qh[kc], bl0);
                mma_bf16(s[2*pr],   ql[kc], bh0);
                mma_bf16(s[2*pr+1], qh[kc], bh1);
                mma_bf16(s[2*pr+1], qh[kc], bl1);
                mma_bf16(s[2*pr+1], ql[kc], bh1);
            }
        }

        #pragma unroll
        for (int nt = 0; nt < 8; nt++)
            #pragma unroll
            for (int q = 0; q < 4; q++) s[nt][q] *= scale;
        if (j0 + 64 > NTOK){
            #pragma unroll
            for (int nt = 0; nt < 8; nt++){
                int c0 = j0 + nt*8 + (lane & 3)*2;
                if (c0     >= NTOK){ s[nt][0] = -1e30f; s[nt][2] = -1e30f; }
                if (c0 + 1 >= NTOK){ s[nt][1] = -1e30f; s[nt][3] = -1e30f; }
            }
        }

        float rm0 = -1e30f, rm1 = -1e30f;
        #pragma unroll
        for (int nt = 0; nt < 8; nt++){
            rm0 = fmaxf(rm0, fmaxf(s[nt][0], s[nt][1]));
            rm1 = fmaxf(rm1, fmaxf(s[nt][2], s[nt][3]));
        }
        rm0 = fmaxf(rm0, __shfl_xor_sync(0xffffffffu, rm0, 1));
        rm0 = fmaxf(rm0, __shfl_xor_sync(0xffffffffu, rm0, 2));
        rm1 = fmaxf(rm1, __shfl_xor_sync(0xffffffffu, rm1, 1));
        rm1 = fmaxf(rm1, __shfl_xor_sync(0xffffffffu, rm1, 2));
        float nm0 = fmaxf(m0, rm0), nm1 = fmaxf(m1, rm1);
        float a0 = __expf(m0 - nm0), a1 = __expf(m1 - nm1);
        float ps0 = 0.f, ps1 = 0.f;
        #pragma unroll
        for (int nt = 0; nt < 8; nt++){
            s[nt][0] = __expf(s[nt][0] - nm0);
            s[nt][1] = __expf(s[nt][1] - nm0);
            s[nt][2] = __expf(s[nt][2] - nm1);
            s[nt][3] = __expf(s[nt][3] - nm1);
            ps0 += s[nt][0] + s[nt][1];
            ps1 += s[nt][2] + s[nt][3];
        }
        ps0 += __shfl_xor_sync(0xffffffffu, ps0, 1);
        ps0 += __shfl_xor_sync(0xffffffffu, ps0, 2);
        ps1 += __shfl_xor_sync(0xffffffffu, ps1, 1);
        ps1 += __shfl_xor_sync(0xffffffffu, ps1, 2);
        l0 = l0*a0 + ps0; l1 = l1*a1 + ps1;
        m0 = nm0; m1 = nm1;
        #pragma unroll
        for (int nt = 0; nt < 4; nt++){
            o[nt][0] *= a0; o[nt][1] *= a0;
            o[nt][2] *= a1; o[nt][3] *= a1;
        }

        #pragma unroll
        for (int kc2 = 0; kc2 < 4; kc2++){
            unsigned pah[4], pal[4];
            {
                const float* u = s[2*kc2];
                const float* v2 = s[2*kc2 + 1];
                bf16 h0,lo0,h1,lo1;
                splitv(u[0], h0, lo0); splitv(u[1], h1, lo1);
                pah[0] = pack2u(h0, h1);   pal[0] = pack2u(lo0, lo1);
                splitv(u[2], h0, lo0); splitv(u[3], h1, lo1);
                pah[1] = pack2u(h0, h1);   pal[1] = pack2u(lo0, lo1);
                splitv(v2[0], h0, lo0); splitv(v2[1], h1, lo1);
                pah[2] = pack2u(h0, h1);   pal[2] = pack2u(lo0, lo1);
                splitv(v2[2], h0, lo0); splitv(v2[3], h1, lo1);
                pah[3] = pack2u(h0, h1);   pal[3] = pack2u(lo0, lo1);
            }
            #pragma unroll
            for (int pr2 = 0; pr2 < 2; pr2++){
                int krow = kc2*16 + (t4 & 1)*8 + lr;
                int ncol = pr2*16 + (t4 >> 1)*8;
                unsigned off = (unsigned)(buf*5120 + (krow*40 + ncol)*2);
                unsigned th[4], tl[4];
                ldsm_x4t(th, smB + 20480 + off);
                ldsm_x4t(tl, smB + 30720 + off);
                unsigned bh0[2] = {th[0], th[1]}, bh1[2] = {th[2], th[3]};
                unsigned bl0[2] = {tl[0], tl[1]}, bl1[2] = {tl[2], tl[3]};
                mma_bf16(o[2*pr2],   pah, bh0);
                mma_bf16(o[2*pr2],   pah, bl0);
                mma_bf16(o[2*pr2],   pal, bh0);
                mma_bf16(o[2*pr2+1], pah, bh1);
                mma_bf16(o[2*pr2+1], pah, bl1);
                mma_bf16(o[2*pr2+1], pal, bh1);
            }
        }
        __syncthreads();
        buf ^= 1;
    }

    float inv0 = 1.f / l0, inv1 = 1.f / l1;
    #pragma unroll
    for (int nt = 0; nt < 4; nt++){
        int row0 = i0 + w*16 + (lane >> 2);
        int col  = nt*8 + (lane & 3)*2;
        if (row0 < NTOK){
            size_t dst = ((size_t)b*NTOK + row0)*D + h*EH + col;
            bf16 h0,lo0,h1,lo1;
            splitv(o[nt][0]*inv0, h0, lo0); splitv(o[nt][1]*inv0, h1, lo1);
            *(__nv_bfloat162*)(p_att + dst)      = __halves2bfloat162(h0, h1);
            *(__nv_bfloat162*)(p_att + MD + dst) = __halves2bfloat162(lo0, lo1);
        }
        if (row0 + 8 < NTOK){
            size_t dst = ((size_t)b*NTOK + row0 + 8)*D + h*EH + col;
            bf16 h2,lo2,h3,lo3;
            splitv(o[nt][2]*inv1, h2, lo2); splitv(o[nt][3]*inv1, h3, lo3);
            *(__nv_bfloat162*)(p_att + dst)      = __halves2bfloat162(h2, h3);
            *(__nv_bfloat162*)(p_att + MD + dst) = __halves2bfloat162(lo2, lo3);
        }
    }
}

// ---------------- LayerNorm(x [- sub]) over D=256 (+ optional planes) ----
__global__ __launch_bounds__(256) void ln_kernel(const float* __restrict__ X,
                                                 const float* __restrict__ Sub,
                                                 const float* __restrict__ g,
                                                 const float* __restrict__ beta,
                                                 float* __restrict__ Out,
                                                 bf16* __restrict__ pH,
                                                 bf16* __restrict__ pL){
    int row = blockIdx.x, d = threadIdx.x;
    size_t i = (size_t)row*D + d;
    float v = X[i] - (Sub ? Sub[i] : 0.f);
    float2 r = blockReduce2(v, v*v);
    float mean = r.x * (1.f/D);
    float var  = r.y * (1.f/D) - mean*mean;
    float o = (v - mean) * rsqrtf(var + EPS) * g[d] + beta[d];
    Out[i] = o;
    if (pH){
        bf16 hh, ll; splitv(o, hh, ll);
        pH[i] = hh; pL[i] = ll;
    }
}

// ---------------- final: transpose + de-standardize + 2-scale mean --------
__global__ __launch_bounds__(256) void final_kernel(float* __restrict__ out, int t){
    __shared__ float tile[32][33];
    int b = blockIdx.z;
    int p0 = blockIdx.x*32, n0 = blockIdx.y*32;
    int tx = threadIdx.x & 31, ty = threadIdx.x >> 5;
    #pragma unroll
    for (int i = 0; i < 4; i++){
        int n = n0 + ty + i*8, pp = p0 + tx;
        if (n < ENC && pp < DB)
            tile[ty + i*8][tx] = g_out[((size_t)b*NTOK + n)*DB + pp];
    }
    __syncthreads();
    #pragma unroll
    for (int i = 0; i < 4; i++){
        int pp = p0 + ty + i*8, n = n0 + tx;
        if (pp < DB && n < ENC){
            float v = tile[tx][ty + i*8]*g_std[b*ENC + n] + g_mean[b*ENC + n];
            v *= 0.5f;
            size_t idx = ((size_t)b*DB + pp)*ENC + n;
            if (t == 0) out[idx] = v; else out[idx] += v;
        }
    }
}

// ---------------- host ----------------
static inline int gsz(int nt){ return nt < 296 ? nt : 296; }
static void* sym(const void* s){ void* p; cudaGetSymbolAddress(&p, s); return p; }

extern "C" void kernel_launch(void* const* d_in, const int* in_sizes, int n_in,
                              void* d_out, int out_size){
    const float* mbx  = (const float*)d_in[0];
    const float* mbxm = (const float*)d_in[1];
    const float* embW = (const float*)d_in[4];
    const float* embB = (const float*)d_in[5];
    const float* Wq = (const float*)d_in[6];
    const float* Wk = (const float*)d_in[7];
    const float* Wv = (const float*)d_in[8];
    const float* Wo = (const float*)d_in[9];
    const float* W3 = (const float*)d_in[10];
    const float* W4 = (const float*)d_in[11];
    const float* bq = (const float*)d_in[12];
    const float* bk = (const float*)d_in[13];
    const float* bv = (const float*)d_in[14];
    const float* bo = (const float*)d_in[15];
    const float* b3 = (const float*)d_in[16];
    const float* b4 = (const float*)d_in[17];
    const float* W1 = (const float*)d_in[18];
    const float* b1 = (const float*)d_in[19];
    const float* W2 = (const float*)d_in[20];
    const float* b2 = (const float*)d_in[21];
    const float* W5 = (const float*)d_in[22];
    const float* b5 = (const float*)d_in[23];
    const float* W6 = (const float*)d_in[24];
    const float* b6 = (const float*)d_in[25];
    const float* ln1g = (const float*)d_in[26];
    const float* ln1b = (const float*)d_in[27];
    const float* ln2g = (const float*)d_in[28];
    const float* ln2b = (const float*)d_in[29];
    float* out = (float*)d_out;

    float* hF   = (float*)sym(g_h);
    float* xatt = (float*)sym(g_xatt);
    float* xln  = (float*)sym(g_xln);
    float* hhF  = (float*)sym(g_hh);
    float* outF = (float*)sym(g_out);

    bf16* xinP = (bf16*)sym(p_xin);
    bf16* hP   = (bf16*)sym(p_h);
    bf16* qkvP = (bf16*)sym(p_qkv);
    bf16* attP = (bf16*)sym(p_att);
    bf16* xlnP = (bf16*)sym(p_xln);
    bf16* y1P  = (bf16*)sym(p_y1);
    bf16* xsP  = (bf16*)sym(p_xs);
    bf16* xattP = (bf16*)sym(p_xatt);
    bf16* yP   = (bf16*)sym(p_y);
    bf16* embWP = (bf16*)sym(p_embW);
    bf16* WqP = (bf16*)sym(p_Wq); bf16* WkP = (bf16*)sym(p_Wk);
    bf16* WvP = (bf16*)sym(p_Wv); bf16* WoP = (bf16*)sym(p_Wo);
    bf16* W3P = (bf16*)sym(p_W3); bf16* W4P = (bf16*)sym(p_W4);
    bf16* W1P = (bf16*)sym(p_W1); bf16* W2P = (bf16*)sym(p_W2);
    bf16* W5P = (bf16*)sym(p_W5); bf16* W6P = (bf16*)sym(p_W6);

    const size_t EWN = (size_t)256*SEQP;
    const size_t WDD = (size_t)LAYERS*D*D;
    const size_t W1N = (size_t)LAYERS*DFF*D;
    const size_t W5N = (size_t)LAYERS*DB*2*D;
    const size_t Y1N = (size_t)MROWS*DFF;

    cudaFuncSetAttribute(mma_gemm<0>, cudaFuncAttributeMaxDynamicSharedMemorySize, 61440);
    cudaFuncSetAttribute(mma_gemm<1>, cudaFuncAttributeMaxDynamicSharedMemorySize, 61440);
    cudaFuncSetAttribute(mma_gemm<2>, cudaFuncAttributeMaxDynamicSharedMemorySize, 61440);
    cudaFuncSetAttribute(mma_gemm2<0>, cudaFuncAttributeMaxDynamicSharedMemorySize, 81920);
    cudaFuncSetAttribute(mma_gemm2<1>, cudaFuncAttributeMaxDynamicSharedMemorySize, 81920);

    // weight splits (one batched launch + embed pad)
    {
        WSArgs ws;
        const float* ss[10] = {Wq, Wk, Wv, Wo, W3, W4, W1, W2, W5, W6};
        bf16* hh[10] = {WqP, WkP, WvP, WoP, W3P, W4P, W1P, W2P, W5P, W6P};
        size_t nn[10] = {WDD, WDD, WDD, WDD, WDD, WDD, W1N, W1N, W5N, W5N};
        for (int i = 0; i < 10; i++){
            ws.s[i] = ss[i]; ws.h[i] = hh[i]; ws.l[i] = hh[i] + nn[i]; ws.n[i] = (int)nn[i];
        }
        wsplit_all<<<dim3(288, 10), 256>>>(ws);
        wsplit_pad<<<(unsigned)((EWN + 255)/256), 256>>>(embW, embWP, embWP + EWN, 256, SEQ, SEQP);
    }

    const int tm = 55;    // ceil(6928/128)

    for (int t = 0; t < TS; t++){
        stats_kernel<<<dim3((ENC + 255)/256, B_), 256>>>(mbx, t);
        xin_kernel<<<dim3((SEQP + 31)/32, (NTOK + 31)/32, B_), 256>>>(mbx, mbxm, t);

        {   // embed -> fp32 h + planes
            GemmArgs a = {};
            a.aH[0] = xinP; a.aL[0] = xinP + XN;
            a.wH[0] = embWP; a.wL[0] = embWP + EWN;
            a.bias[0] = embB; a.C[0] = hF;
            a.cH[0] = hP; a.cL[0] = hP + MD;
            mma_gemm<0><<<gsz(tm*4), 256, 61440>>>(a, MROWS, D, SEQP, 4, tm*4, tm*4);
        }

        for (int l = 0; l < LAYERS; l++){
            {   // QKV -> planes
                GemmArgs a = {};
                for (int z = 0; z < 3; z++){
                    a.aH[z] = hP; a.aL[z] = hP + MD;
                    a.cH[z] = qkvP + (size_t)z*MD;
                    a.cL[z] = qkvP + 3*MD + (size_t)z*MD;
                }
                a.wH[0] = WqP + (size_t)l*D*D; a.wL[0] = WqP + WDD + (size_t)l*D*D;
                a.wH[1] = WkP + (size_t)l*D*D; a.wL[1] = WkP + WDD + (size_t)l*D*D;
                a.wH[2] = WvP + (size_t)l*D*D; a.wL[2] = WvP + WDD + (size_t)l*D*D;
                a.bias[0] = bq + l*D; a.bias[1] = bk + l*D; a.bias[2] = bv + l*D;
                mma_gemm<0><<<gsz(tm*4*3), 256, 61440>>>(a, MROWS, D, D, 4, tm*4, tm*4*3);
            }

            flash_attn<<<dim3(7, B_*NH), 256>>>();

            {   // Wo -> fp32 xatt + planes
                GemmArgs a = {};
                a.aH[0] = attP; a.aL[0] = attP + MD;
                a.wH[0] = WoP + (size_t)l*D*D; a.wL[0] = WoP + WDD + (size_t)l*D*D;
                a.bias[0] = bo + l*D; a.C[0] = xatt;
                a.cH[0] = xattP; a.cL[0] = xattP + MD;
                mma_gemm<0><<<gsz(tm*4), 256, 61440>>>(a, MROWS, D, D, 4, tm*4, tm*4);
            }

            ln_kernel<<<MROWS, 256>>>(hF, xatt, ln1g + l*D, ln1b + l*D, xln,
                                      xlnP, xlnP + MD);

            {   // W1 + GELU -> y1 planes
                GemmArgs a = {};
                a.aH[0] = xlnP; a.aL[0] = xlnP + MD;
                a.wH[0] = W1P + (size_t)l*DFF*D; a.wL[0] = W1P + W1N + (size_t)l*DFF*D;
                a.bias[0] = b1 + l*DFF;
                a.cH[0] = y1P; a.cL[0] = y1P + Y1N;
                mma_gemm<1><<<gsz(tm*8), 256, 61440>>>(a, MROWS, DFF, D, 8, tm*8, tm*8);
            }
            {   // W2 -> y planes + xs=(xln-y) planes (sub fused)
                GemmArgs a = {};
                a.aH[0] = y1P; a.aL[0] = y1P + Y1N;
                a.wH[0] = W2P + (size_t)l*D*DFF; a.wL[0] = W2P + W1N + (size_t)l*D*DFF;
                a.bias[0] = b2 + l*D;
                a.cH[0] = yP; a.cL[0] = yP + MD;
                a.xsub[0] = xln;
                a.c2H[0] = xsP; a.c2L[0] = xsP + MD;
                mma_gemm<2><<<gsz(tm*4), 256, 61440>>>(a, MROWS, D, DFF, 4, tm*4, tm*4);
            }

            {   // fused W3/W4 -> hh = sigmoid(.)*(.)
                Gemm2Args a = {};
                a.a0H = xsP; a.a0L = xsP + MD; a.a1H = xsP; a.a1L = xsP + MD;
                a.kSplit = 1 << 30; a.aStride = D;
                a.w1H = W3P + (size_t)l*D*D; a.w1L = W3P + WDD + (size_t)l*D*D;
                a.w2H = W4P + (size_t)l*D*D; a.w2L = W4P + WDD + (size_t)l*D*D;
                a.b1 = b3 + l*D; a.b2 = b4 + l*D;
                a.Cout = hhF; a.sub = 0;
                mma_gemm2<0><<<gsz(tm*4), 256, 81920>>>(a, MROWS, D, D, 4, tm*4);
            }

            {   // fused W5/W6 over cat(xatt,y) -> g_out (with layer subtract)
                Gemm2Args a = {};
                a.a0H = xattP; a.a0L = xattP + MD;
                a.a1H = yP;    a.a1L = yP + MD;
                a.kSplit = D; a.aStride = D;
                a.w1H = W5P + (size_t)l*DB*2*D; a.w1L = W5P + W5N + (size_t)l*DB*2*D;
                a.w2H = W6P + (size_t)l*DB*2*D; a.w2L = W6P + W5N + (size_t)l*DB*2*D;
                a.b1 = b5 + l*DB; a.b2 = b6 + l*DB;
                a.Cout = outF; a.sub = l;
                mma_gemm2<1><<<gsz(tm*12), 256, 81920>>>(a, MROWS, DB, 2*D, 12, tm*12);
            }

            ln_kernel<<<MROWS, 256>>>(hhF, (const float*)nullptr,
                                      ln2g + l*D, ln2b + l*D, hF, hP, hP + MD);
        }

        final_kernel<<<dim3((DB + 31)/32, (ENC + 31)/32, B_), 256>>>(out, t);
    }
}

// round 10
// speedup vs baseline: 1.0713x; 1.0713x over previous
#include <cuda_runtime.h>
#include <cuda_bf16.h>
#include <math.h>

#define B_    8
#define TS    2
#define SEQ   720
#define SEQP  736
#define ENC   862
#define MARKD 4
#define NTOK  866
#define D     256
#define NH    8
#define EH    32
#define DFF   512
#define DB    720
#define LAYERS 2
#define EPS   1e-5f
#define MROWS (B_*NTOK)   // 6928
#define MD    ((size_t)MROWS*D)
#define XN    ((size_t)MROWS*SEQP)

typedef __nv_bfloat16 bf16;

// ---------------- fp32 scratch ----------------
__device__ float g_mean[B_*ENC], g_std[B_*ENC];
__device__ float g_h[MD], g_xatt[MD], g_xln[MD], g_hh[MD];
__device__ float g_out[(size_t)MROWS*DB];

// ---------------- bf16 hi/lo planes (lo at +n) ----------------
__device__ __align__(16) bf16 p_xin[2*XN];
__device__ __align__(16) bf16 p_h  [2*MD];
__device__ __align__(16) bf16 p_qkv[2*3*MD];
__device__ __align__(16) bf16 p_att[2*MD];
__device__ __align__(16) bf16 p_xln[2*MD];
__device__ __align__(16) bf16 p_y1 [2*(size_t)MROWS*DFF];
__device__ __align__(16) bf16 p_xs [2*MD];
__device__ __align__(16) bf16 p_xatt[2*MD];
__device__ __align__(16) bf16 p_y  [2*MD];
// weights
__device__ __align__(16) bf16 p_embW[2*256*SEQP];
__device__ __align__(16) bf16 p_Wq[2*LAYERS*D*D], p_Wk[2*LAYERS*D*D], p_Wv[2*LAYERS*D*D];
__device__ __align__(16) bf16 p_Wo[2*LAYERS*D*D], p_W3[2*LAYERS*D*D], p_W4[2*LAYERS*D*D];
__device__ __align__(16) bf16 p_W1[2*LAYERS*DFF*D], p_W2[2*LAYERS*D*DFF];
__device__ __align__(16) bf16 p_W5[2*LAYERS*DB*2*D], p_W6[2*LAYERS*DB*2*D];

// ---------------- helpers ----------------
__device__ __forceinline__ void splitv(float x, bf16& h, bf16& l){
    h = __float2bfloat16(x);
    l = __float2bfloat16(x - __bfloat162float(h));
}
__device__ __forceinline__ unsigned pack2u(bf16 a, bf16 b){
    __nv_bfloat162 t = __halves2bfloat162(a, b);
    return *(unsigned*)&t;
}
__device__ __forceinline__ void mma_bf16(float c[4], const unsigned a[4], const unsigned b[2]){
    asm volatile("mma.sync.aligned.m16n8k16.row.col.f32.bf16.bf16.f32 "
                 "{%0,%1,%2,%3}, {%4,%5,%6,%7}, {%8,%9}, {%0,%1,%2,%3};\n"
                 : "+f"(c[0]), "+f"(c[1]), "+f"(c[2]), "+f"(c[3])
                 : "r"(a[0]), "r"(a[1]), "r"(a[2]), "r"(a[3]),
                   "r"(b[0]), "r"(b[1]));
}
__device__ __forceinline__ void ldsm_x4(unsigned r[4], unsigned addr){
    asm volatile("ldmatrix.sync.aligned.m8n8.x4.shared.b16 {%0,%1,%2,%3}, [%4];\n"
                 : "=r"(r[0]), "=r"(r[1]), "=r"(r[2]), "=r"(r[3]) : "r"(addr));
}
__device__ __forceinline__ void ldsm_x4t(unsigned r[4], unsigned addr){
    asm volatile("ldmatrix.sync.aligned.m8n8.x4.trans.shared.b16 {%0,%1,%2,%3}, [%4];\n"
                 : "=r"(r[0]), "=r"(r[1]), "=r"(r[2]), "=r"(r[3]) : "r"(addr));
}
__device__ __forceinline__ void cp16(unsigned dst, const void* src, bool p){
    int sz = p ? 16 : 0;
    asm volatile("cp.async.cg.shared.global [%0], [%1], 16, %2;\n"
                 :: "r"(dst), "l"(src), "r"(sz));
}
__device__ __forceinline__ void cpcommit(){ asm volatile("cp.async.commit_group;\n"); }
template<int N> __device__ __forceinline__ void cpwait(){
    asm volatile("cp.async.wait_group %0;\n" :: "n"(N));
}
__device__ __forceinline__ float gelu_f(float x){
    return 0.5f*x*(1.f + erff(x*0.70710678118654752f));
}
__device__ __forceinline__ float sigmoid_f(float x){
    return 1.f/(1.f + expf(-x));
}
// reduce (a, b) simultaneously across block
__device__ __forceinline__ float2 blockReduce2(float a, float b){
    __shared__ float2 sh[33];
    int lane = threadIdx.x & 31, wid = threadIdx.x >> 5;
    __syncthreads();
    #pragma unroll
    for (int o = 16; o; o >>= 1){
        a += __shfl_down_sync(0xffffffffu, a, o);
        b += __shfl_down_sync(0xffffffffu, b, o);
    }
    if (lane == 0) sh[wid] = make_float2(a, b);
    __syncthreads();
    if (wid == 0){
        int nw = blockDim.x >> 5;
        float2 v = (lane < nw) ? sh[lane] : make_float2(0.f, 0.f);
        a = v.x; b = v.y;
        #pragma unroll
        for (int o = 16; o; o >>= 1){
            a += __shfl_down_sync(0xffffffffu, a, o);
            b += __shfl_down_sync(0xffffffffu, b, o);
        }
        if (lane == 0) sh[32] = make_float2(a, b);
    }
    __syncthreads();
    return sh[32];
}

// ---------------- weight split (batched) ----------------
struct WSArgs { const float* s[10]; bf16* h[10]; bf16* l[10]; int n[10]; };
__global__ void wsplit_all(WSArgs w){
    int z = blockIdx.y;
    int n = w.n[z];
    const float* src = w.s[z];
    bf16* hh = w.h[z]; bf16* ll = w.l[z];
    for (int i = blockIdx.x*blockDim.x + threadIdx.x; i < n; i += gridDim.x*blockDim.x)
        splitv(src[i], hh[i], ll[i]);
}
__global__ void wsplit_pad(const float* __restrict__ s, bf16* __restrict__ h,
                           bf16* __restrict__ l, int rows, int K, int Kp){
    size_t i = (size_t)blockIdx.x*blockDim.x + threadIdx.x;
    size_t total = (size_t)rows*Kp;
    if (i >= total) return;
    int c = (int)(i % Kp); int r = (int)(i / Kp);
    float v = (c < K) ? s[(size_t)r*K + c] : 0.f;
    splitv(v, h[i], l[i]);
}

// ---------------- input standardization ----------------
__global__ void stats_kernel(const float* __restrict__ mbx, int t){
    int b = blockIdx.y;
    int n = blockIdx.x * blockDim.x + threadIdx.x;
    if (n >= ENC) return;
    const float* base = mbx + ((size_t)(b*TS + t)*SEQ)*ENC + n;
    float s = 0.f, ss = 0.f;
    for (int i = 0; i < SEQ; i++){
        float v = base[(size_t)i*ENC];
        s += v; ss += v*v;
    }
    float m = s * (1.f/SEQ);
    float var = ss * (1.f/SEQ) - m*m;
    g_mean[b*ENC + n] = m;
    g_std [b*ENC + n] = sqrtf(var + EPS);
}

// transposed tiled build of xin planes: read coalesced over n, write over s
__global__ __launch_bounds__(256) void xin_kernel(const float* __restrict__ mbx,
                                                  const float* __restrict__ mbxm, int t){
    __shared__ float tile[32][33];
    const int b = blockIdx.z;
    const int s0 = blockIdx.x*32, n0 = blockIdx.y*32;
    const int tx = threadIdx.x & 31, ty = threadIdx.x >> 5;
    #pragma unroll
    for (int i = 0; i < 4; i++){
        int s = s0 + ty + i*8, n = n0 + tx;
        float v = 0.f;
        if (s < SEQ && n < NTOK){
            if (n < ENC){
                v = mbx[((size_t)(b*TS + t)*SEQ + s)*ENC + n];
                v = (v - g_mean[b*ENC + n]) / g_std[b*ENC + n];
            } else {
                v = mbxm[((size_t)(b*TS + t)*SEQ + s)*MARKD + (n - ENC)];
            }
        }
        tile[ty + i*8][tx] = v;
    }
    __syncthreads();
    #pragma unroll
    for (int i = 0; i < 4; i++){
        int n = n0 + ty + i*8, s = s0 + tx;
        if (n < NTOK && s < SEQP){
            size_t idx = ((size_t)b*NTOK + n)*SEQP + s;
            splitv(tile[tx][ty + i*8], p_xin[idx], p_xin[XN + idx]);
        }
    }
}

// =============== MMA GEMM: C = A @ W^T + bias (bf16 planes, cp.async) =====
// ACT 0: plain; 1: gelu; 2: emit y planes + (xsub - y) planes
struct GemmArgs {
    const bf16 *aH[3], *aL[3], *wH[3], *wL[3];
    const float* bias[3];
    float* C[3];
    bf16 *cH[3], *cL[3];
    const float* xsub[3];
    bf16 *c2H[3], *c2L[3];
};

template<int ACT>
__global__ __launch_bounds__(256)
void mma_gemm(GemmArgs p, int M, int N, int K, int tilesN, int tpz, int nTiles){
    extern __shared__ __align__(16) char smraw[];
    bf16* sAh = (bf16*)smraw;            // [2][128][40]
    bf16* sAl = sAh + 2*128*40;
    bf16* sBh = sAl + 2*128*40;          // [2][64][40]
    bf16* sBl = sBh + 2*64*40;
    const unsigned aHiB = (unsigned)__cvta_generic_to_shared(sAh);
    const unsigned aLoB = (unsigned)__cvta_generic_to_shared(sAl);
    const unsigned bHiB = (unsigned)__cvta_generic_to_shared(sBh);
    const unsigned bLoB = (unsigned)__cvta_generic_to_shared(sBl);

    const int tid = threadIdx.x;
    const int lane = tid & 31, w = tid >> 5;
    const int wm = (w >> 1)*32, wn = (w & 1)*32;
    const int t4 = lane >> 3, lr = lane & 7;
    const int ldr = tid >> 2, ldc = (tid & 3)*8;

    for (int t = blockIdx.x; t < nTiles; t += gridDim.x){
        const int z  = t / tpz;
        const int rr = t - z*tpz;
        const int bm = (rr / tilesN)*128, bn = (rr % tilesN)*64;
        const bf16* __restrict__ aHp = p.aH[z];
        const bf16* __restrict__ aLp = p.aL[z];
        const bf16* __restrict__ wHp = p.wH[z];
        const bf16* __restrict__ wLp = p.wL[z];
        const float* __restrict__ bias = p.bias[z];
        float* Cp = p.C[z];
        bf16* cHp = p.cH[z];
        bf16* cLp = p.cL[z];

        float acc[2][4][4];
        #pragma unroll
        for (int i = 0; i < 2; i++)
            #pragma unroll
            for (int j = 0; j < 4; j++)
                #pragma unroll
                for (int q = 0; q < 4; q++) acc[i][j][q] = 0.f;

        auto loadst = [&](int s, int k0){
            #pragma unroll
            for (int rep = 0; rep < 2; rep++){
                int r = ldr + rep*64;
                int gm = bm + r;
                bool pr = gm < M;
                size_t so = (size_t)(pr ? gm : 0)*K + k0 + ldc;
                unsigned doff = (unsigned)(((s*128 + r)*40 + ldc)*2);
                cp16(aHiB + doff, aHp + so, pr);
                cp16(aLoB + doff, aLp + so, pr);
            }
            {
                int gn = bn + ldr;
                bool pn = gn < N;
                size_t so = (size_t)(pn ? gn : 0)*K + k0 + ldc;
                unsigned doff = (unsigned)(((s*64 + ldr)*40 + ldc)*2);
                cp16(bHiB + doff, wHp + so, pn);
                cp16(bLoB + doff, wLp + so, pn);
            }
            cpcommit();
        };

        loadst(0, 0);
        int buf = 0;
        const int KT = K >> 5;
        for (int kt = 0; kt < KT; kt++){
            if (kt + 1 < KT){ loadst(buf ^ 1, (kt+1)*32); cpwait<1>(); }
            else cpwait<0>();
            __syncthreads();

            #pragma unroll
            for (int kh = 0; kh < 32; kh += 16){
                unsigned ah[2][4], al[2][4], bh[4][2], bl[4][2];
                #pragma unroll
                for (int mt = 0; mt < 2; mt++){
                    int arow = wm + mt*16 + (t4 & 1)*8 + lr;
                    unsigned off = (unsigned)((((buf*128) + arow)*40 + kh + (t4 >> 1)*8)*2);
                    ldsm_x4(ah[mt], aHiB + off);
                    ldsm_x4(al[mt], aLoB + off);
                }
                #pragma unroll
                for (int pr2 = 0; pr2 < 2; pr2++){
                    int brow = wn + pr2*16 + (t4 >> 1)*8 + lr;
                    unsigned off = (unsigned)((((buf*64) + brow)*40 + kh + (t4 & 1)*8)*2);
                    unsigned th[4], tl[4];
                    ldsm_x4(th, bHiB + off);
                    ldsm_x4(tl, bLoB + off);
                    bh[pr2*2][0] = th[0]; bh[pr2*2][1] = th[1];
                    bh[pr2*2+1][0] = th[2]; bh[pr2*2+1][1] = th[3];
                    bl[pr2*2][0] = tl[0]; bl[pr2*2][1] = tl[1];
                    bl[pr2*2+1][0] = tl[2]; bl[pr2*2+1][1] = tl[3];
                }
                #pragma unroll
                for (int mt = 0; mt < 2; mt++)
                    #pragma unroll
                    for (int nt = 0; nt < 4; nt++){
                        mma_bf16(acc[mt][nt], ah[mt], bh[nt]);
                        mma_bf16(acc[mt][nt], ah[mt], bl[nt]);
                        mma_bf16(acc[mt][nt], al[mt], bh[nt]);
                    }
            }
            __syncthreads();
            buf ^= 1;
        }

        #pragma unroll
        for (int mt = 0; mt < 2; mt++)
            #pragma unroll
            for (int nt = 0; nt < 4; nt++){
                int row0 = bm + wm + mt*16 + (lane >> 2);
                int col  = bn + wn + nt*8 + (lane & 3)*2;
                if (col >= N) continue;
                float b0 = bias[col], b1 = bias[col + 1];
                float v0 = acc[mt][nt][0] + b0, v1 = acc[mt][nt][1] + b1;
                float v2 = acc[mt][nt][2] + b0, v3 = acc[mt][nt][3] + b1;
                if (ACT == 1){
                    v0 = gelu_f(v0); v1 = gelu_f(v1);
                    v2 = gelu_f(v2); v3 = gelu_f(v3);
                }
                if (row0 < M){
                    size_t ix = (size_t)row0*N + col;
                    if (Cp){ Cp[ix] = v0; Cp[ix + 1] = v1; }
                    if (cHp){
                        bf16 h0,l0,h1,l1; splitv(v0,h0,l0); splitv(v1,h1,l1);
                        *(__nv_bfloat162*)(cHp + ix) = __halves2bfloat162(h0,h1);
                        *(__nv_bfloat162*)(cLp + ix) = __halves2bfloat162(l0,l1);
                    }
                    if (ACT == 2){
                        float x0 = p.xsub[z][ix], x1 = p.xsub[z][ix + 1];
                        bf16 h0,l0,h1,l1; splitv(x0 - v0,h0,l0); splitv(x1 - v1,h1,l1);
                        *(__nv_bfloat162*)(p.c2H[z] + ix) = __halves2bfloat162(h0,h1);
                        *(__nv_bfloat162*)(p.c2L[z] + ix) = __halves2bfloat162(l0,l1);
                    }
                }
                if (row0 + 8 < M){
                    size_t ix = (size_t)(row0+8)*N + col;
                    if (Cp){ Cp[ix] = v2; Cp[ix + 1] = v3; }
                    if (cHp){
                        bf16 h2,l2,h3,l3; splitv(v2,h2,l2); splitv(v3,h3,l3);
                        *(__nv_bfloat162*)(cHp + ix) = __halves2bfloat162(h2,h3);
                        *(__nv_bfloat162*)(cLp + ix) = __halves2bfloat162(l2,l3);
                    }
                    if (ACT == 2){
                        float x2 = p.xsub[z][ix], x3 = p.xsub[z][ix + 1];
                        bf16 h2,l2,h3,l3; splitv(x2 - v2,h2,l2); splitv(x3 - v3,h3,l3);
                        *(__nv_bfloat162*)(p.c2H[z] + ix) = __halves2bfloat162(h2,h3);
                        *(__nv_bfloat162*)(p.c2L[z] + ix) = __halves2bfloat162(l2,l3);
                    }
                }
            }
    }
}

// =============== fused dual GEMM (BM=64): o = sig(A W1^T+b1)*(A W2^T+b2) ==
// A source switches at kSplit (concat fusion).
// MODE 0: Cout = o ;  MODE 1: Cout = sub ? (o - Cout) : o
struct Gemm2Args {
    const bf16 *a0H, *a0L, *a1H, *a1L;
    int kSplit, aStride;
    const bf16 *w1H, *w1L, *w2H, *w2L;
    const float *b1, *b2;
    float* Cout;
    int sub;
};

template<int MODE>
__global__ __launch_bounds__(256)
void mma_gemm2(Gemm2Args p, int M, int N, int K, int tilesN, int nTiles){
    extern __shared__ __align__(16) char smraw[];
    bf16* sm = (bf16*)smraw;
    const unsigned smB = (unsigned)__cvta_generic_to_shared(sm);
    // elements: A(stage s, plane q): (s*2+q)*2560 (64x40 each)
    //           B: 10240 + (s*4 + g*2 + q)*2560 (64x40 each)
    const int tid = threadIdx.x;
    const int lane = tid & 31, w = tid >> 5;
    const int wm = (w >> 1)*16, wn = (w & 1)*32;
    const int t4 = lane >> 3, lr = lane & 7;
    const int ldr = tid >> 2, ldc = (tid & 3)*8;

    for (int t = blockIdx.x; t < nTiles; t += gridDim.x){
        const int bm = (t / tilesN)*64, bn = (t % tilesN)*64;

        float acc[2][4][4];
        #pragma unroll
        for (int g = 0; g < 2; g++)
            #pragma unroll
            for (int j = 0; j < 4; j++)
                #pragma unroll
                for (int q = 0; q < 4; q++) acc[g][j][q] = 0.f;

        auto loadst = [&](int s, int k0){
            const bf16* aH = (k0 < p.kSplit) ? p.a0H : p.a1H;
            const bf16* aL = (k0 < p.kSplit) ? p.a0L : p.a1L;
            int kk = (k0 < p.kSplit) ? k0 : k0 - p.kSplit;
            int gm = bm + ldr;
            bool pr = gm < M;
            size_t soA = (size_t)(pr ? gm : 0)*p.aStride + kk + ldc;
            unsigned dA = (unsigned)((s*2*2560 + ldr*40 + ldc)*2);
            cp16(smB + dA,           aH + soA, pr);
            cp16(smB + dA + 2560*2,  aL + soA, pr);
            int gn = bn + ldr;
            bool pn = gn < N;
            size_t soB = (size_t)(pn ? gn : 0)*K + k0 + ldc;
            unsigned dB = (unsigned)((10240 + s*4*2560 + ldr*40 + ldc)*2);
            cp16(smB + dB,             p.w1H + soB, pn);
            cp16(smB + dB + 2560*2,    p.w1L + soB, pn);
            cp16(smB + dB + 2*2560*2,  p.w2H + soB, pn);
            cp16(smB + dB + 3*2560*2,  p.w2L + soB, pn);
            cpcommit();
        };

        loadst(0, 0);
        int buf = 0;
        const int KT = K >> 5;
        for (int kt = 0; kt < KT; kt++){
            if (kt + 1 < KT){ loadst(buf ^ 1, (kt+1)*32); cpwait<1>(); }
            else cpwait<0>();
            __syncthreads();

            #pragma unroll
            for (int kh = 0; kh < 32; kh += 16){
                unsigned ah[4], al[4];
                {
                    int arow = wm + (t4 & 1)*8 + lr;
                    unsigned off = (unsigned)((buf*2*2560 + arow*40 + kh + (t4 >> 1)*8)*2);
                    ldsm_x4(ah, smB + off);
                    ldsm_x4(al, smB + off + 2560*2);
                }
                #pragma unroll
                for (int g = 0; g < 2; g++){
                    #pragma unroll
                    for (int pr2 = 0; pr2 < 2; pr2++){
                        int brow = wn + pr2*16 + (t4 >> 1)*8 + lr;
                        unsigned off = (unsigned)((10240 + buf*4*2560 + g*2*2560
                                                   + brow*40 + kh + (t4 & 1)*8)*2);
                        unsigned th[4], tl[4];
                        ldsm_x4(th, smB + off);
                        ldsm_x4(tl, smB + off + 2560*2);
                        unsigned bh0[2] = {th[0], th[1]}, bh1[2] = {th[2], th[3]};
                        unsigned bl0[2] = {tl[0], tl[1]}, bl1[2] = {tl[2], tl[3]};
                        mma_bf16(acc[g][2*pr2],   ah, bh0);
                        mma_bf16(acc[g][2*pr2],   ah, bl0);
                        mma_bf16(acc[g][2*pr2],   al, bh0);
                        mma_bf16(acc[g][2*pr2+1], ah, bh1);
                        mma_bf16(acc[g][2*pr2+1], ah, bl1);
                        mma_bf16(acc[g][2*pr2+1], al, bh1);
                    }
                }
            }
            __syncthreads();
            buf ^= 1;
        }

        #pragma unroll
        for (int nt = 0; nt < 4; nt++){
            int row0 = bm + wm + (lane >> 2);
            int col  = bn + wn + nt*8 + (lane & 3)*2;
            if (col >= N) continue;
            float b10 = p.b1[col], b11 = p.b1[col + 1];
            float b20 = p.b2[col], b21 = p.b2[col + 1];
            float o0 = sigmoid_f(acc[0][nt][0] + b10)*(acc[1][nt][0] + b20);
            float o1 = sigmoid_f(acc[0][nt][1] + b11)*(acc[1][nt][1] + b21);
            float o2 = sigmoid_f(acc[0][nt][2] + b10)*(acc[1][nt][2] + b20);
            float o3 = sigmoid_f(acc[0][nt][3] + b11)*(acc[1][nt][3] + b21);
            if (row0 < M){
                size_t ix = (size_t)row0*N + col;
                if (MODE == 1 && p.sub){
                    p.Cout[ix]     = o0 - p.Cout[ix];
                    p.Cout[ix + 1] = o1 - p.Cout[ix + 1];
                } else {
                    p.Cout[ix] = o0; p.Cout[ix + 1] = o1;
                }
            }
            if (row0 + 8 < M){
                size_t ix = (size_t)(row0+8)*N + col;
                if (MODE == 1 && p.sub){
                    p.Cout[ix]     = o2 - p.Cout[ix];
                    p.Cout[ix + 1] = o3 - p.Cout[ix + 1];
                } else {
                    p.Cout[ix] = o2; p.Cout[ix + 1] = o3;
                }
            }
        }
    }
}

// =============== flash attention ==========================================
__global__ __launch_bounds__(256) void flash_attn(){
    __shared__ __align__(16) bf16 sm[20480];   // 40 KB
    const unsigned smB = (unsigned)__cvta_generic_to_shared(sm);
    const int bh = blockIdx.y;
    const int b = bh >> 3, h = bh & 7;
    const int i0 = blockIdx.x * 128;
    const bf16* qH = p_qkv +           (size_t)b*NTOK*D + h*EH;
    const bf16* qL = qH + 3*MD;
    const bf16* kH = p_qkv +    MD +   (size_t)b*NTOK*D + h*EH;
    const bf16* kL = kH + 3*MD;
    const bf16* vH = p_qkv +  2*MD +   (size_t)b*NTOK*D + h*EH;
    const bf16* vL = vH + 3*MD;

    const int tid = threadIdx.x, lane = tid & 31, w = tid >> 5;
    const int t4 = lane >> 3, lr = lane & 7;

    {
        int row = tid >> 1, c = (tid & 1)*16;
        int gi = i0 + row;
        bool ok = gi < NTOK;
        size_t so = (size_t)(ok ? gi : 0)*D + c;
        const float4 z4 = make_float4(0.f,0.f,0.f,0.f);
        float4 f0 = ok ? *(const float4*)(qH + so)     : z4;
        float4 f1 = ok ? *(const float4*)(qH + so + 8) : z4;
        *(float4*)&sm[row*40 + c]     = f0;
        *(float4*)&sm[row*40 + c + 8] = f1;
        f0 = ok ? *(const float4*)(qL + so)     : z4;
        f1 = ok ? *(const float4*)(qL + so + 8) : z4;
        *(float4*)&sm[5120 + row*40 + c]     = f0;
        *(float4*)&sm[5120 + row*40 + c + 8] = f1;
    }
    __syncthreads();
    unsigned qh[2][4], ql[2][4];
    #pragma unroll
    for (int kc = 0; kc < 2; kc++){
        int row = w*16 + (t4 & 1)*8 + lr;
        int col = kc*16 + (t4 >> 1)*8;
        ldsm_x4(qh[kc], smB + (unsigned)((row*40 + col)*2));
        ldsm_x4(ql[kc], smB + (unsigned)((5120 + row*40 + col)*2));
    }
    __syncthreads();

    const int ldr = tid >> 2, ldc = (tid & 3)*8;
    auto loadkv = [&](int s, int j0){
        int gj = j0 + ldr;
        bool ok = gj < NTOK;
        size_t so = (size_t)(ok ? gj : 0)*D + ldc;
        unsigned doff = (unsigned)(s*5120 + (ldr*40 + ldc)*2);
        cp16(smB + doff,         kH + so, ok);
        cp16(smB + 10240 + doff, kL + so, ok);
        cp16(smB + 20480 + doff, vH + so, ok);
        cp16(smB + 30720 + doff, vL + so, ok);
        cpcommit();
    };

    float o[4][4];
    #pragma unroll
    for (int j = 0; j < 4; j++)
        #pragma unroll
        for (int q = 0; q < 4; q++) o[j][q] = 0.f;
    float m0 = -1e30f, m1 = -1e30f, l0 = 0.f, l1 = 0.f;
    const float scale = 0.17677669529663688f;

    loadkv(0, 0);
    int buf = 0;
    const int NJT = 14;
    for (int jt = 0; jt < NJT; jt++){
        const int j0 = jt*64;
        if (jt + 1 < NJT){ loadkv(buf ^ 1, (jt+1)*64); cpwait<1>(); }
        else cpwait<0>();
        __syncthreads();

        float s[8][4];
        #pragma unroll
        for (int nt = 0; nt < 8; nt++)
            #pragma unroll
            for (int q = 0; q < 4; q++) s[nt][q] = 0.f;

        #pragma unroll
        for (int kc = 0; kc < 2; kc++){
            #pragma unroll
            for (int pr = 0; pr < 4; pr++){
                int brow = pr*16 + (t4 >> 1)*8 + lr;
                int col  = kc*16 + (t4 & 1)*8;
                unsigned off = (unsigned)(buf*5120 + (brow*40 + col)*2);
                unsigned th[4], tl[4];
                ldsm_x4(th, smB + off);
                ldsm_x4(tl, smB + 10240 + off);
                unsigned bh0[2] = {th[0], th[1]}, bh1[2] = {th[2], th[3]};
                unsigned bl0[2] = {tl[0], tl[1]}, bl1[2] = {tl[2], tl[3]};
                mma_bf16(s[2*pr],   qh[kc], bh0);
                mma_bf16(s[2*pr],   qh[kc], bl0);
                mma_bf16(s[2*pr],   ql[kc], bh0);
                mma_bf16(s[2*pr+1], qh[kc], bh1);
                mma_bf16(s[2*pr+1], qh[kc], bl1);
                mma_bf16(s[2*pr+1], ql[kc], bh1);
            }
        }

        #pragma unroll
        for (int nt = 0; nt < 8; nt++)
            #pragma unroll
            for (int q = 0; q < 4; q++) s[nt][q] *= scale;
        if (j0 + 64 > NTOK){
            #pragma unroll
            for (int nt = 0; nt < 8; nt++){
                int c0 = j0 + nt*8 + (lane & 3)*2;
                if (c0     >= NTOK){ s[nt][0] = -1e30f; s[nt][2] = -1e30f; }
                if (c0 + 1 >= NTOK){ s[nt][1] = -1e30f; s[nt][3] = -1e30f; }
            }
        }

        float rm0 = -1e30f, rm1 = -1e30f;
        #pragma unroll
        for (int nt = 0; nt < 8; nt++){
            rm0 = fmaxf(rm0, fmaxf(s[nt][0], s[nt][1]));
            rm1 = fmaxf(rm1, fmaxf(s[nt][2], s[nt][3]));
        }
        rm0 = fmaxf(rm0, __shfl_xor_sync(0xffffffffu, rm0, 1));
        rm0 = fmaxf(rm0, __shfl_xor_sync(0xffffffffu, rm0, 2));
        rm1 = fmaxf(rm1, __shfl_xor_sync(0xffffffffu, rm1, 1));
        rm1 = fmaxf(rm1, __shfl_xor_sync(0xffffffffu, rm1, 2));
        float nm0 = fmaxf(m0, rm0), nm1 = fmaxf(m1, rm1);
        float a0 = __expf(m0 - nm0), a1 = __expf(m1 - nm1);
        float ps0 = 0.f, ps1 = 0.f;
        #pragma unroll
        for (int nt = 0; nt < 8; nt++){
            s[nt][0] = __expf(s[nt][0] - nm0);
            s[nt][1] = __expf(s[nt][1] - nm0);
            s[nt][2] = __expf(s[nt][2] - nm1);
            s[nt][3] = __expf(s[nt][3] - nm1);
            ps0 += s[nt][0] + s[nt][1];
            ps1 += s[nt][2] + s[nt][3];
        }
        ps0 += __shfl_xor_sync(0xffffffffu, ps0, 1);
        ps0 += __shfl_xor_sync(0xffffffffu, ps0, 2);
        ps1 += __shfl_xor_sync(0xffffffffu, ps1, 1);
        ps1 += __shfl_xor_sync(0xffffffffu, ps1, 2);
        l0 = l0*a0 + ps0; l1 = l1*a1 + ps1;
        m0 = nm0; m1 = nm1;
        #pragma unroll
        for (int nt = 0; nt < 4; nt++){
            o[nt][0] *= a0; o[nt][1] *= a0;
            o[nt][2] *= a1; o[nt][3] *= a1;
        }

        #pragma unroll
        for (int kc2 = 0; kc2 < 4; kc2++){
            unsigned pah[4], pal[4];
            {
                const float* u = s[2*kc2];
                const float* v2 = s[2*kc2 + 1];
                bf16 h0,lo0,h1,lo1;
                splitv(u[0], h0, lo0); splitv(u[1], h1, lo1);
                pah[0] = pack2u(h0, h1);   pal[0] = pack2u(lo0, lo1);
                splitv(u[2], h0, lo0); splitv(u[3], h1, lo1);
                pah[1] = pack2u(h0, h1);   pal[1] = pack2u(lo0, lo1);
                splitv(v2[0], h0, lo0); splitv(v2[1], h1, lo1);
                pah[2] = pack2u(h0, h1);   pal[2] = pack2u(lo0, lo1);
                splitv(v2[2], h0, lo0); splitv(v2[3], h1, lo1);
                pah[3] = pack2u(h0, h1);   pal[3] = pack2u(lo0, lo1);
            }
            #pragma unroll
            for (int pr2 = 0; pr2 < 2; pr2++){
                int krow = kc2*16 + (t4 & 1)*8 + lr;
                int ncol = pr2*16 + (t4 >> 1)*8;
                unsigned off = (unsigned)(buf*5120 + (krow*40 + ncol)*2);
                unsigned th[4], tl[4];
                ldsm_x4t(th, smB + 20480 + off);
                ldsm_x4t(tl, smB + 30720 + off);
                unsigned bh0[2] = {th[0], th[1]}, bh1[2] = {th[2], th[3]};
                unsigned bl0[2] = {tl[0], tl[1]}, bl1[2] = {tl[2], tl[3]};
                mma_bf16(o[2*pr2],   pah, bh0);
                mma_bf16(o[2*pr2],   pah, bl0);
                mma_bf16(o[2*pr2],   pal, bh0);
                mma_bf16(o[2*pr2+1], pah, bh1);
                mma_bf16(o[2*pr2+1], pah, bl1);
                mma_bf16(o[2*pr2+1], pal, bh1);
            }
        }
        __syncthreads();
        buf ^= 1;
    }

    float inv0 = 1.f / l0, inv1 = 1.f / l1;
    #pragma unroll
    for (int nt = 0; nt < 4; nt++){
        int row0 = i0 + w*16 + (lane >> 2);
        int col  = nt*8 + (lane & 3)*2;
        if (row0 < NTOK){
            size_t dst = ((size_t)b*NTOK + row0)*D + h*EH + col;
            bf16 h0,lo0,h1,lo1;
            splitv(o[nt][0]*inv0, h0, lo0); splitv(o[nt][1]*inv0, h1, lo1);
            *(__nv_bfloat162*)(p_att + dst)      = __halves2bfloat162(h0, h1);
            *(__nv_bfloat162*)(p_att + MD + dst) = __halves2bfloat162(lo0, lo1);
        }
        if (row0 + 8 < NTOK){
            size_t dst = ((size_t)b*NTOK + row0 + 8)*D + h*EH + col;
            bf16 h2,lo2,h3,lo3;
            splitv(o[nt][2]*inv1, h2, lo2); splitv(o[nt][3]*inv1, h3, lo3);
            *(__nv_bfloat162*)(p_att + dst)      = __halves2bfloat162(h2, h3);
            *(__nv_bfloat162*)(p_att + MD + dst) = __halves2bfloat162(lo2, lo3);
        }
    }
}

// ---------------- LayerNorm(x [- sub]) over D=256 (+ optional planes) ----
__global__ __launch_bounds__(256) void ln_kernel(const float* __restrict__ X,
                                                 const float* __restrict__ Sub,
                                                 const float* __restrict__ g,
                                                 const float* __restrict__ beta,
                                                 float* __restrict__ Out,
                                                 bf16* __restrict__ pH,
                                                 bf16* __restrict__ pL){
    int row = blockIdx.x, d = threadIdx.x;
    size_t i = (size_t)row*D + d;
    float v = X[i] - (Sub ? Sub[i] : 0.f);
    float2 r = blockReduce2(v, v*v);
    float mean = r.x * (1.f/D);
    float var  = r.y * (1.f/D) - mean*mean;
    float o = (v - mean) * rsqrtf(var + EPS) * g[d] + beta[d];
    Out[i] = o;
    if (pH){
        bf16 hh, ll; splitv(o, hh, ll);
        pH[i] = hh; pL[i] = ll;
    }
}

// ---------------- final: transpose + de-standardize + 2-scale mean --------
__global__ __launch_bounds__(256) void final_kernel(float* __restrict__ out, int t){
    __shared__ float tile[32][33];
    int b = blockIdx.z;
    int p0 = blockIdx.x*32, n0 = blockIdx.y*32;
    int tx = threadIdx.x & 31, ty = threadIdx.x >> 5;
    #pragma unroll
    for (int i = 0; i < 4; i++){
        int n = n0 + ty + i*8, pp = p0 + tx;
        if (n < ENC && pp < DB)
            tile[ty + i*8][tx] = g_out[((size_t)b*NTOK + n)*DB + pp];
    }
    __syncthreads();
    #pragma unroll
    for (int i = 0; i < 4; i++){
        int pp = p0 + ty + i*8, n = n0 + tx;
        if (pp < DB && n < ENC){
            float v = tile[tx][ty + i*8]*g_std[b*ENC + n] + g_mean[b*ENC + n];
            v *= 0.5f;
            size_t idx = ((size_t)b*DB + pp)*ENC + n;
            if (t == 0) out[idx] = v; else out[idx] += v;
        }
    }
}

// ---------------- host ----------------
static inline int gsz(int nt){ return nt < 296 ? nt : 296; }
static void* sym(const void* s){ void* p; cudaGetSymbolAddress(&p, s); return p; }

extern "C" void kernel_launch(void* const* d_in, const int* in_sizes, int n_in,
                              void* d_out, int out_size){
    const float* mbx  = (const float*)d_in[0];
    const float* mbxm = (const float*)d_in[1];
    const float* embW = (const float*)d_in[4];
    const float* embB = (const float*)d_in[5];
    const float* Wq = (const float*)d_in[6];
    const float* Wk = (const float*)d_in[7];
    const float* Wv = (const float*)d_in[8];
    const float* Wo = (const float*)d_in[9];
    const float* W3 = (const float*)d_in[10];
    const float* W4 = (const float*)d_in[11];
    const float* bq = (const float*)d_in[12];
    const float* bk = (const float*)d_in[13];
    const float* bv = (const float*)d_in[14];
    const float* bo = (const float*)d_in[15];
    const float* b3 = (const float*)d_in[16];
    const float* b4 = (const float*)d_in[17];
    const float* W1 = (const float*)d_in[18];
    const float* b1 = (const float*)d_in[19];
    const float* W2 = (const float*)d_in[20];
    const float* b2 = (const float*)d_in[21];
    const float* W5 = (const float*)d_in[22];
    const float* b5 = (const float*)d_in[23];
    const float* W6 = (const float*)d_in[24];
    const float* b6 = (const float*)d_in[25];
    const float* ln1g = (const float*)d_in[26];
    const float* ln1b = (const float*)d_in[27];
    const float* ln2g = (const float*)d_in[28];
    const float* ln2b = (const float*)d_in[29];
    float* out = (float*)d_out;

    float* hF   = (float*)sym(g_h);
    float* xatt = (float*)sym(g_xatt);
    float* xln  = (float*)sym(g_xln);
    float* hhF  = (float*)sym(g_hh);
    float* outF = (float*)sym(g_out);

    bf16* xinP = (bf16*)sym(p_xin);
    bf16* hP   = (bf16*)sym(p_h);
    bf16* qkvP = (bf16*)sym(p_qkv);
    bf16* attP = (bf16*)sym(p_att);
    bf16* xlnP = (bf16*)sym(p_xln);
    bf16* y1P  = (bf16*)sym(p_y1);
    bf16* xsP  = (bf16*)sym(p_xs);
    bf16* xattP = (bf16*)sym(p_xatt);
    bf16* yP   = (bf16*)sym(p_y);
    bf16* embWP = (bf16*)sym(p_embW);
    bf16* WqP = (bf16*)sym(p_Wq); bf16* WkP = (bf16*)sym(p_Wk);
    bf16* WvP = (bf16*)sym(p_Wv); bf16* WoP = (bf16*)sym(p_Wo);
    bf16* W3P = (bf16*)sym(p_W3); bf16* W4P = (bf16*)sym(p_W4);
    bf16* W1P = (bf16*)sym(p_W1); bf16* W2P = (bf16*)sym(p_W2);
    bf16* W5P = (bf16*)sym(p_W5); bf16* W6P = (bf16*)sym(p_W6);

    const size_t EWN = (size_t)256*SEQP;
    const size_t WDD = (size_t)LAYERS*D*D;
    const size_t W1N = (size_t)LAYERS*DFF*D;
    const size_t W5N = (size_t)LAYERS*DB*2*D;
    const size_t Y1N = (size_t)MROWS*DFF;

    cudaFuncSetAttribute(mma_gemm<0>, cudaFuncAttributeMaxDynamicSharedMemorySize, 61440);
    cudaFuncSetAttribute(mma_gemm<1>, cudaFuncAttributeMaxDynamicSharedMemorySize, 61440);
    cudaFuncSetAttribute(mma_gemm<2>, cudaFuncAttributeMaxDynamicSharedMemorySize, 61440);
    cudaFuncSetAttribute(mma_gemm2<0>, cudaFuncAttributeMaxDynamicSharedMemorySize, 61440);
    cudaFuncSetAttribute(mma_gemm2<1>, cudaFuncAttributeMaxDynamicSharedMemorySize, 61440);

    // weight splits (one batched launch + embed pad)
    {
        WSArgs ws;
        const float* ss[10] = {Wq, Wk, Wv, Wo, W3, W4, W1, W2, W5, W6};
        bf16* hh[10] = {WqP, WkP, WvP, WoP, W3P, W4P, W1P, W2P, W5P, W6P};
        size_t nn[10] = {WDD, WDD, WDD, WDD, WDD, WDD, W1N, W1N, W5N, W5N};
        for (int i = 0; i < 10; i++){
            ws.s[i] = ss[i]; ws.h[i] = hh[i]; ws.l[i] = hh[i] + nn[i]; ws.n[i] = (int)nn[i];
        }
        wsplit_all<<<dim3(288, 10), 256>>>(ws);
        wsplit_pad<<<(unsigned)((EWN + 255)/256), 256>>>(embW, embWP, embWP + EWN, 256, SEQ, SEQP);
    }

    const int tm = 55;    // ceil(6928/128)
    const int tm64 = 109; // ceil(6928/64)

    for (int t = 0; t < TS; t++){
        stats_kernel<<<dim3((ENC + 255)/256, B_), 256>>>(mbx, t);
        xin_kernel<<<dim3((SEQP + 31)/32, (NTOK + 31)/32, B_), 256>>>(mbx, mbxm, t);

        {   // embed -> fp32 h + planes
            GemmArgs a = {};
            a.aH[0] = xinP; a.aL[0] = xinP + XN;
            a.wH[0] = embWP; a.wL[0] = embWP + EWN;
            a.bias[0] = embB; a.C[0] = hF;
            a.cH[0] = hP; a.cL[0] = hP + MD;
            mma_gemm<0><<<gsz(tm*4), 256, 61440>>>(a, MROWS, D, SEQP, 4, tm*4, tm*4);
        }

        for (int l = 0; l < LAYERS; l++){
            {   // QKV -> planes
                GemmArgs a = {};
                for (int z = 0; z < 3; z++){
                    a.aH[z] = hP; a.aL[z] = hP + MD;
                    a.cH[z] = qkvP + (size_t)z*MD;
                    a.cL[z] = qkvP + 3*MD + (size_t)z*MD;
                }
                a.wH[0] = WqP + (size_t)l*D*D; a.wL[0] = WqP + WDD + (size_t)l*D*D;
                a.wH[1] = WkP + (size_t)l*D*D; a.wL[1] = WkP + WDD + (size_t)l*D*D;
                a.wH[2] = WvP + (size_t)l*D*D; a.wL[2] = WvP + WDD + (size_t)l*D*D;
                a.bias[0] = bq + l*D; a.bias[1] = bk + l*D; a.bias[2] = bv + l*D;
                mma_gemm<0><<<gsz(tm*4*3), 256, 61440>>>(a, MROWS, D, D, 4, tm*4, tm*4*3);
            }

            flash_attn<<<dim3(7, B_*NH), 256>>>();

            {   // Wo -> fp32 xatt + planes
                GemmArgs a = {};
                a.aH[0] = attP; a.aL[0] = attP + MD;
                a.wH[0] = WoP + (size_t)l*D*D; a.wL[0] = WoP + WDD + (size_t)l*D*D;
                a.bias[0] = bo + l*D; a.C[0] = xatt;
                a.cH[0] = xattP; a.cL[0] = xattP + MD;
                mma_gemm<0><<<gsz(tm*4), 256, 61440>>>(a, MROWS, D, D, 4, tm*4, tm*4);
            }

            ln_kernel<<<MROWS, 256>>>(hF, xatt, ln1g + l*D, ln1b + l*D, xln,
                                      xlnP, xlnP + MD);

            {   // W1 + GELU -> y1 planes
                GemmArgs a = {};
                a.aH[0] = xlnP; a.aL[0] = xlnP + MD;
                a.wH[0] = W1P + (size_t)l*DFF*D; a.wL[0] = W1P + W1N + (size_t)l*DFF*D;
                a.bias[0] = b1 + l*DFF;
                a.cH[0] = y1P; a.cL[0] = y1P + Y1N;
                mma_gemm<1><<<gsz(tm*8), 256, 61440>>>(a, MROWS, DFF, D, 8, tm*8, tm*8);
            }
            {   // W2 -> y planes + xs=(xln-y) planes (sub fused)
                GemmArgs a = {};
                a.aH[0] = y1P; a.aL[0] = y1P + Y1N;
                a.wH[0] = W2P + (size_t)l*D*DFF; a.wL[0] = W2P + W1N + (size_t)l*D*DFF;
                a.bias[0] = b2 + l*D;
                a.cH[0] = yP; a.cL[0] = yP + MD;
                a.xsub[0] = xln;
                a.c2H[0] = xsP; a.c2L[0] = xsP + MD;
                mma_gemm<2><<<gsz(tm*4), 256, 61440>>>(a, MROWS, D, DFF, 4, tm*4, tm*4);
            }

            {   // fused W3/W4 -> hh = sigmoid(.)*(.)
                Gemm2Args a = {};
                a.a0H = xsP; a.a0L = xsP + MD; a.a1H = xsP; a.a1L = xsP + MD;
                a.kSplit = 1 << 30; a.aStride = D;
                a.w1H = W3P + (size_t)l*D*D; a.w1L = W3P + WDD + (size_t)l*D*D;
                a.w2H = W4P + (size_t)l*D*D; a.w2L = W4P + WDD + (size_t)l*D*D;
                a.b1 = b3 + l*D; a.b2 = b4 + l*D;
                a.Cout = hhF; a.sub = 0;
                mma_gemm2<0><<<gsz(tm64*4), 256, 61440>>>(a, MROWS, D, D, 4, tm64*4);
            }

            {   // fused W5/W6 over cat(xatt,y) -> g_out (with layer subtract)
                Gemm2Args a = {};
                a.a0H = xattP; a.a0L = xattP + MD;
                a.a1H = yP;    a.a1L = yP + MD;
                a.kSplit = D; a.aStride = D;
                a.w1H = W5P + (size_t)l*DB*2*D; a.w1L = W5P + W5N + (size_t)l*DB*2*D;
                a.w2H = W6P + (size_t)l*DB*2*D; a.w2L = W6P + W5N + (size_t)l*DB*2*D;
                a.b1 = b5 + l*DB; a.b2 = b6 + l*DB;
                a.Cout = outF; a.sub = l;
                mma_gemm2<1><<<gsz(tm64*12), 256, 61440>>>(a, MROWS, DB, 2*D, 12, tm64*12);
            }

            ln_kernel<<<MROWS, 256>>>(hhF, (const float*)nullptr,
                                      ln2g + l*D, ln2b + l*D, hF, hP, hP + MD);
        }

        final_kernel<<<dim3((DB + 31)/32, (ENC + 31)/32, B_), 256>>>(out, t);
    }
}

// round 11
// speedup vs baseline: 1.0885x; 1.0161x over previous
#include <cuda_runtime.h>
#include <cuda_bf16.h>
#include <math.h>

#define B_    8
#define TS    2
#define SEQ   720
#define SEQP  736
#define ENC   862
#define MARKD 4
#define NTOK  866
#define D     256
#define NH    8
#define EH    32
#define DFF   512
#define DB    720
#define LAYERS 2
#define EPS   1e-5f
#define MROWS (B_*NTOK)   // 6928
#define MD    ((size_t)MROWS*D)
#define XN    ((size_t)MROWS*SEQP)

typedef __nv_bfloat16 bf16;

// ---------------- fp32 scratch ----------------
__device__ float g_mean[B_*ENC], g_std[B_*ENC];
__device__ float g_h[MD], g_xatt[MD], g_xln[MD], g_hh[MD];
__device__ float g_out[(size_t)MROWS*DB];

// ---------------- bf16 hi/lo planes (lo at +n) ----------------
__device__ __align__(16) bf16 p_xin[2*XN];
__device__ __align__(16) bf16 p_h  [2*MD];
__device__ __align__(16) bf16 p_qkv[2*3*MD];
__device__ __align__(16) bf16 p_att[2*MD];
__device__ __align__(16) bf16 p_xln[2*MD];
__device__ __align__(16) bf16 p_y1 [2*(size_t)MROWS*DFF];
__device__ __align__(16) bf16 p_xs [2*MD];
__device__ __align__(16) bf16 p_xatt[2*MD];
__device__ __align__(16) bf16 p_y  [2*MD];
// weights
__device__ __align__(16) bf16 p_embW[2*256*SEQP];
__device__ __align__(16) bf16 p_Wq[2*LAYERS*D*D], p_Wk[2*LAYERS*D*D], p_Wv[2*LAYERS*D*D];
__device__ __align__(16) bf16 p_Wo[2*LAYERS*D*D], p_W3[2*LAYERS*D*D], p_W4[2*LAYERS*D*D];
__device__ __align__(16) bf16 p_W1[2*LAYERS*DFF*D], p_W2[2*LAYERS*D*DFF];
__device__ __align__(16) bf16 p_W5[2*LAYERS*DB*2*D], p_W6[2*LAYERS*DB*2*D];

// ---------------- helpers ----------------
__device__ __forceinline__ void splitv(float x, bf16& h, bf16& l){
    h = __float2bfloat16(x);
    l = __float2bfloat16(x - __bfloat162float(h));
}
__device__ __forceinline__ unsigned pack2u(bf16 a, bf16 b){
    __nv_bfloat162 t = __halves2bfloat162(a, b);
    return *(unsigned*)&t;
}
__device__ __forceinline__ void mma_bf16(float c[4], const unsigned a[4], const unsigned b[2]){
    asm volatile("mma.sync.aligned.m16n8k16.row.col.f32.bf16.bf16.f32 "
                 "{%0,%1,%2,%3}, {%4,%5,%6,%7}, {%8,%9}, {%0,%1,%2,%3};\n"
                 : "+f"(c[0]), "+f"(c[1]), "+f"(c[2]), "+f"(c[3])
                 : "r"(a[0]), "r"(a[1]), "r"(a[2]), "r"(a[3]),
                   "r"(b[0]), "r"(b[1]));
}
__device__ __forceinline__ void ldsm_x4(unsigned r[4], unsigned addr){
    asm volatile("ldmatrix.sync.aligned.m8n8.x4.shared.b16 {%0,%1,%2,%3}, [%4];\n"
                 : "=r"(r[0]), "=r"(r[1]), "=r"(r[2]), "=r"(r[3]) : "r"(addr));
}
__device__ __forceinline__ void ldsm_x4t(unsigned r[4], unsigned addr){
    asm volatile("ldmatrix.sync.aligned.m8n8.x4.trans.shared.b16 {%0,%1,%2,%3}, [%4];\n"
                 : "=r"(r[0]), "=r"(r[1]), "=r"(r[2]), "=r"(r[3]) : "r"(addr));
}
__device__ __forceinline__ void cp16(unsigned dst, const void* src, bool p){
    int sz = p ? 16 : 0;
    asm volatile("cp.async.cg.shared.global [%0], [%1], 16, %2;\n"
                 :: "r"(dst), "l"(src), "r"(sz));
}
__device__ __forceinline__ void cpcommit(){ asm volatile("cp.async.commit_group;\n"); }
template<int N> __device__ __forceinline__ void cpwait(){
    asm volatile("cp.async.wait_group %0;\n" :: "n"(N));
}
__device__ __forceinline__ float gelu_f(float x){
    return 0.5f*x*(1.f + erff(x*0.70710678118654752f));
}
__device__ __forceinline__ float sigmoid_f(float x){
    return 1.f/(1.f + expf(-x));
}
// reduce (a, b) simultaneously across block
__device__ __forceinline__ float2 blockReduce2(float a, float b){
    __shared__ float2 sh[33];
    int lane = threadIdx.x & 31, wid = threadIdx.x >> 5;
    __syncthreads();
    #pragma unroll
    for (int o = 16; o; o >>= 1){
        a += __shfl_down_sync(0xffffffffu, a, o);
        b += __shfl_down_sync(0xffffffffu, b, o);
    }
    if (lane == 0) sh[wid] = make_float2(a, b);
    __syncthreads();
    if (wid == 0){
        int nw = blockDim.x >> 5;
        float2 v = (lane < nw) ? sh[lane] : make_float2(0.f, 0.f);
        a = v.x; b = v.y;
        #pragma unroll
        for (int o = 16; o; o >>= 1){
            a += __shfl_down_sync(0xffffffffu, a, o);
            b += __shfl_down_sync(0xffffffffu, b, o);
        }
        if (lane == 0) sh[32] = make_float2(a, b);
    }
    __syncthreads();
    return sh[32];
}

// ---------------- weight split (batched) ----------------
struct WSArgs { const float* s[10]; bf16* h[10]; bf16* l[10]; int n[10]; };
__global__ void wsplit_all(WSArgs w){
    int z = blockIdx.y;
    int n = w.n[z];
    const float* src = w.s[z];
    bf16* hh = w.h[z]; bf16* ll = w.l[z];
    for (int i = blockIdx.x*blockDim.x + threadIdx.x; i < n; i += gridDim.x*blockDim.x)
        splitv(src[i], hh[i], ll[i]);
}
__global__ void wsplit_pad(const float* __restrict__ s, bf16* __restrict__ h,
                           bf16* __restrict__ l, int rows, int K, int Kp){
    size_t i = (size_t)blockIdx.x*blockDim.x + threadIdx.x;
    size_t total = (size_t)rows*Kp;
    if (i >= total) return;
    int c = (int)(i % Kp); int r = (int)(i / Kp);
    float v = (c < K) ? s[(size_t)r*K + c] : 0.f;
    splitv(v, h[i], l[i]);
}

// ---------------- input standardization ----------------
__global__ void stats_kernel(const float* __restrict__ mbx, int t){
    int b = blockIdx.y;
    int n = blockIdx.x * blockDim.x + threadIdx.x;
    if (n >= ENC) return;
    const float* base = mbx + ((size_t)(b*TS + t)*SEQ)*ENC + n;
    float s = 0.f, ss = 0.f;
    for (int i = 0; i < SEQ; i++){
        float v = base[(size_t)i*ENC];
        s += v; ss += v*v;
    }
    float m = s * (1.f/SEQ);
    float var = ss * (1.f/SEQ) - m*m;
    g_mean[b*ENC + n] = m;
    g_std [b*ENC + n] = sqrtf(var + EPS);
}

// transposed tiled build of xin planes: read coalesced over n, write over s
__global__ __launch_bounds__(256) void xin_kernel(const float* __restrict__ mbx,
                                                  const float* __restrict__ mbxm, int t){
    __shared__ float tile[32][33];
    const int b = blockIdx.z;
    const int s0 = blockIdx.x*32, n0 = blockIdx.y*32;
    const int tx = threadIdx.x & 31, ty = threadIdx.x >> 5;
    #pragma unroll
    for (int i = 0; i < 4; i++){
        int s = s0 + ty + i*8, n = n0 + tx;
        float v = 0.f;
        if (s < SEQ && n < NTOK){
            if (n < ENC){
                v = mbx[((size_t)(b*TS + t)*SEQ + s)*ENC + n];
                v = (v - g_mean[b*ENC + n]) / g_std[b*ENC + n];
            } else {
                v = mbxm[((size_t)(b*TS + t)*SEQ + s)*MARKD + (n - ENC)];
            }
        }
        tile[ty + i*8][tx] = v;
    }
    __syncthreads();
    #pragma unroll
    for (int i = 0; i < 4; i++){
        int n = n0 + ty + i*8, s = s0 + tx;
        if (n < NTOK && s < SEQP){
            size_t idx = ((size_t)b*NTOK + n)*SEQP + s;
            splitv(tile[tx][ty + i*8], p_xin[idx], p_xin[XN + idx]);
        }
    }
}

// =============== MMA GEMM: C = A @ W^T + bias (bf16 planes, cp.async) =====
// ACT 0: plain; 1: gelu; 2: emit y planes + (xsub - y) planes
struct GemmArgs {
    const bf16 *aH[3], *aL[3], *wH[3], *wL[3];
    const float* bias[3];
    float* C[3];
    bf16 *cH[3], *cL[3];
    const float* xsub[3];
    bf16 *c2H[3], *c2L[3];
};

template<int ACT>
__global__ __launch_bounds__(256, 3)
void mma_gemm(GemmArgs p, int M, int N, int K, int tilesN, int tpz, int nTiles){
    extern __shared__ __align__(16) char smraw[];
    bf16* sAh = (bf16*)smraw;            // [2][128][40]
    bf16* sAl = sAh + 2*128*40;
    bf16* sBh = sAl + 2*128*40;          // [2][64][40]
    bf16* sBl = sBh + 2*64*40;
    const unsigned aHiB = (unsigned)__cvta_generic_to_shared(sAh);
    const unsigned aLoB = (unsigned)__cvta_generic_to_shared(sAl);
    const unsigned bHiB = (unsigned)__cvta_generic_to_shared(sBh);
    const unsigned bLoB = (unsigned)__cvta_generic_to_shared(sBl);

    const int tid = threadIdx.x;
    const int lane = tid & 31, w = tid >> 5;
    const int wm = (w >> 1)*32, wn = (w & 1)*32;
    const int t4 = lane >> 3, lr = lane & 7;
    const int ldr = tid >> 2, ldc = (tid & 3)*8;

    for (int t = blockIdx.x; t < nTiles; t += gridDim.x){
        const int z  = t / tpz;
        const int rr = t - z*tpz;
        const int bm = (rr / tilesN)*128, bn = (rr % tilesN)*64;
        const bf16* __restrict__ aHp = p.aH[z];
        const bf16* __restrict__ aLp = p.aL[z];
        const bf16* __restrict__ wHp = p.wH[z];
        const bf16* __restrict__ wLp = p.wL[z];
        const float* __restrict__ bias = p.bias[z];
        float* Cp = p.C[z];
        bf16* cHp = p.cH[z];
        bf16* cLp = p.cL[z];

        float acc[2][4][4];
        #pragma unroll
        for (int i = 0; i < 2; i++)
            #pragma unroll
            for (int j = 0; j < 4; j++)
                #pragma unroll
                for (int q = 0; q < 4; q++) acc[i][j][q] = 0.f;

        auto loadst = [&](int s, int k0){
            #pragma unroll
            for (int rep = 0; rep < 2; rep++){
                int r = ldr + rep*64;
                int gm = bm + r;
                bool pr = gm < M;
                size_t so = (size_t)(pr ? gm : 0)*K + k0 + ldc;
                unsigned doff = (unsigned)(((s*128 + r)*40 + ldc)*2);
                cp16(aHiB + doff, aHp + so, pr);
                cp16(aLoB + doff, aLp + so, pr);
            }
            {
                int gn = bn + ldr;
                bool pn = gn < N;
                size_t so = (size_t)(pn ? gn : 0)*K + k0 + ldc;
                unsigned doff = (unsigned)(((s*64 + ldr)*40 + ldc)*2);
                cp16(bHiB + doff, wHp + so, pn);
                cp16(bLoB + doff, wLp + so, pn);
            }
            cpcommit();
        };

        loadst(0, 0);
        int buf = 0;
        const int KT = K >> 5;
        for (int kt = 0; kt < KT; kt++){
            if (kt + 1 < KT){ loadst(buf ^ 1, (kt+1)*32); cpwait<1>(); }
            else cpwait<0>();
            __syncthreads();

            #pragma unroll
            for (int kh = 0; kh < 32; kh += 16){
                unsigned ah[2][4], al[2][4], bh[4][2], bl[4][2];
                #pragma unroll
                for (int mt = 0; mt < 2; mt++){
                    int arow = wm + mt*16 + (t4 & 1)*8 + lr;
                    unsigned off = (unsigned)((((buf*128) + arow)*40 + kh + (t4 >> 1)*8)*2);
                    ldsm_x4(ah[mt], aHiB + off);
                    ldsm_x4(al[mt], aLoB + off);
                }
                #pragma unroll
                for (int pr2 = 0; pr2 < 2; pr2++){
                    int brow = wn + pr2*16 + (t4 >> 1)*8 + lr;
                    unsigned off = (unsigned)((((buf*64) + brow)*40 + kh + (t4 & 1)*8)*2);
                    unsigned th[4], tl[4];
                    ldsm_x4(th, bHiB + off);
                    ldsm_x4(tl, bLoB + off);
                    bh[pr2*2][0] = th[0]; bh[pr2*2][1] = th[1];
                    bh[pr2*2+1][0] = th[2]; bh[pr2*2+1][1] = th[3];
                    bl[pr2*2][0] = tl[0]; bl[pr2*2][1] = tl[1];
                    bl[pr2*2+1][0] = tl[2]; bl[pr2*2+1][1] = tl[3];
                }
                #pragma unroll
                for (int mt = 0; mt < 2; mt++)
                    #pragma unroll
                    for (int nt = 0; nt < 4; nt++){
                        mma_bf16(acc[mt][nt], ah[mt], bh[nt]);
                        mma_bf16(acc[mt][nt], ah[mt], bl[nt]);
                        mma_bf16(acc[mt][nt], al[mt], bh[nt]);
                    }
            }
            __syncthreads();
            buf ^= 1;
        }

        #pragma unroll
        for (int mt = 0; mt < 2; mt++)
            #pragma unroll
            for (int nt = 0; nt < 4; nt++){
                int row0 = bm + wm + mt*16 + (lane >> 2);
                int col  = bn + wn + nt*8 + (lane & 3)*2;
                if (col >= N) continue;
                float b0 = bias[col], b1 = bias[col + 1];
                float v0 = acc[mt][nt][0] + b0, v1 = acc[mt][nt][1] + b1;
                float v2 = acc[mt][nt][2] + b0, v3 = acc[mt][nt][3] + b1;
                if (ACT == 1){
                    v0 = gelu_f(v0); v1 = gelu_f(v1);
                    v2 = gelu_f(v2); v3 = gelu_f(v3);
                }
                if (row0 < M){
                    size_t ix = (size_t)row0*N + col;
                    if (Cp){ Cp[ix] = v0; Cp[ix + 1] = v1; }
                    if (cHp){
                        bf16 h0,l0,h1,l1; splitv(v0,h0,l0); splitv(v1,h1,l1);
                        *(__nv_bfloat162*)(cHp + ix) = __halves2bfloat162(h0,h1);
                        *(__nv_bfloat162*)(cLp + ix) = __halves2bfloat162(l0,l1);
                    }
                    if (ACT == 2){
                        float x0 = p.xsub[z][ix], x1 = p.xsub[z][ix + 1];
                        bf16 h0,l0,h1,l1; splitv(x0 - v0,h0,l0); splitv(x1 - v1,h1,l1);
                        *(__nv_bfloat162*)(p.c2H[z] + ix) = __halves2bfloat162(h0,h1);
                        *(__nv_bfloat162*)(p.c2L[z] + ix) = __halves2bfloat162(l0,l1);
                    }
                }
                if (row0 + 8 < M){
                    size_t ix = (size_t)(row0+8)*N + col;
                    if (Cp){ Cp[ix] = v2; Cp[ix + 1] = v3; }
                    if (cHp){
                        bf16 h2,l2,h3,l3; splitv(v2,h2,l2); splitv(v3,h3,l3);
                        *(__nv_bfloat162*)(cHp + ix) = __halves2bfloat162(h2,h3);
                        *(__nv_bfloat162*)(cLp + ix) = __halves2bfloat162(l2,l3);
                    }
                    if (ACT == 2){
                        float x2 = p.xsub[z][ix], x3 = p.xsub[z][ix + 1];
                        bf16 h2,l2,h3,l3; splitv(x2 - v2,h2,l2); splitv(x3 - v3,h3,l3);
                        *(__nv_bfloat162*)(p.c2H[z] + ix) = __halves2bfloat162(h2,h3);
                        *(__nv_bfloat162*)(p.c2L[z] + ix) = __halves2bfloat162(l2,l3);
                    }
                }
            }
    }
}

// =============== fused dual GEMM (BM=64): o = sig(A W1^T+b1)*(A W2^T+b2) ==
// A source switches at kSplit (concat fusion).
// MODE 0: Cout = o ;  MODE 1: Cout = sub ? (o - Cout) : o
struct Gemm2Args {
    const bf16 *a0H, *a0L, *a1H, *a1L;
    int kSplit, aStride;
    const bf16 *w1H, *w1L, *w2H, *w2L;
    const float *b1, *b2;
    float* Cout;
    int sub;
};

template<int MODE>
__global__ __launch_bounds__(256, 3)
void mma_gemm2(Gemm2Args p, int M, int N, int K, int tilesN, int nTiles){
    extern __shared__ __align__(16) char smraw[];
    bf16* sm = (bf16*)smraw;
    const unsigned smB = (unsigned)__cvta_generic_to_shared(sm);
    // elements: A(stage s, plane q): (s*2+q)*2560 (64x40 each)
    //           B: 10240 + (s*4 + g*2 + q)*2560 (64x40 each)
    const int tid = threadIdx.x;
    const int lane = tid & 31, w = tid >> 5;
    const int wm = (w >> 1)*16, wn = (w & 1)*32;
    const int t4 = lane >> 3, lr = lane & 7;
    const int ldr = tid >> 2, ldc = (tid & 3)*8;

    for (int t = blockIdx.x; t < nTiles; t += gridDim.x){
        const int bm = (t / tilesN)*64, bn = (t % tilesN)*64;

        float acc[2][4][4];
        #pragma unroll
        for (int g = 0; g < 2; g++)
            #pragma unroll
            for (int j = 0; j < 4; j++)
                #pragma unroll
                for (int q = 0; q < 4; q++) acc[g][j][q] = 0.f;

        auto loadst = [&](int s, int k0){
            const bf16* aH = (k0 < p.kSplit) ? p.a0H : p.a1H;
            const bf16* aL = (k0 < p.kSplit) ? p.a0L : p.a1L;
            int kk = (k0 < p.kSplit) ? k0 : k0 - p.kSplit;
            int gm = bm + ldr;
            bool pr = gm < M;
            size_t soA = (size_t)(pr ? gm : 0)*p.aStride + kk + ldc;
            unsigned dA = (unsigned)((s*2*2560 + ldr*40 + ldc)*2);
            cp16(smB + dA,           aH + soA, pr);
            cp16(smB + dA + 2560*2,  aL + soA, pr);
            int gn = bn + ldr;
            bool pn = gn < N;
            size_t soB = (size_t)(pn ? gn : 0)*K + k0 + ldc;
            unsigned dB = (unsigned)((10240 + s*4*2560 + ldr*40 + ldc)*2);
            cp16(smB + dB,             p.w1H + soB, pn);
            cp16(smB + dB + 2560*2,    p.w1L + soB, pn);
            cp16(smB + dB + 2*2560*2,  p.w2H + soB, pn);
            cp16(smB + dB + 3*2560*2,  p.w2L + soB, pn);
            cpcommit();
        };

        loadst(0, 0);
        int buf = 0;
        const int KT = K >> 5;
        for (int kt = 0; kt < KT; kt++){
            if (kt + 1 < KT){ loadst(buf ^ 1, (kt+1)*32); cpwait<1>(); }
            else cpwait<0>();
            __syncthreads();

            #pragma unroll
            for (int kh = 0; kh < 32; kh += 16){
                unsigned ah[4], al[4];
                {
                    int arow = wm + (t4 & 1)*8 + lr;
                    unsigned off = (unsigned)((buf*2*2560 + arow*40 + kh + (t4 >> 1)*8)*2);
                    ldsm_x4(ah, smB + off);
                    ldsm_x4(al, smB + off + 2560*2);
                }
                #pragma unroll
                for (int g = 0; g < 2; g++){
                    #pragma unroll
                    for (int pr2 = 0; pr2 < 2; pr2++){
                        int brow = wn + pr2*16 + (t4 >> 1)*8 + lr;
                        unsigned off = (unsigned)((10240 + buf*4*2560 + g*2*2560
                                                   + brow*40 + kh + (t4 & 1)*8)*2);
                        unsigned th[4], tl[4];
                        ldsm_x4(th, smB + off);
                        ldsm_x4(tl, smB + off + 2560*2);
                        unsigned bh0[2] = {th[0], th[1]}, bh1[2] = {th[2], th[3]};
                        unsigned bl0[2] = {tl[0], tl[1]}, bl1[2] = {tl[2], tl[3]};
                        mma_bf16(acc[g][2*pr2],   ah, bh0);
                        mma_bf16(acc[g][2*pr2],   ah, bl0);
                        mma_bf16(acc[g][2*pr2],   al, bh0);
                        mma_bf16(acc[g][2*pr2+1], ah, bh1);
                        mma_bf16(acc[g][2*pr2+1], ah, bl1);
                        mma_bf16(acc[g][2*pr2+1], al, bh1);
                    }
                }
            }
            __syncthreads();
            buf ^= 1;
        }

        #pragma unroll
        for (int nt = 0; nt < 4; nt++){
            int row0 = bm + wm + (lane >> 2);
            int col  = bn + wn + nt*8 + (lane & 3)*2;
            if (col >= N) continue;
            float b10 = p.b1[col], b11 = p.b1[col + 1];
            float b20 = p.b2[col], b21 = p.b2[col + 1];
            float o0 = sigmoid_f(acc[0][nt][0] + b10)*(acc[1][nt][0] + b20);
            float o1 = sigmoid_f(acc[0][nt][1] + b11)*(acc[1][nt][1] + b21);
            float o2 = sigmoid_f(acc[0][nt][2] + b10)*(acc[1][nt][2] + b20);
            float o3 = sigmoid_f(acc[0][nt][3] + b11)*(acc[1][nt][3] + b21);
            if (row0 < M){
                size_t ix = (size_t)row0*N + col;
                if (MODE == 1 && p.sub){
                    p.Cout[ix]     = o0 - p.Cout[ix];
                    p.Cout[ix + 1] = o1 - p.Cout[ix + 1];
                } else {
                    p.Cout[ix] = o0; p.Cout[ix + 1] = o1;
                }
            }
            if (row0 + 8 < M){
                size_t ix = (size_t)(row0+8)*N + col;
                if (MODE == 1 && p.sub){
                    p.Cout[ix]     = o2 - p.Cout[ix];
                    p.Cout[ix + 1] = o3 - p.Cout[ix + 1];
                } else {
                    p.Cout[ix] = o2; p.Cout[ix + 1] = o3;
                }
            }
        }
    }
}

// =============== flash attention ==========================================
__global__ __launch_bounds__(256) void flash_attn(){
    __shared__ __align__(16) bf16 sm[20480];   // 40 KB
    const unsigned smB = (unsigned)__cvta_generic_to_shared(sm);
    const int bh = blockIdx.y;
    const int b = bh >> 3, h = bh & 7;
    const int i0 = blockIdx.x * 128;
    const bf16* qH = p_qkv +           (size_t)b*NTOK*D + h*EH;
    const bf16* qL = qH + 3*MD;
    const bf16* kH = p_qkv +    MD +   (size_t)b*NTOK*D + h*EH;
    const bf16* kL = kH + 3*MD;
    const bf16* vH = p_qkv +  2*MD +   (size_t)b*NTOK*D + h*EH;
    const bf16* vL = vH + 3*MD;

    const int tid = threadIdx.x, lane = tid & 31, w = tid >> 5;
    const int t4 = lane >> 3, lr = lane & 7;

    {
        int row = tid >> 1, c = (tid & 1)*16;
        int gi = i0 + row;
        bool ok = gi < NTOK;
        size_t so = (size_t)(ok ? gi : 0)*D + c;
        const float4 z4 = make_float4(0.f,0.f,0.f,0.f);
        float4 f0 = ok ? *(const float4*)(qH + so)     : z4;
        float4 f1 = ok ? *(const float4*)(qH + so + 8) : z4;
        *(float4*)&sm[row*40 + c]     = f0;
        *(float4*)&sm[row*40 + c + 8] = f1;
        f0 = ok ? *(const float4*)(qL + so)     : z4;
        f1 = ok ? *(const float4*)(qL + so + 8) : z4;
        *(float4*)&sm[5120 + row*40 + c]     = f0;
        *(float4*)&sm[5120 + row*40 + c + 8] = f1;
    }
    __syncthreads();
    unsigned qh[2][4], ql[2][4];
    #pragma unroll
    for (int kc = 0; kc < 2; kc++){
        int row = w*16 + (t4 & 1)*8 + lr;
        int col = kc*16 + (t4 >> 1)*8;
        ldsm_x4(qh[kc], smB + (unsigned)((row*40 + col)*2));
        ldsm_x4(ql[kc], smB + (unsigned)((5120 + row*40 + col)*2));
    }
    __syncthreads();

    const int ldr = tid >> 2, ldc = (tid & 3)*8;
    auto loadkv = [&](int s, int j0){
        int gj = j0 + ldr;
        bool ok = gj < NTOK;
        size_t so = (size_t)(ok ? gj : 0)*D + ldc;
        unsigned doff = (unsigned)(s*5120 + (ldr*40 + ldc)*2);
        cp16(smB + doff,         kH + so, ok);
        cp16(smB + 10240 + doff, kL + so, ok);
        cp16(smB + 20480 + doff, vH + so, ok);
        cp16(smB + 30720 + doff, vL + so, ok);
        cpcommit();
    };

    float o[4][4];
    #pragma unroll
    for (int j = 0; j < 4; j++)
        #pragma unroll
        for (int q = 0; q < 4; q++) o[j][q] = 0.f;
    float m0 = -1e30f, m1 = -1e30f, l0 = 0.f, l1 = 0.f;
    const float scale = 0.17677669529663688f;

    loadkv(0, 0);
    int buf = 0;
    const int NJT = 14;
    for (int jt = 0; jt < NJT; jt++){
        const int j0 = jt*64;
        if (jt + 1 < NJT){ loadkv(buf ^ 1, (jt+1)*64); cpwait<1>(); }
        else cpwait<0>();
        __syncthreads();

        float s[8][4];
        #pragma unroll
        for (int nt = 0; nt < 8; nt++)
            #pragma unroll
            for (int q = 0; q < 4; q++) s[nt][q] = 0.f;

        #pragma unroll
        for (int kc = 0; kc < 2; kc++){
            #pragma unroll
            for (int pr = 0; pr < 4; pr++){
                int brow = pr*16 + (t4 >> 1)*8 + lr;
                int col  = kc*16 + (t4 & 1)*8;
                unsigned off = (unsigned)(buf*5120 + (brow*40 + col)*2);
                unsigned th[4], tl[4];
                ldsm_x4(th, smB + off);
                ldsm_x4(tl, smB + 10240 + off);
                unsigned bh0[2] = {th[0], th[1]}, bh1[2] = {th[2], th[3]};
                unsigned bl0[2] = {tl[0], tl[1]}, bl1[2] = {tl[2], tl[3]};
                mma_bf16(s[2*pr],   qh[kc], bh0);
                mma_bf16(s[2*pr],   qh[kc], bl0);
                mma_bf16(s[2*pr],   ql[kc], bh0);
                mma_bf16(s[2*pr+1], qh[kc], bh1);
                mma_bf16(s[2*pr+1], qh[kc], bl1);
                mma_bf16(s[2*pr+1], ql[kc], bh1);
            }
        }

        #pragma unroll
        for (int nt = 0; nt < 8; nt++)
            #pragma unroll
            for (int q = 0; q < 4; q++) s[nt][q] *= scale;
        if (j0 + 64 > NTOK){
            #pragma unroll
            for (int nt = 0; nt < 8; nt++){
                int c0 = j0 + nt*8 + (lane & 3)*2;
                if (c0     >= NTOK){ s[nt][0] = -1e30f; s[nt][2] = -1e30f; }
                if (c0 + 1 >= NTOK){ s[nt][1] = -1e30f; s[nt][3] = -1e30f; }
            }
        }

        float rm0 = -1e30f, rm1 = -1e30f;
        #pragma unroll
        for (int nt = 0; nt < 8; nt++){
            rm0 = fmaxf(rm0, fmaxf(s[nt][0], s[nt][1]));
            rm1 = fmaxf(rm1, fmaxf(s[nt][2], s[nt][3]));
        }
        rm0 = fmaxf(rm0, __shfl_xor_sync(0xffffffffu, rm0, 1));
        rm0 = fmaxf(rm0, __shfl_xor_sync(0xffffffffu, rm0, 2));
        rm1 = fmaxf(rm1, __shfl_xor_sync(0xffffffffu, rm1, 1));
        rm1 = fmaxf(rm1, __shfl_xor_sync(0xffffffffu, rm1, 2));
        float nm0 = fmaxf(m0, rm0), nm1 = fmaxf(m1, rm1);
        float a0 = __expf(m0 - nm0), a1 = __expf(m1 - nm1);
        float ps0 = 0.f, ps1 = 0.f;
        #pragma unroll
        for (int nt = 0; nt < 8; nt++){
            s[nt][0] = __expf(s[nt][0] - nm0);
            s[nt][1] = __expf(s[nt][1] - nm0);
            s[nt][2] = __expf(s[nt][2] - nm1);
            s[nt][3] = __expf(s[nt][3] - nm1);
            ps0 += s[nt][0] + s[nt][1];
            ps1 += s[nt][2] + s[nt][3];
        }
        ps0 += __shfl_xor_sync(0xffffffffu, ps0, 1);
        ps0 += __shfl_xor_sync(0xffffffffu, ps0, 2);
        ps1 += __shfl_xor_sync(0xffffffffu, ps1, 1);
        ps1 += __shfl_xor_sync(0xffffffffu, ps1, 2);
        l0 = l0*a0 + ps0; l1 = l1*a1 + ps1;
        m0 = nm0; m1 = nm1;
        #pragma unroll
        for (int nt = 0; nt < 4; nt++){
            o[nt][0] *= a0; o[nt][1] *= a0;
            o[nt][2] *= a1; o[nt][3] *= a1;
        }

        #pragma unroll
        for (int kc2 = 0; kc2 < 4; kc2++){
            unsigned pah[4], pal[4];
            {
                const float* u = s[2*kc2];
                const float* v2 = s[2*kc2 + 1];
                bf16 h0,lo0,h1,lo1;
                splitv(u[0], h0, lo0); splitv(u[1], h1, lo1);
                pah[0] = pack2u(h0, h1);   pal[0] = pack2u(lo0, lo1);
                splitv(u[2], h0, lo0); splitv(u[3], h1, lo1);
                pah[1] = pack2u(h0, h1);   pal[1] = pack2u(lo0, lo1);
                splitv(v2[0], h0, lo0); splitv(v2[1], h1, lo1);
                pah[2] = pack2u(h0, h1);   pal[2] = pack2u(lo0, lo1);
                splitv(v2[2], h0, lo0); splitv(v2[3], h1, lo1);
                pah[3] = pack2u(h0, h1);   pal[3] = pack2u(lo0, lo1);
            }
            #pragma unroll
            for (int pr2 = 0; pr2 < 2; pr2++){
                int krow = kc2*16 + (t4 & 1)*8 + lr;
                int ncol = pr2*16 + (t4 >> 1)*8;
                unsigned off = (unsigned)(buf*5120 + (krow*40 + ncol)*2);
                unsigned th[4], tl[4];
                ldsm_x4t(th, smB + 20480 + off);
                ldsm_x4t(tl, smB + 30720 + off);
                unsigned bh0[2] = {th[0], th[1]}, bh1[2] = {th[2], th[3]};
                unsigned bl0[2] = {tl[0], tl[1]}, bl1[2] = {tl[2], tl[3]};
                mma_bf16(o[2*pr2],   pah, bh0);
                mma_bf16(o[2*pr2],   pah, bl0);
                mma_bf16(o[2*pr2],   pal, bh0);
                mma_bf16(o[2*pr2+1], pah, bh1);
                mma_bf16(o[2*pr2+1], pah, bl1);
                mma_bf16(o[2*pr2+1], pal, bh1);
            }
        }
        __syncthreads();
        buf ^= 1;
    }

    float inv0 = 1.f / l0, inv1 = 1.f / l1;
    #pragma unroll
    for (int nt = 0; nt < 4; nt++){
        int row0 = i0 + w*16 + (lane >> 2);
        int col  = nt*8 + (lane & 3)*2;
        if (row0 < NTOK){
            size_t dst = ((size_t)b*NTOK + row0)*D + h*EH + col;
            bf16 h0,lo0,h1,lo1;
            splitv(o[nt][0]*inv0, h0, lo0); splitv(o[nt][1]*inv0, h1, lo1);
            *(__nv_bfloat162*)(p_att + dst)      = __halves2bfloat162(h0, h1);
            *(__nv_bfloat162*)(p_att + MD + dst) = __halves2bfloat162(lo0, lo1);
        }
        if (row0 + 8 < NTOK){
            size_t dst = ((size_t)b*NTOK + row0 + 8)*D + h*EH + col;
            bf16 h2,lo2,h3,lo3;
            splitv(o[nt][2]*inv1, h2, lo2); splitv(o[nt][3]*inv1, h3, lo3);
            *(__nv_bfloat162*)(p_att + dst)      = __halves2bfloat162(h2, h3);
            *(__nv_bfloat162*)(p_att + MD + dst) = __halves2bfloat162(lo2, lo3);
        }
    }
}

// ---------------- LayerNorm(x [- sub]) over D=256 (+ optional planes) ----
__global__ __launch_bounds__(256) void ln_kernel(const float* __restrict__ X,
                                                 const float* __restrict__ Sub,
                                                 const float* __restrict__ g,
                                                 const float* __restrict__ beta,
                                                 float* __restrict__ Out,
                                                 bf16* __restrict__ pH,
                                                 bf16* __restrict__ pL){
    int row = blockIdx.x, d = threadIdx.x;
    size_t i = (size_t)row*D + d;
    float v = X[i] - (Sub ? Sub[i] : 0.f);
    float2 r = blockReduce2(v, v*v);
    float mean = r.x * (1.f/D);
    float var  = r.y * (1.f/D) - mean*mean;
    float o = (v - mean) * rsqrtf(var + EPS) * g[d] + beta[d];
    Out[i] = o;
    if (pH){
        bf16 hh, ll; splitv(o, hh, ll);
        pH[i] = hh; pL[i] = ll;
    }
}

// ---------------- final: transpose + de-standardize + 2-scale mean --------
__global__ __launch_bounds__(256) void final_kernel(float* __restrict__ out, int t){
    __shared__ float tile[32][33];
    int b = blockIdx.z;
    int p0 = blockIdx.x*32, n0 = blockIdx.y*32;
    int tx = threadIdx.x & 31, ty = threadIdx.x >> 5;
    #pragma unroll
    for (int i = 0; i < 4; i++){
        int n = n0 + ty + i*8, pp = p0 + tx;
        if (n < ENC && pp < DB)
            tile[ty + i*8][tx] = g_out[((size_t)b*NTOK + n)*DB + pp];
    }
    __syncthreads();
    #pragma unroll
    for (int i = 0; i < 4; i++){
        int pp = p0 + ty + i*8, n = n0 + tx;
        if (pp < DB && n < ENC){
            float v = tile[tx][ty + i*8]*g_std[b*ENC + n] + g_mean[b*ENC + n];
            v *= 0.5f;
            size_t idx = ((size_t)b*DB + pp)*ENC + n;
            if (t == 0) out[idx] = v; else out[idx] += v;
        }
    }
}

// ---------------- host ----------------
static inline int gsz(int nt){ return nt < 444 ? nt : 444; }
static void* sym(const void* s){ void* p; cudaGetSymbolAddress(&p, s); return p; }

extern "C" void kernel_launch(void* const* d_in, const int* in_sizes, int n_in,
                              void* d_out, int out_size){
    const float* mbx  = (const float*)d_in[0];
    const float* mbxm = (const float*)d_in[1];
    const float* embW = (const float*)d_in[4];
    const float* embB = (const float*)d_in[5];
    const float* Wq = (const float*)d_in[6];
    const float* Wk = (const float*)d_in[7];
    const float* Wv = (const float*)d_in[8];
    const float* Wo = (const float*)d_in[9];
    const float* W3 = (const float*)d_in[10];
    const float* W4 = (const float*)d_in[11];
    const float* bq = (const float*)d_in[12];
    const float* bk = (const float*)d_in[13];
    const float* bv = (const float*)d_in[14];
    const float* bo = (const float*)d_in[15];
    const float* b3 = (const float*)d_in[16];
    const float* b4 = (const float*)d_in[17];
    const float* W1 = (const float*)d_in[18];
    const float* b1 = (const float*)d_in[19];
    const float* W2 = (const float*)d_in[20];
    const float* b2 = (const float*)d_in[21];
    const float* W5 = (const float*)d_in[22];
    const float* b5 = (const float*)d_in[23];
    const float* W6 = (const float*)d_in[24];
    const float* b6 = (const float*)d_in[25];
    const float* ln1g = (const float*)d_in[26];
    const float* ln1b = (const float*)d_in[27];
    const float* ln2g = (const float*)d_in[28];
    const float* ln2b = (const float*)d_in[29];
    float* out = (float*)d_out;

    float* hF   = (float*)sym(g_h);
    float* xatt = (float*)sym(g_xatt);
    float* xln  = (float*)sym(g_xln);
    float* hhF  = (float*)sym(g_hh);
    float* outF = (float*)sym(g_out);

    bf16* xinP = (bf16*)sym(p_xin);
    bf16* hP   = (bf16*)sym(p_h);
    bf16* qkvP = (bf16*)sym(p_qkv);
    bf16* attP = (bf16*)sym(p_att);
    bf16* xlnP = (bf16*)sym(p_xln);
    bf16* y1P  = (bf16*)sym(p_y1);
    bf16* xsP  = (bf16*)sym(p_xs);
    bf16* xattP = (bf16*)sym(p_xatt);
    bf16* yP   = (bf16*)sym(p_y);
    bf16* embWP = (bf16*)sym(p_embW);
    bf16* WqP = (bf16*)sym(p_Wq); bf16* WkP = (bf16*)sym(p_Wk);
    bf16* WvP = (bf16*)sym(p_Wv); bf16* WoP = (bf16*)sym(p_Wo);
    bf16* W3P = (bf16*)sym(p_W3); bf16* W4P = (bf16*)sym(p_W4);
    bf16* W1P = (bf16*)sym(p_W1); bf16* W2P = (bf16*)sym(p_W2);
    bf16* W5P = (bf16*)sym(p_W5); bf16* W6P = (bf16*)sym(p_W6);

    const size_t EWN = (size_t)256*SEQP;
    const size_t WDD = (size_t)LAYERS*D*D;
    const size_t W1N = (size_t)LAYERS*DFF*D;
    const size_t W5N = (size_t)LAYERS*DB*2*D;
    const size_t Y1N = (size_t)MROWS*DFF;

    cudaFuncSetAttribute(mma_gemm<0>, cudaFuncAttributeMaxDynamicSharedMemorySize, 61440);
    cudaFuncSetAttribute(mma_gemm<1>, cudaFuncAttributeMaxDynamicSharedMemorySize, 61440);
    cudaFuncSetAttribute(mma_gemm<2>, cudaFuncAttributeMaxDynamicSharedMemorySize, 61440);
    cudaFuncSetAttribute(mma_gemm2<0>, cudaFuncAttributeMaxDynamicSharedMemorySize, 61440);
    cudaFuncSetAttribute(mma_gemm2<1>, cudaFuncAttributeMaxDynamicSharedMemorySize, 61440);

    // weight splits (one batched launch + embed pad)
    {
        WSArgs ws;
        const float* ss[10] = {Wq, Wk, Wv, Wo, W3, W4, W1, W2, W5, W6};
        bf16* hh[10] = {WqP, WkP, WvP, WoP, W3P, W4P, W1P, W2P, W5P, W6P};
        size_t nn[10] = {WDD, WDD, WDD, WDD, WDD, WDD, W1N, W1N, W5N, W5N};
        for (int i = 0; i < 10; i++){
            ws.s[i] = ss[i]; ws.h[i] = hh[i]; ws.l[i] = hh[i] + nn[i]; ws.n[i] = (int)nn[i];
        }
        wsplit_all<<<dim3(288, 10), 256>>>(ws);
        wsplit_pad<<<(unsigned)((EWN + 255)/256), 256>>>(embW, embWP, embWP + EWN, 256, SEQ, SEQP);
    }

    const int tm = 55;    // ceil(6928/128)
    const int tm64 = 109; // ceil(6928/64)

    for (int t = 0; t < TS; t++){
        stats_kernel<<<dim3((ENC + 255)/256, B_), 256>>>(mbx, t);
        xin_kernel<<<dim3((SEQP + 31)/32, (NTOK + 31)/32, B_), 256>>>(mbx, mbxm, t);

        {   // embed -> fp32 h + planes
            GemmArgs a = {};
            a.aH[0] = xinP; a.aL[0] = xinP + XN;
            a.wH[0] = embWP; a.wL[0] = embWP + EWN;
            a.bias[0] = embB; a.C[0] = hF;
            a.cH[0] = hP; a.cL[0] = hP + MD;
            mma_gemm<0><<<gsz(tm*4), 256, 61440>>>(a, MROWS, D, SEQP, 4, tm*4, tm*4);
        }

        for (int l = 0; l < LAYERS; l++){
            {   // QKV -> planes
                GemmArgs a = {};
                for (int z = 0; z < 3; z++){
                    a.aH[z] = hP; a.aL[z] = hP + MD;
                    a.cH[z] = qkvP + (size_t)z*MD;
                    a.cL[z] = qkvP + 3*MD + (size_t)z*MD;
                }
                a.wH[0] = WqP + (size_t)l*D*D; a.wL[0] = WqP + WDD + (size_t)l*D*D;
                a.wH[1] = WkP + (size_t)l*D*D; a.wL[1] = WkP + WDD + (size_t)l*D*D;
                a.wH[2] = WvP + (size_t)l*D*D; a.wL[2] = WvP + WDD + (size_t)l*D*D;
                a.bias[0] = bq + l*D; a.bias[1] = bk + l*D; a.bias[2] = bv + l*D;
                mma_gemm<0><<<gsz(tm*4*3), 256, 61440>>>(a, MROWS, D, D, 4, tm*4, tm*4*3);
            }

            flash_attn<<<dim3(7, B_*NH), 256>>>();

            {   // Wo -> fp32 xatt + planes
                GemmArgs a = {};
                a.aH[0] = attP; a.aL[0] = attP + MD;
                a.wH[0] = WoP + (size_t)l*D*D; a.wL[0] = WoP + WDD + (size_t)l*D*D;
                a.bias[0] = bo + l*D; a.C[0] = xatt;
                a.cH[0] = xattP; a.cL[0] = xattP + MD;
                mma_gemm<0><<<gsz(tm*4), 256, 61440>>>(a, MROWS, D, D, 4, tm*4, tm*4);
            }

            ln_kernel<<<MROWS, 256>>>(hF, xatt, ln1g + l*D, ln1b + l*D, xln,
                                      xlnP, xlnP + MD);

            {   // W1 + GELU -> y1 planes
                GemmArgs a = {};
                a.aH[0] = xlnP; a.aL[0] = xlnP + MD;
                a.wH[0] = W1P + (size_t)l*DFF*D; a.wL[0] = W1P + W1N + (size_t)l*DFF*D;
                a.bias[0] = b1 + l*DFF;
                a.cH[0] = y1P; a.cL[0] = y1P + Y1N;
                mma_gemm<1><<<gsz(tm*8), 256, 61440>>>(a, MROWS, DFF, D, 8, tm*8, tm*8);
            }
            {   // W2 -> y planes + xs=(xln-y) planes (sub fused)
                GemmArgs a = {};
                a.aH[0] = y1P; a.aL[0] = y1P + Y1N;
                a.wH[0] = W2P + (size_t)l*D*DFF; a.wL[0] = W2P + W1N + (size_t)l*D*DFF;
                a.bias[0] = b2 + l*D;
                a.cH[0] = yP; a.cL[0] = yP + MD;
                a.xsub[0] = xln;
                a.c2H[0] = xsP; a.c2L[0] = xsP + MD;
                mma_gemm<2><<<gsz(tm*4), 256, 61440>>>(a, MROWS, D, DFF, 4, tm*4, tm*4);
            }

            {   // fused W3/W4 -> hh = sigmoid(.)*(.)
                Gemm2Args a = {};
                a.a0H = xsP; a.a0L = xsP + MD; a.a1H = xsP; a.a1L = xsP + MD;
                a.kSplit = 1 << 30; a.aStride = D;
                a.w1H = W3P + (size_t)l*D*D; a.w1L = W3P + WDD + (size_t)l*D*D;
                a.w2H = W4P + (size_t)l*D*D; a.w2L = W4P + WDD + (size_t)l*D*D;
                a.b1 = b3 + l*D; a.b2 = b4 + l*D;
                a.Cout = hhF; a.sub = 0;
                mma_gemm2<0><<<gsz(tm64*4), 256, 61440>>>(a, MROWS, D, D, 4, tm64*4);
            }

            {   // fused W5/W6 over cat(xatt,y) -> g_out (with layer subtract)
                Gemm2Args a = {};
                a.a0H = xattP; a.a0L = xattP + MD;
                a.a1H = yP;    a.a1L = yP + MD;
                a.kSplit = D; a.aStride = D;
                a.w1H = W5P + (size_t)l*DB*2*D; a.w1L = W5P + W5N + (size_t)l*DB*2*D;
                a.w2H = W6P + (size_t)l*DB*2*D; a.w2L = W6P + W5N + (size_t)l*DB*2*D;
                a.b1 = b5 + l*DB; a.b2 = b6 + l*DB;
                a.Cout = outF; a.sub = l;
                mma_gemm2<1><<<gsz(tm64*12), 256, 61440>>>(a, MROWS, DB, 2*D, 12, tm64*12);
            }

            ln_kernel<<<MROWS, 256>>>(hhF, (const float*)nullptr,
                                      ln2g + l*D, ln2b + l*D, hF, hP, hP + MD);
        }

        final_kernel<<<dim3((DB + 31)/32, (ENC + 31)/32, B_), 256>>>(out, t);
    }
}

// round 12
// speedup vs baseline: 1.2330x; 1.1328x over previous
#include <cuda_runtime.h>
#include <cuda_bf16.h>
#include <math.h>

#define B_    8
#define TS    2
#define SEQ   720
#define SEQP  736
#define ENC   862
#define MARKD 4
#define NTOK  866
#define D     256
#define NH    8
#define EH    32
#define DFF   512
#define DB    720
#define LAYERS 2
#define EPS   1e-5f
#define MROWS (B_*NTOK)        // 6928 per scale
#define TM    (TS*MROWS)       // 13856 combined
#define TMD   ((size_t)TM*D)
#define TXN   ((size_t)TM*SEQP)

typedef __nv_bfloat16 bf16;

// ---------------- fp32 scratch ----------------
__device__ float g_mean[TS*B_*ENC], g_std[TS*B_*ENC];
__device__ float g_h[TMD], g_xatt[TMD], g_xln[TMD], g_hh[TMD];
__device__ float g_out[(size_t)TM*DB];

// ---------------- bf16 hi/lo planes (lo at +n) ----------------
__device__ __align__(16) bf16 p_xin[2*TXN];
__device__ __align__(16) bf16 p_h  [2*TMD];
__device__ __align__(16) bf16 p_qkv[2*3*TMD];
__device__ __align__(16) bf16 p_att[2*TMD];
__device__ __align__(16) bf16 p_xln[2*TMD];
__device__ __align__(16) bf16 p_y1 [2*(size_t)TM*DFF];
__device__ __align__(16) bf16 p_xs [2*TMD];
__device__ __align__(16) bf16 p_xatt[2*TMD];
__device__ __align__(16) bf16 p_y  [2*TMD];
// weights
__device__ __align__(16) bf16 p_embW[2*256*SEQP];
__device__ __align__(16) bf16 p_Wq[2*LAYERS*D*D], p_Wk[2*LAYERS*D*D], p_Wv[2*LAYERS*D*D];
__device__ __align__(16) bf16 p_Wo[2*LAYERS*D*D], p_W3[2*LAYERS*D*D], p_W4[2*LAYERS*D*D];
__device__ __align__(16) bf16 p_W1[2*LAYERS*DFF*D], p_W2[2*LAYERS*D*DFF];
__device__ __align__(16) bf16 p_W5[2*LAYERS*DB*2*D], p_W6[2*LAYERS*DB*2*D];

// ---------------- helpers ----------------
__device__ __forceinline__ void splitv(float x, bf16& h, bf16& l){
    h = __float2bfloat16(x);
    l = __float2bfloat16(x - __bfloat162float(h));
}
__device__ __forceinline__ unsigned pack2u(bf16 a, bf16 b){
    __nv_bfloat162 t = __halves2bfloat162(a, b);
    return *(unsigned*)&t;
}
__device__ __forceinline__ void mma_bf16(float c[4], const unsigned a[4], const unsigned b[2]){
    asm volatile("mma.sync.aligned.m16n8k16.row.col.f32.bf16.bf16.f32 "
                 "{%0,%1,%2,%3}, {%4,%5,%6,%7}, {%8,%9}, {%0,%1,%2,%3};\n"
                 : "+f"(c[0]), "+f"(c[1]), "+f"(c[2]), "+f"(c[3])
                 : "r"(a[0]), "r"(a[1]), "r"(a[2]), "r"(a[3]),
                   "r"(b[0]), "r"(b[1]));
}
__device__ __forceinline__ void ldsm_x4(unsigned r[4], unsigned addr){
    asm volatile("ldmatrix.sync.aligned.m8n8.x4.shared.b16 {%0,%1,%2,%3}, [%4];\n"
                 : "=r"(r[0]), "=r"(r[1]), "=r"(r[2]), "=r"(r[3]) : "r"(addr));
}
__device__ __forceinline__ void ldsm_x4t(unsigned r[4], unsigned addr){
    asm volatile("ldmatrix.sync.aligned.m8n8.x4.trans.shared.b16 {%0,%1,%2,%3}, [%4];\n"
                 : "=r"(r[0]), "=r"(r[1]), "=r"(r[2]), "=r"(r[3]) : "r"(addr));
}
__device__ __forceinline__ void cp16(unsigned dst, const void* src, bool p){
    int sz = p ? 16 : 0;
    asm volatile("cp.async.cg.shared.global [%0], [%1], 16, %2;\n"
                 :: "r"(dst), "l"(src), "r"(sz));
}
__device__ __forceinline__ void cpcommit(){ asm volatile("cp.async.commit_group;\n"); }
template<int N> __device__ __forceinline__ void cpwait(){
    asm volatile("cp.async.wait_group %0;\n" :: "n"(N));
}
__device__ __forceinline__ float gelu_f(float x){
    return 0.5f*x*(1.f + erff(x*0.70710678118654752f));
}
__device__ __forceinline__ float sigmoid_f(float x){
    return 1.f/(1.f + expf(-x));
}
__device__ __forceinline__ float2 blockReduce2(float a, float b){
    __shared__ float2 sh[33];
    int lane = threadIdx.x & 31, wid = threadIdx.x >> 5;
    __syncthreads();
    #pragma unroll
    for (int o = 16; o; o >>= 1){
        a += __shfl_down_sync(0xffffffffu, a, o);
        b += __shfl_down_sync(0xffffffffu, b, o);
    }
    if (lane == 0) sh[wid] = make_float2(a, b);
    __syncthreads();
    if (wid == 0){
        int nw = blockDim.x >> 5;
        float2 v = (lane < nw) ? sh[lane] : make_float2(0.f, 0.f);
        a = v.x; b = v.y;
        #pragma unroll
        for (int o = 16; o; o >>= 1){
            a += __shfl_down_sync(0xffffffffu, a, o);
            b += __shfl_down_sync(0xffffffffu, b, o);
        }
        if (lane == 0) sh[32] = make_float2(a, b);
    }
    __syncthreads();
    return sh[32];
}

// ---------------- weight split (batched) ----------------
struct WSArgs { const float* s[10]; bf16* h[10]; bf16* l[10]; int n[10]; };
__global__ void wsplit_all(WSArgs w){
    int z = blockIdx.y;
    int n = w.n[z];
    const float* src = w.s[z];
    bf16* hh = w.h[z]; bf16* ll = w.l[z];
    for (int i = blockIdx.x*blockDim.x + threadIdx.x; i < n; i += gridDim.x*blockDim.x)
        splitv(src[i], hh[i], ll[i]);
}
__global__ void wsplit_pad(const float* __restrict__ s, bf16* __restrict__ h,
                           bf16* __restrict__ l, int rows, int K, int Kp){
    size_t i = (size_t)blockIdx.x*blockDim.x + threadIdx.x;
    size_t total = (size_t)rows*Kp;
    if (i >= total) return;
    int c = (int)(i % Kp); int r = (int)(i / Kp);
    float v = (c < K) ? s[(size_t)r*K + c] : 0.f;
    splitv(v, h[i], l[i]);
}

// ---------------- input standardization (both scales) ----------------
__global__ void stats_kernel(const float* __restrict__ mbx){
    int t = blockIdx.z, b = blockIdx.y;
    int n = blockIdx.x * blockDim.x + threadIdx.x;
    if (n >= ENC) return;
    const float* base = mbx + ((size_t)(b*TS + t)*SEQ)*ENC + n;
    float s = 0.f, ss = 0.f;
    for (int i = 0; i < SEQ; i++){
        float v = base[(size_t)i*ENC];
        s += v; ss += v*v;
    }
    float m = s * (1.f/SEQ);
    float var = ss * (1.f/SEQ) - m*m;
    g_mean[(t*B_ + b)*ENC + n] = m;
    g_std [(t*B_ + b)*ENC + n] = sqrtf(var + EPS);
}

// transposed tiled build of xin planes for both scales
__global__ __launch_bounds__(256) void xin_kernel(const float* __restrict__ mbx,
                                                  const float* __restrict__ mbxm){
    __shared__ float tile[32][33];
    const int zb = blockIdx.z;            // t*B_ + b
    const int t = zb / B_, b = zb % B_;
    const int s0 = blockIdx.x*32, n0 = blockIdx.y*32;
    const int tx = threadIdx.x & 31, ty = threadIdx.x >> 5;
    #pragma unroll
    for (int i = 0; i < 4; i++){
        int s = s0 + ty + i*8, n = n0 + tx;
        float v = 0.f;
        if (s < SEQ && n < NTOK){
            if (n < ENC){
                v = mbx[((size_t)(b*TS + t)*SEQ + s)*ENC + n];
                v = (v - g_mean[zb*ENC + n]) / g_std[zb*ENC + n];
            } else {
                v = mbxm[((size_t)(b*TS + t)*SEQ + s)*MARKD + (n - ENC)];
            }
        }
        tile[ty + i*8][tx] = v;
    }
    __syncthreads();
    #pragma unroll
    for (int i = 0; i < 4; i++){
        int n = n0 + ty + i*8, s = s0 + tx;
        if (n < NTOK && s < SEQP){
            size_t idx = ((size_t)zb*NTOK + n)*SEQP + s;
            splitv(tile[tx][ty + i*8], p_xin[idx], p_xin[TXN + idx]);
        }
    }
}

// =============== MMA GEMM: C = A @ W^T + bias (bf16 planes, cp.async) =====
// ACT 0: plain; 1: gelu; 2: emit y planes + (xsub - y) planes
struct GemmArgs {
    const bf16 *aH[3], *aL[3], *wH[3], *wL[3];
    const float* bias[3];
    float* C[3];
    bf16 *cH[3], *cL[3];
    const float* xsub[3];
    bf16 *c2H[3], *c2L[3];
};

template<int ACT>
__global__ __launch_bounds__(256, 3)
void mma_gemm(GemmArgs p, int M, int N, int K, int tilesN, int tpz, int nTiles){
    extern __shared__ __align__(16) char smraw[];
    bf16* sAh = (bf16*)smraw;            // [2][128][40]
    bf16* sAl = sAh + 2*128*40;
    bf16* sBh = sAl + 2*128*40;          // [2][64][40]
    bf16* sBl = sBh + 2*64*40;
    const unsigned aHiB = (unsigned)__cvta_generic_to_shared(sAh);
    const unsigned aLoB = (unsigned)__cvta_generic_to_shared(sAl);
    const unsigned bHiB = (unsigned)__cvta_generic_to_shared(sBh);
    const unsigned bLoB = (unsigned)__cvta_generic_to_shared(sBl);

    const int tid = threadIdx.x;
    const int lane = tid & 31, w = tid >> 5;
    const int wm = (w >> 1)*32, wn = (w & 1)*32;
    const int t4 = lane >> 3, lr = lane & 7;
    const int ldr = tid >> 2, ldc = (tid & 3)*8;

    for (int t = blockIdx.x; t < nTiles; t += gridDim.x){
        const int z  = t / tpz;
        const int rr = t - z*tpz;
        const int bm = (rr / tilesN)*128, bn = (rr % tilesN)*64;
        const bf16* __restrict__ aHp = p.aH[z];
        const bf16* __restrict__ aLp = p.aL[z];
        const bf16* __restrict__ wHp = p.wH[z];
        const bf16* __restrict__ wLp = p.wL[z];
        const float* __restrict__ bias = p.bias[z];
        float* Cp = p.C[z];
        bf16* cHp = p.cH[z];
        bf16* cLp = p.cL[z];

        float acc[2][4][4];
        #pragma unroll
        for (int i = 0; i < 2; i++)
            #pragma unroll
            for (int j = 0; j < 4; j++)
                #pragma unroll
                for (int q = 0; q < 4; q++) acc[i][j][q] = 0.f;

        auto loadst = [&](int s, int k0){
            #pragma unroll
            for (int rep = 0; rep < 2; rep++){
                int r = ldr + rep*64;
                int gm = bm + r;
                bool pr = gm < M;
                size_t so = (size_t)(pr ? gm : 0)*K + k0 + ldc;
                unsigned doff = (unsigned)(((s*128 + r)*40 + ldc)*2);
                cp16(aHiB + doff, aHp + so, pr);
                cp16(aLoB + doff, aLp + so, pr);
            }
            {
                int gn = bn + ldr;
                bool pn = gn < N;
                size_t so = (size_t)(pn ? gn : 0)*K + k0 + ldc;
                unsigned doff = (unsigned)(((s*64 + ldr)*40 + ldc)*2);
                cp16(bHiB + doff, wHp + so, pn);
                cp16(bLoB + doff, wLp + so, pn);
            }
            cpcommit();
        };

        loadst(0, 0);
        int buf = 0;
        const int KT = K >> 5;
        for (int kt = 0; kt < KT; kt++){
            if (kt + 1 < KT){ loadst(buf ^ 1, (kt+1)*32); cpwait<1>(); }
            else cpwait<0>();
            __syncthreads();

            #pragma unroll
            for (int kh = 0; kh < 32; kh += 16){
                unsigned ah[2][4], al[2][4], bh[4][2], bl[4][2];
                #pragma unroll
                for (int mt = 0; mt < 2; mt++){
                    int arow = wm + mt*16 + (t4 & 1)*8 + lr;
                    unsigned off = (unsigned)((((buf*128) + arow)*40 + kh + (t4 >> 1)*8)*2);
                    ldsm_x4(ah[mt], aHiB + off);
                    ldsm_x4(al[mt], aLoB + off);
                }
                #pragma unroll
                for (int pr2 = 0; pr2 < 2; pr2++){
                    int brow = wn + pr2*16 + (t4 >> 1)*8 + lr;
                    unsigned off = (unsigned)((((buf*64) + brow)*40 + kh + (t4 & 1)*8)*2);
                    unsigned th[4], tl[4];
                    ldsm_x4(th, bHiB + off);
                    ldsm_x4(tl, bLoB + off);
                    bh[pr2*2][0] = th[0]; bh[pr2*2][1] = th[1];
                    bh[pr2*2+1][0] = th[2]; bh[pr2*2+1][1] = th[3];
                    bl[pr2*2][0] = tl[0]; bl[pr2*2][1] = tl[1];
                    bl[pr2*2+1][0] = tl[2]; bl[pr2*2+1][1] = tl[3];
                }
                #pragma unroll
                for (int mt = 0; mt < 2; mt++)
                    #pragma unroll
                    for (int nt = 0; nt < 4; nt++){
                        mma_bf16(acc[mt][nt], ah[mt], bh[nt]);
                        mma_bf16(acc[mt][nt], ah[mt], bl[nt]);
                        mma_bf16(acc[mt][nt], al[mt], bh[nt]);
                    }
            }
            __syncthreads();
            buf ^= 1;
        }

        #pragma unroll
        for (int mt = 0; mt < 2; mt++)
            #pragma unroll
            for (int nt = 0; nt < 4; nt++){
                int row0 = bm + wm + mt*16 + (lane >> 2);
                int col  = bn + wn + nt*8 + (lane & 3)*2;
                if (col >= N) continue;
                float b0 = bias[col], b1 = bias[col + 1];
                float v0 = acc[mt][nt][0] + b0, v1 = acc[mt][nt][1] + b1;
                float v2 = acc[mt][nt][2] + b0, v3 = acc[mt][nt][3] + b1;
                if (ACT == 1){
                    v0 = gelu_f(v0); v1 = gelu_f(v1);
                    v2 = gelu_f(v2); v3 = gelu_f(v3);
                }
                if (row0 < M){
                    size_t ix = (size_t)row0*N + col;
                    if (Cp){ Cp[ix] = v0; Cp[ix + 1] = v1; }
                    if (cHp){
                        bf16 h0,l0,h1,l1; splitv(v0,h0,l0); splitv(v1,h1,l1);
                        *(__nv_bfloat162*)(cHp + ix) = __halves2bfloat162(h0,h1);
                        *(__nv_bfloat162*)(cLp + ix) = __halves2bfloat162(l0,l1);
                    }
                    if (ACT == 2){
                        float x0 = p.xsub[z][ix], x1 = p.xsub[z][ix + 1];
                        bf16 h0,l0,h1,l1; splitv(x0 - v0,h0,l0); splitv(x1 - v1,h1,l1);
                        *(__nv_bfloat162*)(p.c2H[z] + ix) = __halves2bfloat162(h0,h1);
                        *(__nv_bfloat162*)(p.c2L[z] + ix) = __halves2bfloat162(l0,l1);
                    }
                }
                if (row0 + 8 < M){
                    size_t ix = (size_t)(row0+8)*N + col;
                    if (Cp){ Cp[ix] = v2; Cp[ix + 1] = v3; }
                    if (cHp){
                        bf16 h2,l2,h3,l3; splitv(v2,h2,l2); splitv(v3,h3,l3);
                        *(__nv_bfloat162*)(cHp + ix) = __halves2bfloat162(h2,h3);
                        *(__nv_bfloat162*)(cLp + ix) = __halves2bfloat162(l2,l3);
                    }
                    if (ACT == 2){
                        float x2 = p.xsub[z][ix], x3 = p.xsub[z][ix + 1];
                        bf16 h2,l2,h3,l3; splitv(x2 - v2,h2,l2); splitv(x3 - v3,h3,l3);
                        *(__nv_bfloat162*)(p.c2H[z] + ix) = __halves2bfloat162(h2,h3);
                        *(__nv_bfloat162*)(p.c2L[z] + ix) = __halves2bfloat162(l2,l3);
                    }
                }
            }
    }
}

// =============== fused dual GEMM (BM=64): o = sig(A W1^T+b1)*(A W2^T+b2) ==
struct Gemm2Args {
    const bf16 *a0H, *a0L, *a1H, *a1L;
    int kSplit, aStride;
    const bf16 *w1H, *w1L, *w2H, *w2L;
    const float *b1, *b2;
    float* Cout;
    int sub;
};

template<int MODE>
__global__ __launch_bounds__(256, 3)
void mma_gemm2(Gemm2Args p, int M, int N, int K, int tilesN, int nTiles){
    extern __shared__ __align__(16) char smraw[];
    bf16* sm = (bf16*)smraw;
    const unsigned smB = (unsigned)__cvta_generic_to_shared(sm);
    const int tid = threadIdx.x;
    const int lane = tid & 31, w = tid >> 5;
    const int wm = (w >> 1)*16, wn = (w & 1)*32;
    const int t4 = lane >> 3, lr = lane & 7;
    const int ldr = tid >> 2, ldc = (tid & 3)*8;

    for (int t = blockIdx.x; t < nTiles; t += gridDim.x){
        const int bm = (t / tilesN)*64, bn = (t % tilesN)*64;

        float acc[2][4][4];
        #pragma unroll
        for (int g = 0; g < 2; g++)
            #pragma unroll
            for (int j = 0; j < 4; j++)
                #pragma unroll
                for (int q = 0; q < 4; q++) acc[g][j][q] = 0.f;

        auto loadst = [&](int s, int k0){
            const bf16* aH = (k0 < p.kSplit) ? p.a0H : p.a1H;
            const bf16* aL = (k0 < p.kSplit) ? p.a0L : p.a1L;
            int kk = (k0 < p.kSplit) ? k0 : k0 - p.kSplit;
            int gm = bm + ldr;
            bool pr = gm < M;
            size_t soA = (size_t)(pr ? gm : 0)*p.aStride + kk + ldc;
            unsigned dA = (unsigned)((s*2*2560 + ldr*40 + ldc)*2);
            cp16(smB + dA,           aH + soA, pr);
            cp16(smB + dA + 2560*2,  aL + soA, pr);
            int gn = bn + ldr;
            bool pn = gn < N;
            size_t soB = (size_t)(pn ? gn : 0)*K + k0 + ldc;
            unsigned dB = (unsigned)((10240 + s*4*2560 + ldr*40 + ldc)*2);
            cp16(smB + dB,             p.w1H + soB, pn);
            cp16(smB + dB + 2560*2,    p.w1L + soB, pn);
            cp16(smB + dB + 2*2560*2,  p.w2H + soB, pn);
            cp16(smB + dB + 3*2560*2,  p.w2L + soB, pn);
            cpcommit();
        };

        loadst(0, 0);
        int buf = 0;
        const int KT = K >> 5;
        for (int kt = 0; kt < KT; kt++){
            if (kt + 1 < KT){ loadst(buf ^ 1, (kt+1)*32); cpwait<1>(); }
            else cpwait<0>();
            __syncthreads();

            #pragma unroll
            for (int kh = 0; kh < 32; kh += 16){
                unsigned ah[4], al[4];
                {
                    int arow = wm + (t4 & 1)*8 + lr;
                    unsigned off = (unsigned)((buf*2*2560 + arow*40 + kh + (t4 >> 1)*8)*2);
                    ldsm_x4(ah, smB + off);
                    ldsm_x4(al, smB + off + 2560*2);
                }
                #pragma unroll
                for (int g = 0; g < 2; g++){
                    #pragma unroll
                    for (int pr2 = 0; pr2 < 2; pr2++){
                        int brow = wn + pr2*16 + (t4 >> 1)*8 + lr;
                        unsigned off = (unsigned)((10240 + buf*4*2560 + g*2*2560
                                                   + brow*40 + kh + (t4 & 1)*8)*2);
                        unsigned th[4], tl[4];
                        ldsm_x4(th, smB + off);
                        ldsm_x4(tl, smB + off + 2560*2);
                        unsigned bh0[2] = {th[0], th[1]}, bh1[2] = {th[2], th[3]};
                        unsigned bl0[2] = {tl[0], tl[1]}, bl1[2] = {tl[2], tl[3]};
                        mma_bf16(acc[g][2*pr2],   ah, bh0);
                        mma_bf16(acc[g][2*pr2],   ah, bl0);
                        mma_bf16(acc[g][2*pr2],   al, bh0);
                        mma_bf16(acc[g][2*pr2+1], ah, bh1);
                        mma_bf16(acc[g][2*pr2+1], ah, bl1);
                        mma_bf16(acc[g][2*pr2+1], al, bh1);
                    }
                }
            }
            __syncthreads();
            buf ^= 1;
        }

        #pragma unroll
        for (int nt = 0; nt < 4; nt++){
            int row0 = bm + wm + (lane >> 2);
            int col  = bn + wn + nt*8 + (lane & 3)*2;
            if (col >= N) continue;
            float b10 = p.b1[col], b11 = p.b1[col + 1];
            float b20 = p.b2[col], b21 = p.b2[col + 1];
            float o0 = sigmoid_f(acc[0][nt][0] + b10)*(acc[1][nt][0] + b20);
            float o1 = sigmoid_f(acc[0][nt][1] + b11)*(acc[1][nt][1] + b21);
            float o2 = sigmoid_f(acc[0][nt][2] + b10)*(acc[1][nt][2] + b20);
            float o3 = sigmoid_f(acc[0][nt][3] + b11)*(acc[1][nt][3] + b21);
            if (row0 < M){
                size_t ix = (size_t)row0*N + col;
                if (MODE == 1 && p.sub){
                    p.Cout[ix]     = o0 - p.Cout[ix];
                    p.Cout[ix + 1] = o1 - p.Cout[ix + 1];
                } else {
                    p.Cout[ix] = o0; p.Cout[ix + 1] = o1;
                }
            }
            if (row0 + 8 < M){
                size_t ix = (size_t)(row0+8)*N + col;
                if (MODE == 1 && p.sub){
                    p.Cout[ix]     = o2 - p.Cout[ix];
                    p.Cout[ix + 1] = o3 - p.Cout[ix + 1];
                } else {
                    p.Cout[ix] = o2; p.Cout[ix + 1] = o3;
                }
            }
        }
    }
}

// =============== flash attention (both scales via batch index) ============
__global__ __launch_bounds__(256) void flash_attn(){
    __shared__ __align__(16) bf16 sm[20480];   // 40 KB
    const unsigned smB = (unsigned)__cvta_generic_to_shared(sm);
    const int bh = blockIdx.y;                 // (t*B_ + b)*NH + ... packed
    const int tb = bh >> 3, h = bh & 7;        // tb in [0, TS*B_)
    const int i0 = blockIdx.x * 128;
    const bf16* qH = p_qkv +            (size_t)tb*NTOK*D + h*EH;
    const bf16* qL = qH + 3*TMD;
    const bf16* kH = p_qkv +    TMD +   (size_t)tb*NTOK*D + h*EH;
    const bf16* kL = kH + 3*TMD;
    const bf16* vH = p_qkv +  2*TMD +   (size_t)tb*NTOK*D + h*EH;
    const bf16* vL = vH + 3*TMD;

    const int tid = threadIdx.x, lane = tid & 31, w = tid >> 5;
    const int t4 = lane >> 3, lr = lane & 7;

    {
        int row = tid >> 1, c = (tid & 1)*16;
        int gi = i0 + row;
        bool ok = gi < NTOK;
        size_t so = (size_t)(ok ? gi : 0)*D + c;
        const float4 z4 = make_float4(0.f,0.f,0.f,0.f);
        float4 f0 = ok ? *(const float4*)(qH + so)     : z4;
        float4 f1 = ok ? *(const float4*)(qH + so + 8) : z4;
        *(float4*)&sm[row*40 + c]     = f0;
        *(float4*)&sm[row*40 + c + 8] = f1;
        f0 = ok ? *(const float4*)(qL + so)     : z4;
        f1 = ok ? *(const float4*)(qL + so + 8) : z4;
        *(float4*)&sm[5120 + row*40 + c]     = f0;
        *(float4*)&sm[5120 + row*40 + c + 8] = f1;
    }
    __syncthreads();
    unsigned qh[2][4], ql[2][4];
    #pragma unroll
    for (int kc = 0; kc < 2; kc++){
        int row = w*16 + (t4 & 1)*8 + lr;
        int col = kc*16 + (t4 >> 1)*8;
        ldsm_x4(qh[kc], smB + (unsigned)((row*40 + col)*2));
        ldsm_x4(ql[kc], smB + (unsigned)((5120 + row*40 + col)*2));
    }
    __syncthreads();

    const int ldr = tid >> 2, ldc = (tid & 3)*8;
    auto loadkv = [&](int s, int j0){
        int gj = j0 + ldr;
        bool ok = gj < NTOK;
        size_t so = (size_t)(ok ? gj : 0)*D + ldc;
        unsigned doff = (unsigned)(s*5120 + (ldr*40 + ldc)*2);
        cp16(smB + doff,         kH + so, ok);
        cp16(smB + 10240 + doff, kL + so, ok);
        cp16(smB + 20480 + doff, vH + so, ok);
        cp16(smB + 30720 + doff, vL + so, ok);
        cpcommit();
    };

    float o[4][4];
    #pragma unroll
    for (int j = 0; j < 4; j++)
        #pragma unroll
        for (int q = 0; q < 4; q++) o[j][q] = 0.f;
    float m0 = -1e30f, m1 = -1e30f, l0 = 0.f, l1 = 0.f;
    const float scale = 0.17677669529663688f;

    loadkv(0, 0);
    int buf = 0;
    const int NJT = 14;
    for (int jt = 0; jt < NJT; jt++){
        const int j0 = jt*64;
        if (jt + 1 < NJT){ loadkv(buf ^ 1, (jt+1)*64); cpwait<1>(); }
        else cpwait<0>();
        __syncthreads();

        float s[8][4];
        #pragma unroll
        for (int nt = 0; nt < 8; nt++)
            #pragma unroll
            for (int q = 0; q < 4; q++) s[nt][q] = 0.f;

        #pragma unroll
        for (int kc = 0; kc < 2; kc++){
            #pragma unroll
            for (int pr = 0; pr < 4; pr++){
                int brow = pr*16 + (t4 >> 1)*8 + lr;
                int col  = kc*16 + (t4 & 1)*8;
                unsigned off = (unsigned)(buf*5120 + (brow*40 + col)*2);
                unsigned th[4], tl[4];
                ldsm_x4(th, smB + off);
                ldsm_x4(tl, smB + 10240 + off);
                unsigned bh0[2] = {th[0], th[1]}, bh1[2] = {th[2], th[3]};
                unsigned bl0[2] = {tl[0], tl[1]}, bl1[2] = {tl[2], tl[3]};
                mma_bf16(s[2*pr],   qh[kc], bh0);
                mma_bf16(s[2*pr],   qh[kc], bl0);
                mma_bf16(s[2*pr],   ql[kc], bh0);
                mma_bf16(s[2*pr+1], qh[kc], bh1);
                mma_bf16(s[2*pr+1], qh[kc], bl1);
                mma_bf16(s[2*pr+1], ql[kc], bh1);
            }
        }

        #pragma unroll
        for (int nt = 0; nt < 8; nt++)
            #pragma unroll
            for (int q = 0; q < 4; q++) s[nt][q] *= scale;
        if (j0 + 64 > NTOK){
            #pragma unroll
            for (int nt = 0; nt < 8; nt++){
                int c0 = j0 + nt*8 + (lane & 3)*2;
                if (c0     >= NTOK){ s[nt][0] = -1e30f; s[nt][2] = -1e30f; }
                if (c0 + 1 >= NTOK){ s[nt][1] = -1e30f; s[nt][3] = -1e30f; }
            }
        }

        float rm0 = -1e30f, rm1 = -1e30f;
        #pragma unroll
        for (int nt = 0; nt < 8; nt++){
            rm0 = fmaxf(rm0, fmaxf(s[nt][0], s[nt][1]));
            rm1 = fmaxf(rm1, fmaxf(s[nt][2], s[nt][3]));
        }
        rm0 = fmaxf(rm0, __shfl_xor_sync(0xffffffffu, rm0, 1));
        rm0 = fmaxf(rm0, __shfl_xor_sync(0xffffffffu, rm0, 2));
        rm1 = fmaxf(rm1, __shfl_xor_sync(0xffffffffu, rm1, 1));
        rm1 = fmaxf(rm1, __shfl_xor_sync(0xffffffffu, rm1, 2));
        float nm0 = fmaxf(m0, rm0), nm1 = fmaxf(m1, rm1);
        float a0 = __expf(m0 - nm0), a1 = __expf(m1 - nm1);
        float ps0 = 0.f, ps1 = 0.f;
        #pragma unroll
        for (int nt = 0; nt < 8; nt++){
            s[nt][0] = __expf(s[nt][0] - nm0);
            s[nt][1] = __expf(s[nt][1] - nm0);
            s[nt][2] = __expf(s[nt][2] - nm1);
            s[nt][3] = __expf(s[nt][3] - nm1);
            ps0 += s[nt][0] + s[nt][1];
            ps1 += s[nt][2] + s[nt][3];
        }
        ps0 += __shfl_xor_sync(0xffffffffu, ps0, 1);
        ps0 += __shfl_xor_sync(0xffffffffu, ps0, 2);
        ps1 += __shfl_xor_sync(0xffffffffu, ps1, 1);
        ps1 += __shfl_xor_sync(0xffffffffu, ps1, 2);
        l0 = l0*a0 + ps0; l1 = l1*a1 + ps1;
        m0 = nm0; m1 = nm1;
        #pragma unroll
        for (int nt = 0; nt < 4; nt++){
            o[nt][0] *= a0; o[nt][1] *= a0;
            o[nt][2] *= a1; o[nt][3] *= a1;
        }

        #pragma unroll
        for (int kc2 = 0; kc2 < 4; kc2++){
            unsigned pah[4], pal[4];
            {
                const float* u = s[2*kc2];
                const float* v2 = s[2*kc2 + 1];
                bf16 h0,lo0,h1,lo1;
                splitv(u[0], h0, lo0); splitv(u[1], h1, lo1);
                pah[0] = pack2u(h0, h1);   pal[0] = pack2u(lo0, lo1);
                splitv(u[2], h0, lo0); splitv(u[3], h1, lo1);
                pah[1] = pack2u(h0, h1);   pal[1] = pack2u(lo0, lo1);
                splitv(v2[0], h0, lo0); splitv(v2[1], h1, lo1);
                pah[2] = pack2u(h0, h1);   pal[2] = pack2u(lo0, lo1);
                splitv(v2[2], h0, lo0); splitv(v2[3], h1, lo1);
                pah[3] = pack2u(h0, h1);   pal[3] = pack2u(lo0, lo1);
            }
            #pragma unroll
            for (int pr2 = 0; pr2 < 2; pr2++){
                int krow = kc2*16 + (t4 & 1)*8 + lr;
                int ncol = pr2*16 + (t4 >> 1)*8;
                unsigned off = (unsigned)(buf*5120 + (krow*40 + ncol)*2);
                unsigned th[4], tl[4];
                ldsm_x4t(th, smB + 20480 + off);
                ldsm_x4t(tl, smB + 30720 + off);
                unsigned bh0[2] = {th[0], th[1]}, bh1[2] = {th[2], th[3]};
                unsigned bl0[2] = {tl[0], tl[1]}, bl1[2] = {tl[2], tl[3]};
                mma_bf16(o[2*pr2],   pah, bh0);
                mma_bf16(o[2*pr2],   pah, bl0);
                mma_bf16(o[2*pr2],   pal, bh0);
                mma_bf16(o[2*pr2+1], pah, bh1);
                mma_bf16(o[2*pr2+1], pah, bl1);
                mma_bf16(o[2*pr2+1], pal, bh1);
            }
        }
        __syncthreads();
        buf ^= 1;
    }

    float inv0 = 1.f / l0, inv1 = 1.f / l1;
    #pragma unroll
    for (int nt = 0; nt < 4; nt++){
        int row0 = i0 + w*16 + (lane >> 2);
        int col  = nt*8 + (lane & 3)*2;
        if (row0 < NTOK){
            size_t dst = ((size_t)tb*NTOK + row0)*D + h*EH + col;
            bf16 h0,lo0,h1,lo1;
            splitv(o[nt][0]*inv0, h0, lo0); splitv(o[nt][1]*inv0, h1, lo1);
            *(__nv_bfloat162*)(p_att + dst)       = __halves2bfloat162(h0, h1);
            *(__nv_bfloat162*)(p_att + TMD + dst) = __halves2bfloat162(lo0, lo1);
        }
        if (row0 + 8 < NTOK){
            size_t dst = ((size_t)tb*NTOK + row0 + 8)*D + h*EH + col;
            bf16 h2,lo2,h3,lo3;
            splitv(o[nt][2]*inv1, h2, lo2); splitv(o[nt][3]*inv1, h3, lo3);
            *(__nv_bfloat162*)(p_att + dst)       = __halves2bfloat162(h2, h3);
            *(__nv_bfloat162*)(p_att + TMD + dst) = __halves2bfloat162(lo2, lo3);
        }
    }
}

// ---------------- LayerNorm(x [- sub]) over D=256 (+ optional planes) ----
__global__ __launch_bounds__(256) void ln_kernel(const float* __restrict__ X,
                                                 const float* __restrict__ Sub,
                                                 const float* __restrict__ g,
                                                 const float* __restrict__ beta,
                                                 float* __restrict__ Out,
                                                 bf16* __restrict__ pH,
                                                 bf16* __restrict__ pL){
    int row = blockIdx.x, d = threadIdx.x;
    size_t i = (size_t)row*D + d;
    float v = X[i] - (Sub ? Sub[i] : 0.f);
    float2 r = blockReduce2(v, v*v);
    float mean = r.x * (1.f/D);
    float var  = r.y * (1.f/D) - mean*mean;
    float o = (v - mean) * rsqrtf(var + EPS) * g[d] + beta[d];
    Out[i] = o;
    if (pH){
        bf16 hh, ll; splitv(o, hh, ll);
        pH[i] = hh; pL[i] = ll;
    }
}

// ---------------- final: transpose + de-standardize + average scales ------
__global__ __launch_bounds__(256) void final_kernel(float* __restrict__ out){
    __shared__ float t0[32][33], t1[32][33];
    int b = blockIdx.z;
    int p0 = blockIdx.x*32, n0 = blockIdx.y*32;
    int tx = threadIdx.x & 31, ty = threadIdx.x >> 5;
    #pragma unroll
    for (int i = 0; i < 4; i++){
        int n = n0 + ty + i*8, pp = p0 + tx;
        if (n < ENC && pp < DB){
            t0[ty + i*8][tx] = g_out[((size_t)b*NTOK + n)*DB + pp];
            t1[ty + i*8][tx] = g_out[((size_t)(B_ + b)*NTOK + n)*DB + pp];
        }
    }
    __syncthreads();
    #pragma unroll
    for (int i = 0; i < 4; i++){
        int pp = p0 + ty + i*8, n = n0 + tx;
        if (pp < DB && n < ENC){
            float v0 = t0[tx][ty + i*8]*g_std[b*ENC + n]        + g_mean[b*ENC + n];
            float v1 = t1[tx][ty + i*8]*g_std[(B_ + b)*ENC + n] + g_mean[(B_ + b)*ENC + n];
            out[((size_t)b*DB + pp)*ENC + n] = 0.5f*(v0 + v1);
        }
    }
}

// ---------------- host ----------------
static inline int gsz(int nt){ return nt < 444 ? nt : 444; }
static void* sym(const void* s){ void* p; cudaGetSymbolAddress(&p, s); return p; }

extern "C" void kernel_launch(void* const* d_in, const int* in_sizes, int n_in,
                              void* d_out, int out_size){
    const float* mbx  = (const float*)d_in[0];
    const float* mbxm = (const float*)d_in[1];
    const float* embW = (const float*)d_in[4];
    const float* embB = (const float*)d_in[5];
    const float* Wq = (const float*)d_in[6];
    const float* Wk = (const float*)d_in[7];
    const float* Wv = (const float*)d_in[8];
    const float* Wo = (const float*)d_in[9];
    const float* W3 = (const float*)d_in[10];
    const float* W4 = (const float*)d_in[11];
    const float* bq = (const float*)d_in[12];
    const float* bk = (const float*)d_in[13];
    const float* bv = (const float*)d_in[14];
    const float* bo = (const float*)d_in[15];
    const float* b3 = (const float*)d_in[16];
    const float* b4 = (const float*)d_in[17];
    const float* W1 = (const float*)d_in[18];
    const float* b1 = (const float*)d_in[19];
    const float* W2 = (const float*)d_in[20];
    const float* b2 = (const float*)d_in[21];
    const float* W5 = (const float*)d_in[22];
    const float* b5 = (const float*)d_in[23];
    const float* W6 = (const float*)d_in[24];
    const float* b6 = (const float*)d_in[25];
    const float* ln1g = (const float*)d_in[26];
    const float* ln1b = (const float*)d_in[27];
    const float* ln2g = (const float*)d_in[28];
    const float* ln2b = (const float*)d_in[29];
    float* out = (float*)d_out;

    float* hF   = (float*)sym(g_h);
    float* xatt = (float*)sym(g_xatt);
    float* xln  = (float*)sym(g_xln);
    float* hhF  = (float*)sym(g_hh);
    float* outF = (float*)sym(g_out);

    bf16* xinP = (bf16*)sym(p_xin);
    bf16* hP   = (bf16*)sym(p_h);
    bf16* qkvP = (bf16*)sym(p_qkv);
    bf16* attP = (bf16*)sym(p_att);
    bf16* xlnP = (bf16*)sym(p_xln);
    bf16* y1P  = (bf16*)sym(p_y1);
    bf16* xsP  = (bf16*)sym(p_xs);
    bf16* xattP = (bf16*)sym(p_xatt);
    bf16* yP   = (bf16*)sym(p_y);
    bf16* embWP = (bf16*)sym(p_embW);
    bf16* WqP = (bf16*)sym(p_Wq); bf16* WkP = (bf16*)sym(p_Wk);
    bf16* WvP = (bf16*)sym(p_Wv); bf16* WoP = (bf16*)sym(p_Wo);
    bf16* W3P = (bf16*)sym(p_W3); bf16* W4P = (bf16*)sym(p_W4);
    bf16* W1P = (bf16*)sym(p_W1); bf16* W2P = (bf16*)sym(p_W2);
    bf16* W5P = (bf16*)sym(p_W5); bf16* W6P = (bf16*)sym(p_W6);

    const size_t EWN = (size_t)256*SEQP;
    const size_t WDD = (size_t)LAYERS*D*D;
    const size_t W1N = (size_t)LAYERS*DFF*D;
    const size_t W5N = (size_t)LAYERS*DB*2*D;
    const size_t Y1N = (size_t)TM*DFF;

    cudaFuncSetAttribute(mma_gemm<0>, cudaFuncAttributeMaxDynamicSharedMemorySize, 61440);
    cudaFuncSetAttribute(mma_gemm<1>, cudaFuncAttributeMaxDynamicSharedMemorySize, 61440);
    cudaFuncSetAttribute(mma_gemm<2>, cudaFuncAttributeMaxDynamicSharedMemorySize, 61440);
    cudaFuncSetAttribute(mma_gemm2<0>, cudaFuncAttributeMaxDynamicSharedMemorySize, 61440);
    cudaFuncSetAttribute(mma_gemm2<1>, cudaFuncAttributeMaxDynamicSharedMemorySize, 61440);

    // weight splits (one batched launch + embed pad)
    {
        WSArgs ws;
        const float* ss[10] = {Wq, Wk, Wv, Wo, W3, W4, W1, W2, W5, W6};
        bf16* hh[10] = {WqP, WkP, WvP, WoP, W3P, W4P, W1P, W2P, W5P, W6P};
        size_t nn[10] = {WDD, WDD, WDD, WDD, WDD, WDD, W1N, W1N, W5N, W5N};
        for (int i = 0; i < 10; i++){
            ws.s[i] = ss[i]; ws.h[i] = hh[i]; ws.l[i] = hh[i] + nn[i]; ws.n[i] = (int)nn[i];
        }
        wsplit_all<<<dim3(288, 10), 256>>>(ws);
        wsplit_pad<<<(unsigned)((EWN + 255)/256), 256>>>(embW, embWP, embWP + EWN, 256, SEQ, SEQP);
    }

    const int tm = 109;   // ceil(13856/128)
    const int tm64 = 217; // ceil(13856/64)

    // ---- both time-scales in one batched pass ----
    stats_kernel<<<dim3((ENC + 255)/256, B_, TS), 256>>>(mbx);
    xin_kernel<<<dim3((SEQP + 31)/32, (NTOK + 31)/32, TS*B_), 256>>>(mbx, mbxm);

    {   // embed -> fp32 h + planes
        GemmArgs a = {};
        a.aH[0] = xinP; a.aL[0] = xinP + TXN;
        a.wH[0] = embWP; a.wL[0] = embWP + EWN;
        a.bias[0] = embB; a.C[0] = hF;
        a.cH[0] = hP; a.cL[0] = hP + TMD;
        mma_gemm<0><<<gsz(tm*4), 256, 61440>>>(a, TM, D, SEQP, 4, tm*4, tm*4);
    }

    for (int l = 0; l < LAYERS; l++){
        {   // QKV -> planes
            GemmArgs a = {};
            for (int z = 0; z < 3; z++){
                a.aH[z] = hP; a.aL[z] = hP + TMD;
                a.cH[z] = qkvP + (size_t)z*TMD;
                a.cL[z] = qkvP + 3*TMD + (size_t)z*TMD;
            }
            a.wH[0] = WqP + (size_t)l*D*D; a.wL[0] = WqP + WDD + (size_t)l*D*D;
            a.wH[1] = WkP + (size_t)l*D*D; a.wL[1] = WkP + WDD + (size_t)l*D*D;
            a.wH[2] = WvP + (size_t)l*D*D; a.wL[2] = WvP + WDD + (size_t)l*D*D;
            a.bias[0] = bq + l*D; a.bias[1] = bk + l*D; a.bias[2] = bv + l*D;
            mma_gemm<0><<<gsz(tm*4*3), 256, 61440>>>(a, TM, D, D, 4, tm*4, tm*4*3);
        }

        flash_attn<<<dim3(7, TS*B_*NH), 256>>>();

        {   // Wo -> fp32 xatt + planes
            GemmArgs a = {};
            a.aH[0] = attP; a.aL[0] = attP + TMD;
            a.wH[0] = WoP + (size_t)l*D*D; a.wL[0] = WoP + WDD + (size_t)l*D*D;
            a.bias[0] = bo + l*D; a.C[0] = xatt;
            a.cH[0] = xattP; a.cL[0] = xattP + TMD;
            mma_gemm<0><<<gsz(tm*4), 256, 61440>>>(a, TM, D, D, 4, tm*4, tm*4);
        }

        ln_kernel<<<TM, 256>>>(hF, xatt, ln1g + l*D, ln1b + l*D, xln,
                               xlnP, xlnP + TMD);

        {   // W1 + GELU -> y1 planes
            GemmArgs a = {};
            a.aH[0] = xlnP; a.aL[0] = xlnP + TMD;
            a.wH[0] = W1P + (size_t)l*DFF*D; a.wL[0] = W1P + W1N + (size_t)l*DFF*D;
            a.bias[0] = b1 + l*DFF;
            a.cH[0] = y1P; a.cL[0] = y1P + Y1N;
            mma_gemm<1><<<gsz(tm*8), 256, 61440>>>(a, TM, DFF, D, 8, tm*8, tm*8);
        }
        {   // W2 -> y planes + xs=(xln-y) planes (sub fused)
            GemmArgs a = {};
            a.aH[0] = y1P; a.aL[0] = y1P + Y1N;
            a.wH[0] = W2P + (size_t)l*D*DFF; a.wL[0] = W2P + W1N + (size_t)l*D*DFF;
            a.bias[0] = b2 + l*D;
            a.cH[0] = yP; a.cL[0] = yP + TMD;
            a.xsub[0] = xln;
            a.c2H[0] = xsP; a.c2L[0] = xsP + TMD;
            mma_gemm<2><<<gsz(tm*4), 256, 61440>>>(a, TM, D, DFF, 4, tm*4, tm*4);
        }

        {   // fused W3/W4 -> hh = sigmoid(.)*(.)
            Gemm2Args a = {};
            a.a0H = xsP; a.a0L = xsP + TMD; a.a1H = xsP; a.a1L = xsP + TMD;
            a.kSplit = 1 << 30; a.aStride = D;
            a.w1H = W3P + (size_t)l*D*D; a.w1L = W3P + WDD + (size_t)l*D*D;
            a.w2H = W4P + (size_t)l*D*D; a.w2L = W4P + WDD + (size_t)l*D*D;
            a.b1 = b3 + l*D; a.b2 = b4 + l*D;
            a.Cout = hhF; a.sub = 0;
            mma_gemm2<0><<<gsz(tm64*4), 256, 61440>>>(a, TM, D, D, 4, tm64*4);
        }

        {   // fused W5/W6 over cat(xatt,y) -> g_out (with layer subtract)
            Gemm2Args a = {};
            a.a0H = xattP; a.a0L = xattP + TMD;
            a.a1H = yP;    a.a1L = yP + TMD;
            a.kSplit = D; a.aStride = D;
            a.w1H = W5P + (size_t)l*DB*2*D; a.w1L = W5P + W5N + (size_t)l*DB*2*D;
            a.w2H = W6P + (size_t)l*DB*2*D; a.w2L = W6P + W5N + (size_t)l*DB*2*D;
            a.b1 = b5 + l*DB; a.b2 = b6 + l*DB;
            a.Cout = outF; a.sub = l;
            mma_gemm2<1><<<gsz(tm64*12), 256, 61440>>>(a, TM, DB, 2*D, 12, tm64*12);
        }

        ln_kernel<<<TM, 256>>>(hhF, (const float*)nullptr,
                               ln2g + l*D, ln2b + l*D, hF, hP, hP + TMD);
    }

    final_kernel<<<dim3((DB + 31)/32, (ENC + 31)/32, B_), 256>>>(out);
}

// round 13
// speedup vs baseline: 1.2372x; 1.0034x over previous
#include <cuda_runtime.h>
#include <cuda_bf16.h>
#include <math.h>

#define B_    8
#define TS    2
#define SEQ   720
#define SEQP  736
#define ENC   862
#define MARKD 4
#define NTOK  866
#define D     256
#define NH    8
#define EH    32
#define DFF   512
#define DB    720
#define LAYERS 2
#define EPS   1e-5f
#define MROWS (B_*NTOK)        // 6928 per scale
#define TM    (TS*MROWS)       // 13856 combined
#define TMD   ((size_t)TM*D)
#define TXN   ((size_t)TM*SEQP)

typedef __nv_bfloat16 bf16;

// ---------------- fp32 scratch ----------------
__device__ float g_mean[TS*B_*ENC], g_std[TS*B_*ENC];
__device__ float g_out[(size_t)TM*DB];

// ---------------- bf16 hi/lo planes (lo at +n) ----------------
__device__ __align__(16) bf16 p_xin[2*TXN];
__device__ __align__(16) bf16 p_h  [2*TMD];
__device__ __align__(16) bf16 p_qkv[2*3*TMD];
__device__ __align__(16) bf16 p_att[2*TMD];
__device__ __align__(16) bf16 p_xln[2*TMD];
__device__ __align__(16) bf16 p_y1 [2*(size_t)TM*DFF];
__device__ __align__(16) bf16 p_xs [2*TMD];
__device__ __align__(16) bf16 p_xatt[2*TMD];
__device__ __align__(16) bf16 p_y  [2*TMD];
__device__ __align__(16) bf16 p_hh [2*TMD];
// weights
__device__ __align__(16) bf16 p_embW[2*256*SEQP];
__device__ __align__(16) bf16 p_Wq[2*LAYERS*D*D], p_Wk[2*LAYERS*D*D], p_Wv[2*LAYERS*D*D];
__device__ __align__(16) bf16 p_Wo[2*LAYERS*D*D], p_W3[2*LAYERS*D*D], p_W4[2*LAYERS*D*D];
__device__ __align__(16) bf16 p_W1[2*LAYERS*DFF*D], p_W2[2*LAYERS*D*DFF];
__device__ __align__(16) bf16 p_W5[2*LAYERS*DB*2*D], p_W6[2*LAYERS*DB*2*D];

// ---------------- helpers ----------------
__device__ __forceinline__ void splitv(float x, bf16& h, bf16& l){
    h = __float2bfloat16(x);
    l = __float2bfloat16(x - __bfloat162float(h));
}
__device__ __forceinline__ unsigned pack2u(bf16 a, bf16 b){
    __nv_bfloat162 t = __halves2bfloat162(a, b);
    return *(unsigned*)&t;
}
__device__ __forceinline__ void mma_bf16(float c[4], const unsigned a[4], const unsigned b[2]){
    asm volatile("mma.sync.aligned.m16n8k16.row.col.f32.bf16.bf16.f32 "
                 "{%0,%1,%2,%3}, {%4,%5,%6,%7}, {%8,%9}, {%0,%1,%2,%3};\n"
                 : "+f"(c[0]), "+f"(c[1]), "+f"(c[2]), "+f"(c[3])
                 : "r"(a[0]), "r"(a[1]), "r"(a[2]), "r"(a[3]),
                   "r"(b[0]), "r"(b[1]));
}
__device__ __forceinline__ void ldsm_x4(unsigned r[4], unsigned addr){
    asm volatile("ldmatrix.sync.aligned.m8n8.x4.shared.b16 {%0,%1,%2,%3}, [%4];\n"
                 : "=r"(r[0]), "=r"(r[1]), "=r"(r[2]), "=r"(r[3]) : "r"(addr));
}
__device__ __forceinline__ void ldsm_x4t(unsigned r[4], unsigned addr){
    asm volatile("ldmatrix.sync.aligned.m8n8.x4.trans.shared.b16 {%0,%1,%2,%3}, [%4];\n"
                 : "=r"(r[0]), "=r"(r[1]), "=r"(r[2]), "=r"(r[3]) : "r"(addr));
}
__device__ __forceinline__ void cp16(unsigned dst, const void* src, bool p){
    int sz = p ? 16 : 0;
    asm volatile("cp.async.cg.shared.global [%0], [%1], 16, %2;\n"
                 :: "r"(dst), "l"(src), "r"(sz));
}
__device__ __forceinline__ void cpcommit(){ asm volatile("cp.async.commit_group;\n"); }
template<int N> __device__ __forceinline__ void cpwait(){
    asm volatile("cp.async.wait_group %0;\n" :: "n"(N));
}
__device__ __forceinline__ float gelu_f(float x){
    return 0.5f*x*(1.f + erff(x*0.70710678118654752f));
}
__device__ __forceinline__ float sigmoid_f(float x){
    return 1.f/(1.f + expf(-x));
}
__device__ __forceinline__ float2 blockReduce2(float a, float b){
    __shared__ float2 sh[33];
    int lane = threadIdx.x & 31, wid = threadIdx.x >> 5;
    __syncthreads();
    #pragma unroll
    for (int o = 16; o; o >>= 1){
        a += __shfl_down_sync(0xffffffffu, a, o);
        b += __shfl_down_sync(0xffffffffu, b, o);
    }
    if (lane == 0) sh[wid] = make_float2(a, b);
    __syncthreads();
    if (wid == 0){
        int nw = blockDim.x >> 5;
        float2 v = (lane < nw) ? sh[lane] : make_float2(0.f, 0.f);
        a = v.x; b = v.y;
        #pragma unroll
        for (int o = 16; o; o >>= 1){
            a += __shfl_down_sync(0xffffffffu, a, o);
            b += __shfl_down_sync(0xffffffffu, b, o);
        }
        if (lane == 0) sh[32] = make_float2(a, b);
    }
    __syncthreads();
    return sh[32];
}

// ---------------- weight split (batched) ----------------
struct WSArgs { const float* s[10]; bf16* h[10]; bf16* l[10]; int n[10]; };
__global__ void wsplit_all(WSArgs w){
    int z = blockIdx.y;
    int n = w.n[z];
    const float* src = w.s[z];
    bf16* hh = w.h[z]; bf16* ll = w.l[z];
    for (int i = blockIdx.x*blockDim.x + threadIdx.x; i < n; i += gridDim.x*blockDim.x)
        splitv(src[i], hh[i], ll[i]);
}
__global__ void wsplit_pad(const float* __restrict__ s, bf16* __restrict__ h,
                           bf16* __restrict__ l, int rows, int K, int Kp){
    size_t i = (size_t)blockIdx.x*blockDim.x + threadIdx.x;
    size_t total = (size_t)rows*Kp;
    if (i >= total) return;
    int c = (int)(i % Kp); int r = (int)(i / Kp);
    float v = (c < K) ? s[(size_t)r*K + c] : 0.f;
    splitv(v, h[i], l[i]);
}

// ---------------- input standardization (both scales) ----------------
__global__ void stats_kernel(const float* __restrict__ mbx){
    int t = blockIdx.z, b = blockIdx.y;
    int n = blockIdx.x * blockDim.x + threadIdx.x;
    if (n >= ENC) return;
    const float* base = mbx + ((size_t)(b*TS + t)*SEQ)*ENC + n;
    float s = 0.f, ss = 0.f;
    for (int i = 0; i < SEQ; i++){
        float v = base[(size_t)i*ENC];
        s += v; ss += v*v;
    }
    float m = s * (1.f/SEQ);
    float var = ss * (1.f/SEQ) - m*m;
    g_mean[(t*B_ + b)*ENC + n] = m;
    g_std [(t*B_ + b)*ENC + n] = sqrtf(var + EPS);
}

// transposed tiled build of xin planes for both scales
__global__ __launch_bounds__(256) void xin_kernel(const float* __restrict__ mbx,
                                                  const float* __restrict__ mbxm){
    __shared__ float tile[32][33];
    const int zb = blockIdx.z;            // t*B_ + b
    const int t = zb / B_, b = zb % B_;
    const int s0 = blockIdx.x*32, n0 = blockIdx.y*32;
    const int tx = threadIdx.x & 31, ty = threadIdx.x >> 5;
    #pragma unroll
    for (int i = 0; i < 4; i++){
        int s = s0 + ty + i*8, n = n0 + tx;
        float v = 0.f;
        if (s < SEQ && n < NTOK){
            if (n < ENC){
                v = mbx[((size_t)(b*TS + t)*SEQ + s)*ENC + n];
                v = (v - g_mean[zb*ENC + n]) / g_std[zb*ENC + n];
            } else {
                v = mbxm[((size_t)(b*TS + t)*SEQ + s)*MARKD + (n - ENC)];
            }
        }
        tile[ty + i*8][tx] = v;
    }
    __syncthreads();
    #pragma unroll
    for (int i = 0; i < 4; i++){
        int n = n0 + ty + i*8, s = s0 + tx;
        if (n < NTOK && s < SEQP){
            size_t idx = ((size_t)zb*NTOK + n)*SEQP + s;
            splitv(tile[tx][ty + i*8], p_xin[idx], p_xin[TXN + idx]);
        }
    }
}

// =============== MMA GEMM: planes = A @ W^T + bias (bf16 planes) ==========
// ACT 0: plain; 1: gelu; 2: also emit (xsub - y) planes (xsub from planes)
struct GemmArgs {
    const bf16 *aH[3], *aL[3], *wH[3], *wL[3];
    const float* bias[3];
    bf16 *cH[3], *cL[3];
    const bf16 *xsH[3], *xsL[3];
    bf16 *c2H[3], *c2L[3];
};

template<int ACT>
__global__ __launch_bounds__(256, 3)
void mma_gemm(GemmArgs p, int M, int N, int K, int tilesN, int tpz, int nTiles){
    extern __shared__ __align__(16) char smraw[];
    bf16* sAh = (bf16*)smraw;            // [2][128][40]
    bf16* sAl = sAh + 2*128*40;
    bf16* sBh = sAl + 2*128*40;          // [2][64][40]
    bf16* sBl = sBh + 2*64*40;
    const unsigned aHiB = (unsigned)__cvta_generic_to_shared(sAh);
    const unsigned aLoB = (unsigned)__cvta_generic_to_shared(sAl);
    const unsigned bHiB = (unsigned)__cvta_generic_to_shared(sBh);
    const unsigned bLoB = (unsigned)__cvta_generic_to_shared(sBl);

    const int tid = threadIdx.x;
    const int lane = tid & 31, w = tid >> 5;
    const int wm = (w >> 1)*32, wn = (w & 1)*32;
    const int t4 = lane >> 3, lr = lane & 7;
    const int ldr = tid >> 2, ldc = (tid & 3)*8;

    for (int t = blockIdx.x; t < nTiles; t += gridDim.x){
        const int z  = t / tpz;
        const int rr = t - z*tpz;
        const int bm = (rr / tilesN)*128, bn = (rr % tilesN)*64;
        const bf16* __restrict__ aHp = p.aH[z];
        const bf16* __restrict__ aLp = p.aL[z];
        const bf16* __restrict__ wHp = p.wH[z];
        const bf16* __restrict__ wLp = p.wL[z];
        const float* __restrict__ bias = p.bias[z];
        bf16* cHp = p.cH[z];
        bf16* cLp = p.cL[z];

        float acc[2][4][4];
        #pragma unroll
        for (int i = 0; i < 2; i++)
            #pragma unroll
            for (int j = 0; j < 4; j++)
                #pragma unroll
                for (int q = 0; q < 4; q++) acc[i][j][q] = 0.f;

        auto loadst = [&](int s, int k0){
            #pragma unroll
            for (int rep = 0; rep < 2; rep++){
                int r = ldr + rep*64;
                int gm = bm + r;
                bool pr = gm < M;
                size_t so = (size_t)(pr ? gm : 0)*K + k0 + ldc;
                unsigned doff = (unsigned)(((s*128 + r)*40 + ldc)*2);
                cp16(aHiB + doff, aHp + so, pr);
                cp16(aLoB + doff, aLp + so, pr);
            }
            {
                int gn = bn + ldr;
                bool pn = gn < N;
                size_t so = (size_t)(pn ? gn : 0)*K + k0 + ldc;
                unsigned doff = (unsigned)(((s*64 + ldr)*40 + ldc)*2);
                cp16(bHiB + doff, wHp + so, pn);
                cp16(bLoB + doff, wLp + so, pn);
            }
            cpcommit();
        };

        loadst(0, 0);
        int buf = 0;
        const int KT = K >> 5;
        for (int kt = 0; kt < KT; kt++){
            if (kt + 1 < KT){ loadst(buf ^ 1, (kt+1)*32); cpwait<1>(); }
            else cpwait<0>();
            __syncthreads();

            #pragma unroll
            for (int kh = 0; kh < 32; kh += 16){
                unsigned ah[2][4], al[2][4], bh[4][2], bl[4][2];
                #pragma unroll
                for (int mt = 0; mt < 2; mt++){
                    int arow = wm + mt*16 + (t4 & 1)*8 + lr;
                    unsigned off = (unsigned)((((buf*128) + arow)*40 + kh + (t4 >> 1)*8)*2);
                    ldsm_x4(ah[mt], aHiB + off);
                    ldsm_x4(al[mt], aLoB + off);
                }
                #pragma unroll
                for (int pr2 = 0; pr2 < 2; pr2++){
                    int brow = wn + pr2*16 + (t4 >> 1)*8 + lr;
                    unsigned off = (unsigned)((((buf*64) + brow)*40 + kh + (t4 & 1)*8)*2);
                    unsigned th[4], tl[4];
                    ldsm_x4(th, bHiB + off);
                    ldsm_x4(tl, bLoB + off);
                    bh[pr2*2][0] = th[0]; bh[pr2*2][1] = th[1];
                    bh[pr2*2+1][0] = th[2]; bh[pr2*2+1][1] = th[3];
                    bl[pr2*2][0] = tl[0]; bl[pr2*2][1] = tl[1];
                    bl[pr2*2+1][0] = tl[2]; bl[pr2*2+1][1] = tl[3];
                }
                #pragma unroll
                for (int mt = 0; mt < 2; mt++)
                    #pragma unroll
                    for (int nt = 0; nt < 4; nt++){
                        mma_bf16(acc[mt][nt], ah[mt], bh[nt]);
                        mma_bf16(acc[mt][nt], ah[mt], bl[nt]);
                        mma_bf16(acc[mt][nt], al[mt], bh[nt]);
                    }
            }
            __syncthreads();
            buf ^= 1;
        }

        #pragma unroll
        for (int mt = 0; mt < 2; mt++)
            #pragma unroll
            for (int nt = 0; nt < 4; nt++){
                int row0 = bm + wm + mt*16 + (lane >> 2);
                int col  = bn + wn + nt*8 + (lane & 3)*2;
                if (col >= N) continue;
                float b0 = bias[col], b1 = bias[col + 1];
                float v0 = acc[mt][nt][0] + b0, v1 = acc[mt][nt][1] + b1;
                float v2 = acc[mt][nt][2] + b0, v3 = acc[mt][nt][3] + b1;
                if (ACT == 1){
                    v0 = gelu_f(v0); v1 = gelu_f(v1);
                    v2 = gelu_f(v2); v3 = gelu_f(v3);
                }
                if (row0 < M){
                    size_t ix = (size_t)row0*N + col;
                    bf16 h0,l0,h1,l1; splitv(v0,h0,l0); splitv(v1,h1,l1);
                    *(__nv_bfloat162*)(cHp + ix) = __halves2bfloat162(h0,h1);
                    *(__nv_bfloat162*)(cLp + ix) = __halves2bfloat162(l0,l1);
                    if (ACT == 2){
                        float x0 = __bfloat162float(p.xsH[z][ix]) + __bfloat162float(p.xsL[z][ix]);
                        float x1 = __bfloat162float(p.xsH[z][ix+1]) + __bfloat162float(p.xsL[z][ix+1]);
                        bf16 s0,t0,s1,t1; splitv(x0 - v0,s0,t0); splitv(x1 - v1,s1,t1);
                        *(__nv_bfloat162*)(p.c2H[z] + ix) = __halves2bfloat162(s0,s1);
                        *(__nv_bfloat162*)(p.c2L[z] + ix) = __halves2bfloat162(t0,t1);
                    }
                }
                if (row0 + 8 < M){
                    size_t ix = (size_t)(row0+8)*N + col;
                    bf16 h2,l2,h3,l3; splitv(v2,h2,l2); splitv(v3,h3,l3);
                    *(__nv_bfloat162*)(cHp + ix) = __halves2bfloat162(h2,h3);
                    *(__nv_bfloat162*)(cLp + ix) = __halves2bfloat162(l2,l3);
                    if (ACT == 2){
                        float x2 = __bfloat162float(p.xsH[z][ix]) + __bfloat162float(p.xsL[z][ix]);
                        float x3 = __bfloat162float(p.xsH[z][ix+1]) + __bfloat162float(p.xsL[z][ix+1]);
                        bf16 s2,t2,s3,t3; splitv(x2 - v2,s2,t2); splitv(x3 - v3,s3,t3);
                        *(__nv_bfloat162*)(p.c2H[z] + ix) = __halves2bfloat162(s2,s3);
                        *(__nv_bfloat162*)(p.c2L[z] + ix) = __halves2bfloat162(t2,t3);
                    }
                }
            }
    }
}

// =============== fused dual GEMM (BM=64): o = sig(A W1^T+b1)*(A W2^T+b2) ==
// MODE 0: write o as bf16 planes (cH/cL); MODE 1: fp32 Cout = sub ? o-C : o
struct Gemm2Args {
    const bf16 *a0H, *a0L, *a1H, *a1L;
    int kSplit, aStride;
    const bf16 *w1H, *w1L, *w2H, *w2L;
    const float *b1, *b2;
    float* Cout;
    bf16 *cH, *cL;
    int sub;
};

template<int MODE>
__global__ __launch_bounds__(256, 3)
void mma_gemm2(Gemm2Args p, int M, int N, int K, int tilesN, int nTiles){
    extern __shared__ __align__(16) char smraw[];
    bf16* sm = (bf16*)smraw;
    const unsigned smB = (unsigned)__cvta_generic_to_shared(sm);
    const int tid = threadIdx.x;
    const int lane = tid & 31, w = tid >> 5;
    const int wm = (w >> 1)*16, wn = (w & 1)*32;
    const int t4 = lane >> 3, lr = lane & 7;
    const int ldr = tid >> 2, ldc = (tid & 3)*8;

    for (int t = blockIdx.x; t < nTiles; t += gridDim.x){
        const int bm = (t / tilesN)*64, bn = (t % tilesN)*64;

        float acc[2][4][4];
        #pragma unroll
        for (int g = 0; g < 2; g++)
            #pragma unroll
            for (int j = 0; j < 4; j++)
                #pragma unroll
                for (int q = 0; q < 4; q++) acc[g][j][q] = 0.f;

        auto loadst = [&](int s, int k0){
            const bf16* aH = (k0 < p.kSplit) ? p.a0H : p.a1H;
            const bf16* aL = (k0 < p.kSplit) ? p.a0L : p.a1L;
            int kk = (k0 < p.kSplit) ? k0 : k0 - p.kSplit;
            int gm = bm + ldr;
            bool pr = gm < M;
            size_t soA = (size_t)(pr ? gm : 0)*p.aStride + kk + ldc;
            unsigned dA = (unsigned)((s*2*2560 + ldr*40 + ldc)*2);
            cp16(smB + dA,           aH + soA, pr);
            cp16(smB + dA + 2560*2,  aL + soA, pr);
            int gn = bn + ldr;
            bool pn = gn < N;
            size_t soB = (size_t)(pn ? gn : 0)*K + k0 + ldc;
            unsigned dB = (unsigned)((10240 + s*4*2560 + ldr*40 + ldc)*2);
            cp16(smB + dB,             p.w1H + soB, pn);
            cp16(smB + dB + 2560*2,    p.w1L + soB, pn);
            cp16(smB + dB + 2*2560*2,  p.w2H + soB, pn);
            cp16(smB + dB + 3*2560*2,  p.w2L + soB, pn);
            cpcommit();
        };

        loadst(0, 0);
        int buf = 0;
        const int KT = K >> 5;
        for (int kt = 0; kt < KT; kt++){
            if (kt + 1 < KT){ loadst(buf ^ 1, (kt+1)*32); cpwait<1>(); }
            else cpwait<0>();
            __syncthreads();

            #pragma unroll
            for (int kh = 0; kh < 32; kh += 16){
                unsigned ah[4], al[4];
                {
                    int arow = wm + (t4 & 1)*8 + lr;
                    unsigned off = (unsigned)((buf*2*2560 + arow*40 + kh + (t4 >> 1)*8)*2);
                    ldsm_x4(ah, smB + off);
                    ldsm_x4(al, smB + off + 2560*2);
                }
                #pragma unroll
                for (int g = 0; g < 2; g++){
                    #pragma unroll
                    for (int pr2 = 0; pr2 < 2; pr2++){
                        int brow = wn + pr2*16 + (t4 >> 1)*8 + lr;
                        unsigned off = (unsigned)((10240 + buf*4*2560 + g*2*2560
                                                   + brow*40 + kh + (t4 & 1)*8)*2);
                        unsigned th[4], tl[4];
                        ldsm_x4(th, smB + off);
                        ldsm_x4(tl, smB + off + 2560*2);
                        unsigned bh0[2] = {th[0], th[1]}, bh1[2] = {th[2], th[3]};
                        unsigned bl0[2] = {tl[0], tl[1]}, bl1[2] = {tl[2], tl[3]};
                        mma_bf16(acc[g][2*pr2],   ah, bh0);
                        mma_bf16(acc[g][2*pr2],   ah, bl0);
                        mma_bf16(acc[g][2*pr2],   al, bh0);
                        mma_bf16(acc[g][2*pr2+1], ah, bh1);
                        mma_bf16(acc[g][2*pr2+1], ah, bl1);
                        mma_bf16(acc[g][2*pr2+1], al, bh1);
                    }
                }
            }
            __syncthreads();
            buf ^= 1;
        }

        #pragma unroll
        for (int nt = 0; nt < 4; nt++){
            int row0 = bm + wm + (lane >> 2);
            int col  = bn + wn + nt*8 + (lane & 3)*2;
            if (col >= N) continue;
            float b10 = p.b1[col], b11 = p.b1[col + 1];
            float b20 = p.b2[col], b21 = p.b2[col + 1];
            float o0 = sigmoid_f(acc[0][nt][0] + b10)*(acc[1][nt][0] + b20);
            float o1 = sigmoid_f(acc[0][nt][1] + b11)*(acc[1][nt][1] + b21);
            float o2 = sigmoid_f(acc[0][nt][2] + b10)*(acc[1][nt][2] + b20);
            float o3 = sigmoid_f(acc[0][nt][3] + b11)*(acc[1][nt][3] + b21);
            if (row0 < M){
                size_t ix = (size_t)row0*N + col;
                if (MODE == 0){
                    bf16 h0,l0,h1,l1; splitv(o0,h0,l0); splitv(o1,h1,l1);
                    *(__nv_bfloat162*)(p.cH + ix) = __halves2bfloat162(h0,h1);
                    *(__nv_bfloat162*)(p.cL + ix) = __halves2bfloat162(l0,l1);
                } else if (p.sub){
                    p.Cout[ix]     = o0 - p.Cout[ix];
                    p.Cout[ix + 1] = o1 - p.Cout[ix + 1];
                } else {
                    p.Cout[ix] = o0; p.Cout[ix + 1] = o1;
                }
            }
            if (row0 + 8 < M){
                size_t ix = (size_t)(row0+8)*N + col;
                if (MODE == 0){
                    bf16 h2,l2,h3,l3; splitv(o2,h2,l2); splitv(o3,h3,l3);
                    *(__nv_bfloat162*)(p.cH + ix) = __halves2bfloat162(h2,h3);
                    *(__nv_bfloat162*)(p.cL + ix) = __halves2bfloat162(l2,l3);
                } else if (p.sub){
                    p.Cout[ix]     = o2 - p.Cout[ix];
                    p.Cout[ix + 1] = o3 - p.Cout[ix + 1];
                } else {
                    p.Cout[ix] = o2; p.Cout[ix + 1] = o3;
                }
            }
        }
    }
}

// =============== flash attention (both scales via batch index) ============
__global__ __launch_bounds__(256) void flash_attn(){
    __shared__ __align__(16) bf16 sm[20480];   // 40 KB
    const unsigned smB = (unsigned)__cvta_generic_to_shared(sm);
    const int bh = blockIdx.y;
    const int tb = bh >> 3, h = bh & 7;
    const int i0 = blockIdx.x * 128;
    const bf16* qH = p_qkv +            (size_t)tb*NTOK*D + h*EH;
    const bf16* qL = qH + 3*TMD;
    const bf16* kH = p_qkv +    TMD +   (size_t)tb*NTOK*D + h*EH;
    const bf16* kL = kH + 3*TMD;
    const bf16* vH = p_qkv +  2*TMD +   (size_t)tb*NTOK*D + h*EH;
    const bf16* vL = vH + 3*TMD;

    const int tid = threadIdx.x, lane = tid & 31, w = tid >> 5;
    const int t4 = lane >> 3, lr = lane & 7;

    {
        int row = tid >> 1, c = (tid & 1)*16;
        int gi = i0 + row;
        bool ok = gi < NTOK;
        size_t so = (size_t)(ok ? gi : 0)*D + c;
        const float4 z4 = make_float4(0.f,0.f,0.f,0.f);
        float4 f0 = ok ? *(const float4*)(qH + so)     : z4;
        float4 f1 = ok ? *(const float4*)(qH + so + 8) : z4;
        *(float4*)&sm[row*40 + c]     = f0;
        *(float4*)&sm[row*40 + c + 8] = f1;
        f0 = ok ? *(const float4*)(qL + so)     : z4;
        f1 = ok ? *(const float4*)(qL + so + 8) : z4;
        *(float4*)&sm[5120 + row*40 + c]     = f0;
        *(float4*)&sm[5120 + row*40 + c + 8] = f1;
    }
    __syncthreads();
    unsigned qh[2][4], ql[2][4];
    #pragma unroll
    for (int kc = 0; kc < 2; kc++){
        int row = w*16 + (t4 & 1)*8 + lr;
        int col = kc*16 + (t4 >> 1)*8;
        ldsm_x4(qh[kc], smB + (unsigned)((row*40 + col)*2));
        ldsm_x4(ql[kc], smB + (unsigned)((5120 + row*40 + col)*2));
    }
    __syncthreads();

    const int ldr = tid >> 2, ldc = (tid & 3)*8;
    auto loadkv = [&](int s, int j0){
        int gj = j0 + ldr;
        bool ok = gj < NTOK;
        size_t so = (size_t)(ok ? gj : 0)*D + ldc;
        unsigned doff = (unsigned)(s*5120 + (ldr*40 + ldc)*2);
        cp16(smB + doff,         kH + so, ok);
        cp16(smB + 10240 + doff, kL + so, ok);
        cp16(smB + 20480 + doff, vH + so, ok);
        cp16(smB + 30720 + doff, vL + so, ok);
        cpcommit();
    };

    float o[4][4];
    #pragma unroll
    for (int j = 0; j < 4; j++)
        #pragma unroll
        for (int q = 0; q < 4; q++) o[j][q] = 0.f;
    float m0 = -1e30f, m1 = -1e30f, l0 = 0.f, l1 = 0.f;
    const float scale = 0.17677669529663688f;

    loadkv(0, 0);
    int buf = 0;
    const int NJT = 14;
    for (int jt = 0; jt < NJT; jt++){
        const int j0 = jt*64;
        if (jt + 1 < NJT){ loadkv(buf ^ 1, (jt+1)*64); cpwait<1>(); }
        else cpwait<0>();
        __syncthreads();

        float s[8][4];
        #pragma unroll
        for (int nt = 0; nt < 8; nt++)
            #pragma unroll
            for (int q = 0; q < 4; q++) s[nt][q] = 0.f;

        #pragma unroll
        for (int kc = 0; kc < 2; kc++){
            #pragma unroll
            for (int pr = 0; pr < 4; pr++){
                int brow = pr*16 + (t4 >> 1)*8 + lr;
                int col  = kc*16 + (t4 & 1)*8;
                unsigned off = (unsigned)(buf*5120 + (brow*40 + col)*2);
                unsigned th[4], tl[4];
                ldsm_x4(th, smB + off);
                ldsm_x4(tl, smB + 10240 + off);
                unsigned bh0[2] = {th[0], th[1]}, bh1[2] = {th[2], th[3]};
                unsigned bl0[2] = {tl[0], tl[1]}, bl1[2] = {tl[2], tl[3]};
                mma_bf16(s[2*pr],   qh[kc], bh0);
                mma_bf16(s[2*pr],   qh[kc], bl0);
                mma_bf16(s[2*pr],   ql[kc], bh0);
                mma_bf16(s[2*pr+1], qh[kc], bh1);
                mma_bf16(s[2*pr+1], qh[kc], bl1);
                mma_bf16(s[2*pr+1], ql[kc], bh1);
            }
        }

        #pragma unroll
        for (int nt = 0; nt < 8; nt++)
            #pragma unroll
            for (int q = 0; q < 4; q++) s[nt][q] *= scale;
        if (j0 + 64 > NTOK){
            #pragma unroll
            for (int nt = 0; nt < 8; nt++){
                int c0 = j0 + nt*8 + (lane & 3)*2;
                if (c0     >= NTOK){ s[nt][0] = -1e30f; s[nt][2] = -1e30f; }
                if (c0 + 1 >= NTOK){ s[nt][1] = -1e30f; s[nt][3] = -1e30f; }
            }
        }

        float rm0 = -1e30f, rm1 = -1e30f;
        #pragma unroll
        for (int nt = 0; nt < 8; nt++){
            rm0 = fmaxf(rm0, fmaxf(s[nt][0], s[nt][1]));
            rm1 = fmaxf(rm1, fmaxf(s[nt][2], s[nt][3]));
        }
        rm0 = fmaxf(rm0, __shfl_xor_sync(0xffffffffu, rm0, 1));
        rm0 = fmaxf(rm0, __shfl_xor_sync(0xffffffffu, rm0, 2));
        rm1 = fmaxf(rm1, __shfl_xor_sync(0xffffffffu, rm1, 1));
        rm1 = fmaxf(rm1, __shfl_xor_sync(0xffffffffu, rm1, 2));
        float nm0 = fmaxf(m0, rm0), nm1 = fmaxf(m1, rm1);
        float a0 = __expf(m0 - nm0), a1 = __expf(m1 - nm1);
        float ps0 = 0.f, ps1 = 0.f;
        #pragma unroll
        for (int nt = 0; nt < 8; nt++){
            s[nt][0] = __expf(s[nt][0] - nm0);
            s[nt][1] = __expf(s[nt][1] - nm0);
            s[nt][2] = __expf(s[nt][2] - nm1);
            s[nt][3] = __expf(s[nt][3] - nm1);
            ps0 += s[nt][0] + s[nt][1];
            ps1 += s[nt][2] + s[nt][3];
        }
        ps0 += __shfl_xor_sync(0xffffffffu, ps0, 1);
        ps0 += __shfl_xor_sync(0xffffffffu, ps0, 2);
        ps1 += __shfl_xor_sync(0xffffffffu, ps1, 1);
        ps1 += __shfl_xor_sync(0xffffffffu, ps1, 2);
        l0 = l0*a0 + ps0; l1 = l1*a1 + ps1;
        m0 = nm0; m1 = nm1;
        #pragma unroll
        for (int nt = 0; nt < 4; nt++){
            o[nt][0] *= a0; o[nt][1] *= a0;
            o[nt][2] *= a1; o[nt][3] *= a1;
        }

        #pragma unroll
        for (int kc2 = 0; kc2 < 4; kc2++){
            unsigned pah[4], pal[4];
            {
                const float* u = s[2*kc2];
                const float* v2 = s[2*kc2 + 1];
                bf16 h0,lo0,h1,lo1;
                splitv(u[0], h0, lo0); splitv(u[1], h1, lo1);
                pah[0] = pack2u(h0, h1);   pal[0] = pack2u(lo0, lo1);
                splitv(u[2], h0, lo0); splitv(u[3], h1, lo1);
                pah[1] = pack2u(h0, h1);   pal[1] = pack2u(lo0, lo1);
                splitv(v2[0], h0, lo0); splitv(v2[1], h1, lo1);
                pah[2] = pack2u(h0, h1);   pal[2] = pack2u(lo0, lo1);
                splitv(v2[2], h0, lo0); splitv(v2[3], h1, lo1);
                pah[3] = pack2u(h0, h1);   pal[3] = pack2u(lo0, lo1);
            }
            #pragma unroll
            for (int pr2 = 0; pr2 < 2; pr2++){
                int krow = kc2*16 + (t4 & 1)*8 + lr;
                int ncol = pr2*16 + (t4 >> 1)*8;
                unsigned off = (unsigned)(buf*5120 + (krow*40 + ncol)*2);
                unsigned th[4], tl[4];
                ldsm_x4t(th, smB + 20480 + off);
                ldsm_x4t(tl, smB + 30720 + off);
                unsigned bh0[2] = {th[0], th[1]}, bh1[2] = {th[2], th[3]};
                unsigned bl0[2] = {tl[0], tl[1]}, bl1[2] = {tl[2], tl[3]};
                mma_bf16(o[2*pr2],   pah, bh0);
                mma_bf16(o[2*pr2],   pah, bl0);
                mma_bf16(o[2*pr2],   pal, bh0);
                mma_bf16(o[2*pr2+1], pah, bh1);
                mma_bf16(o[2*pr2+1], pah, bl1);
                mma_bf16(o[2*pr2+1], pal, bh1);
            }
        }
        __syncthreads();
        buf ^= 1;
    }

    float inv0 = 1.f / l0, inv1 = 1.f / l1;
    #pragma unroll
    for (int nt = 0; nt < 4; nt++){
        int row0 = i0 + w*16 + (lane >> 2);
        int col  = nt*8 + (lane & 3)*2;
        if (row0 < NTOK){
            size_t dst = ((size_t)tb*NTOK + row0)*D + h*EH + col;
            bf16 h0,lo0,h1,lo1;
            splitv(o[nt][0]*inv0, h0, lo0); splitv(o[nt][1]*inv0, h1, lo1);
            *(__nv_bfloat162*)(p_att + dst)       = __halves2bfloat162(h0, h1);
            *(__nv_bfloat162*)(p_att + TMD + dst) = __halves2bfloat162(lo0, lo1);
        }
        if (row0 + 8 < NTOK){
            size_t dst = ((size_t)tb*NTOK + row0 + 8)*D + h*EH + col;
            bf16 h2,lo2,h3,lo3;
            splitv(o[nt][2]*inv1, h2, lo2); splitv(o[nt][3]*inv1, h3, lo3);
            *(__nv_bfloat162*)(p_att + dst)       = __halves2bfloat162(h2, h3);
            *(__nv_bfloat162*)(p_att + TMD + dst) = __halves2bfloat162(lo2, lo3);
        }
    }
}

// ---------------- LayerNorm over D=256, plane in/out ----------------
// v = (xH+xL) [- (sH+sL)], out planes
__global__ __launch_bounds__(256) void ln_kernel(const bf16* __restrict__ xH,
                                                 const bf16* __restrict__ xL,
                                                 const bf16* __restrict__ sH,
                                                 const bf16* __restrict__ sL,
                                                 const float* __restrict__ g,
                                                 const float* __restrict__ beta,
                                                 bf16* __restrict__ pH,
                                                 bf16* __restrict__ pL){
    int row = blockIdx.x, d = threadIdx.x;
    size_t i = (size_t)row*D + d;
    float v = __bfloat162float(xH[i]) + __bfloat162float(xL[i]);
    if (sH) v -= __bfloat162float(sH[i]) + __bfloat162float(sL[i]);
    float2 r = blockReduce2(v, v*v);
    float mean = r.x * (1.f/D);
    float var  = r.y * (1.f/D) - mean*mean;
    float o = (v - mean) * rsqrtf(var + EPS) * g[d] + beta[d];
    bf16 hh, ll; splitv(o, hh, ll);
    pH[i] = hh; pL[i] = ll;
}

// ---------------- final: transpose + de-standardize + average scales ------
__global__ __launch_bounds__(256) void final_kernel(float* __restrict__ out){
    __shared__ float t0[32][33], t1[32][33];
    int b = blockIdx.z;
    int p0 = blockIdx.x*32, n0 = blockIdx.y*32;
    int tx = threadIdx.x & 31, ty = threadIdx.x >> 5;
    #pragma unroll
    for (int i = 0; i < 4; i++){
        int n = n0 + ty + i*8, pp = p0 + tx;
        if (n < ENC && pp < DB){
            t0[ty + i*8][tx] = g_out[((size_t)b*NTOK + n)*DB + pp];
            t1[ty + i*8][tx] = g_out[((size_t)(B_ + b)*NTOK + n)*DB + pp];
        }
    }
    __syncthreads();
    #pragma unroll
    for (int i = 0; i < 4; i++){
        int pp = p0 + ty + i*8, n = n0 + tx;
        if (pp < DB && n < ENC){
            float v0 = t0[tx][ty + i*8]*g_std[b*ENC + n]        + g_mean[b*ENC + n];
            float v1 = t1[tx][ty + i*8]*g_std[(B_ + b)*ENC + n] + g_mean[(B_ + b)*ENC + n];
            out[((size_t)b*DB + pp)*ENC + n] = 0.5f*(v0 + v1);
        }
    }
}

// ---------------- host ----------------
static inline int gsz(int nt){ return nt < 444 ? nt : 444; }
static void* sym(const void* s){ void* p; cudaGetSymbolAddress(&p, s); return p; }

extern "C" void kernel_launch(void* const* d_in, const int* in_sizes, int n_in,
                              void* d_out, int out_size){
    const float* mbx  = (const float*)d_in[0];
    const float* mbxm = (const float*)d_in[1];
    const float* embW = (const float*)d_in[4];
    const float* embB = (const float*)d_in[5];
    const float* Wq = (const float*)d_in[6];
    const float* Wk = (const float*)d_in[7];
    const float* Wv = (const float*)d_in[8];
    const float* Wo = (const float*)d_in[9];
    const float* W3 = (const float*)d_in[10];
    const float* W4 = (const float*)d_in[11];
    const float* bq = (const float*)d_in[12];
    const float* bk = (const float*)d_in[13];
    const float* bv = (const float*)d_in[14];
    const float* bo = (const float*)d_in[15];
    const float* b3 = (const float*)d_in[16];
    const float* b4 = (const float*)d_in[17];
    const float* W1 = (const float*)d_in[18];
    const float* b1 = (const float*)d_in[19];
    const float* W2 = (const float*)d_in[20];
    const float* b2 = (const float*)d_in[21];
    const float* W5 = (const float*)d_in[22];
    const float* b5 = (const float*)d_in[23];
    const float* W6 = (const float*)d_in[24];
    const float* b6 = (const float*)d_in[25];
    const float* ln1g = (const float*)d_in[26];
    const float* ln1b = (const float*)d_in[27];
    const float* ln2g = (const float*)d_in[28];
    const float* ln2b = (const float*)d_in[29];
    float* out = (float*)d_out;

    float* outF = (float*)sym(g_out);

    bf16* xinP = (bf16*)sym(p_xin);
    bf16* hP   = (bf16*)sym(p_h);
    bf16* qkvP = (bf16*)sym(p_qkv);
    bf16* attP = (bf16*)sym(p_att);
    bf16* xlnP = (bf16*)sym(p_xln);
    bf16* y1P  = (bf16*)sym(p_y1);
    bf16* xsP  = (bf16*)sym(p_xs);
    bf16* xattP = (bf16*)sym(p_xatt);
    bf16* yP   = (bf16*)sym(p_y);
    bf16* hhP  = (bf16*)sym(p_hh);
    bf16* embWP = (bf16*)sym(p_embW);
    bf16* WqP = (bf16*)sym(p_Wq); bf16* WkP = (bf16*)sym(p_Wk);
    bf16* WvP = (bf16*)sym(p_Wv); bf16* WoP = (bf16*)sym(p_Wo);
    bf16* W3P = (bf16*)sym(p_W3); bf16* W4P = (bf16*)sym(p_W4);
    bf16* W1P = (bf16*)sym(p_W1); bf16* W2P = (bf16*)sym(p_W2);
    bf16* W5P = (bf16*)sym(p_W5); bf16* W6P = (bf16*)sym(p_W6);

    const size_t EWN = (size_t)256*SEQP;
    const size_t WDD = (size_t)LAYERS*D*D;
    const size_t W1N = (size_t)LAYERS*DFF*D;
    const size_t W5N = (size_t)LAYERS*DB*2*D;
    const size_t Y1N = (size_t)TM*DFF;

    cudaFuncSetAttribute(mma_gemm<0>, cudaFuncAttributeMaxDynamicSharedMemorySize, 61440);
    cudaFuncSetAttribute(mma_gemm<1>, cudaFuncAttributeMaxDynamicSharedMemorySize, 61440);
    cudaFuncSetAttribute(mma_gemm<2>, cudaFuncAttributeMaxDynamicSharedMemorySize, 61440);
    cudaFuncSetAttribute(mma_gemm2<0>, cudaFuncAttributeMaxDynamicSharedMemorySize, 61440);
    cudaFuncSetAttribute(mma_gemm2<1>, cudaFuncAttributeMaxDynamicSharedMemorySize, 61440);

    // weight splits (one batched launch + embed pad)
    {
        WSArgs ws;
        const float* ss[10] = {Wq, Wk, Wv, Wo, W3, W4, W1, W2, W5, W6};
        bf16* hh[10] = {WqP, WkP, WvP, WoP, W3P, W4P, W1P, W2P, W5P, W6P};
        size_t nn[10] = {WDD, WDD, WDD, WDD, WDD, WDD, W1N, W1N, W5N, W5N};
        for (int i = 0; i < 10; i++){
            ws.s[i] = ss[i]; ws.h[i] = hh[i]; ws.l[i] = hh[i] + nn[i]; ws.n[i] = (int)nn[i];
        }
        wsplit_all<<<dim3(288, 10), 256>>>(ws);
        wsplit_pad<<<(unsigned)((EWN + 255)/256), 256>>>(embW, embWP, embWP + EWN, 256, SEQ, SEQP);
    }

    const int tm = 109;   // ceil(13856/128)
    const int tm64 = 217; // ceil(13856/64)

    stats_kernel<<<dim3((ENC + 255)/256, B_, TS), 256>>>(mbx);
    xin_kernel<<<dim3((SEQP + 31)/32, (NTOK + 31)/32, TS*B_), 256>>>(mbx, mbxm);

    {   // embed -> h planes
        GemmArgs a = {};
        a.aH[0] = xinP; a.aL[0] = xinP + TXN;
        a.wH[0] = embWP; a.wL[0] = embWP + EWN;
        a.bias[0] = embB;
        a.cH[0] = hP; a.cL[0] = hP + TMD;
        mma_gemm<0><<<gsz(tm*4), 256, 61440>>>(a, TM, D, SEQP, 4, tm*4, tm*4);
    }

    for (int l = 0; l < LAYERS; l++){
        {   // QKV -> planes
            GemmArgs a = {};
            for (int z = 0; z < 3; z++){
                a.aH[z] = hP; a.aL[z] = hP + TMD;
                a.cH[z] = qkvP + (size_t)z*TMD;
                a.cL[z] = qkvP + 3*TMD + (size_t)z*TMD;
            }
            a.wH[0] = WqP + (size_t)l*D*D; a.wL[0] = WqP + WDD + (size_t)l*D*D;
            a.wH[1] = WkP + (size_t)l*D*D; a.wL[1] = WkP + WDD + (size_t)l*D*D;
            a.wH[2] = WvP + (size_t)l*D*D; a.wL[2] = WvP + WDD + (size_t)l*D*D;
            a.bias[0] = bq + l*D; a.bias[1] = bk + l*D; a.bias[2] = bv + l*D;
            mma_gemm<0><<<gsz(tm*4*3), 256, 61440>>>(a, TM, D, D, 4, tm*4, tm*4*3);
        }

        flash_attn<<<dim3(7, TS*B_*NH), 256>>>();

        {   // Wo -> xatt planes
            GemmArgs a = {};
            a.aH[0] = attP; a.aL[0] = attP + TMD;
            a.wH[0] = WoP + (size_t)l*D*D; a.wL[0] = WoP + WDD + (size_t)l*D*D;
            a.bias[0] = bo + l*D;
            a.cH[0] = xattP; a.cL[0] = xattP + TMD;
            mma_gemm<0><<<gsz(tm*4), 256, 61440>>>(a, TM, D, D, 4, tm*4, tm*4);
        }

        // LN1: ln(h - xatt) -> xln planes
        ln_kernel<<<TM, 256>>>(hP, hP + TMD, xattP, xattP + TMD,
                               ln1g + l*D, ln1b + l*D, xlnP, xlnP + TMD);

        {   // W1 + GELU -> y1 planes
            GemmArgs a = {};
            a.aH[0] = xlnP; a.aL[0] = xlnP + TMD;
            a.wH[0] = W1P + (size_t)l*DFF*D; a.wL[0] = W1P + W1N + (size_t)l*DFF*D;
            a.bias[0] = b1 + l*DFF;
            a.cH[0] = y1P; a.cL[0] = y1P + Y1N;
            mma_gemm<1><<<gsz(tm*8), 256, 61440>>>(a, TM, DFF, D, 8, tm*8, tm*8);
        }
        {   // W2 -> y planes + xs=(xln-y) planes (sub fused, xln from planes)
            GemmArgs a = {};
            a.aH[0] = y1P; a.aL[0] = y1P + Y1N;
            a.wH[0] = W2P + (size_t)l*D*DFF; a.wL[0] = W2P + W1N + (size_t)l*D*DFF;
            a.bias[0] = b2 + l*D;
            a.cH[0] = yP; a.cL[0] = yP + TMD;
            a.xsH[0] = xlnP; a.xsL[0] = xlnP + TMD;
            a.c2H[0] = xsP; a.c2L[0] = xsP + TMD;
            mma_gemm<2><<<gsz(tm*4), 256, 61440>>>(a, TM, D, DFF, 4, tm*4, tm*4);
        }

        {   // fused W3/W4 -> hh planes = sigmoid(.)*(.)
            Gemm2Args a = {};
            a.a0H = xsP; a.a0L = xsP + TMD; a.a1H = xsP; a.a1L = xsP + TMD;
            a.kSplit = 1 << 30; a.aStride = D;
            a.w1H = W3P + (size_t)l*D*D; a.w1L = W3P + WDD + (size_t)l*D*D;
            a.w2H = W4P + (size_t)l*D*D; a.w2L = W4P + WDD + (size_t)l*D*D;
            a.b1 = b3 + l*D; a.b2 = b4 + l*D;
            a.cH = hhP; a.cL = hhP + TMD;
            mma_gemm2<0><<<gsz(tm64*4), 256, 61440>>>(a, TM, D, D, 4, tm64*4);
        }

        {   // fused W5/W6 over cat(xatt,y) -> g_out (with layer subtract)
            Gemm2Args a = {};
            a.a0H = xattP; a.a0L = xattP + TMD;
            a.a1H = yP;    a.a1L = yP + TMD;
            a.kSplit = D; a.aStride = D;
            a.w1H = W5P + (size_t)l*DB*2*D; a.w1L = W5P + W5N + (size_t)l*DB*2*D;
            a.w2H = W6P + (size_t)l*DB*2*D; a.w2L = W6P + W5N + (size_t)l*DB*2*D;
            a.b1 = b5 + l*DB; a.b2 = b6 + l*DB;
            a.Cout = outF; a.sub = l;
            mma_gemm2<1><<<gsz(tm64*12), 256, 61440>>>(a, TM, DB, 2*D, 12, tm64*12);
        }

        // LN2: ln(hh) -> h planes
        ln_kernel<<<TM, 256>>>(hhP, hhP + TMD, (const bf16*)nullptr, (const bf16*)nullptr,
                               ln2g + l*D, ln2b + l*D, hP, hP + TMD);
    }

    final_kernel<<<dim3((DB + 31)/32, (ENC + 31)/32, B_), 256>>>(out);
}

// round 14
// speedup vs baseline: 1.2779x; 1.0328x over previous
#include <cuda_runtime.h>
#include <cuda_bf16.h>
#include <math.h>

#define B_    8
#define TS    2
#define SEQ   720
#define SEQP  736
#define ENC   862
#define MARKD 4
#define NTOK  866
#define D     256
#define NH    8
#define EH    32
#define DFF   512
#define DB    720
#define LAYERS 2
#define EPS   1e-5f
#define MROWS (B_*NTOK)        // 6928 per scale
#define TM    (TS*MROWS)       // 13856 combined
#define TMD   ((size_t)TM*D)
#define TXN   ((size_t)TM*SEQP)

typedef __nv_bfloat16 bf16;

// ---------------- fp32 scratch ----------------
__device__ float g_mean[TS*B_*ENC], g_std[TS*B_*ENC];
__device__ float g_out[(size_t)TM*DB];

// ---------------- bf16 hi/lo planes (lo at +n) ----------------
__device__ __align__(16) bf16 p_xin[2*TXN];
__device__ __align__(16) bf16 p_h  [2*TMD];
__device__ __align__(16) bf16 p_qkv[2*3*TMD];
__device__ __align__(16) bf16 p_att[2*TMD];
__device__ __align__(16) bf16 p_xln[2*TMD];
__device__ __align__(16) bf16 p_y1 [2*(size_t)TM*DFF];
__device__ __align__(16) bf16 p_xs [2*TMD];
__device__ __align__(16) bf16 p_xatt[2*TMD];
__device__ __align__(16) bf16 p_y  [2*TMD];
__device__ __align__(16) bf16 p_hh [2*TMD];
// weights
__device__ __align__(16) bf16 p_embW[2*256*SEQP];
__device__ __align__(16) bf16 p_Wq[2*LAYERS*D*D], p_Wk[2*LAYERS*D*D], p_Wv[2*LAYERS*D*D];
__device__ __align__(16) bf16 p_Wo[2*LAYERS*D*D], p_W3[2*LAYERS*D*D], p_W4[2*LAYERS*D*D];
__device__ __align__(16) bf16 p_W1[2*LAYERS*DFF*D], p_W2[2*LAYERS*D*DFF];
__device__ __align__(16) bf16 p_W5[2*LAYERS*DB*2*D], p_W6[2*LAYERS*DB*2*D];

// ---------------- helpers ----------------
__device__ __forceinline__ void splitv(float x, bf16& h, bf16& l){
    h = __float2bfloat16(x);
    l = __float2bfloat16(x - __bfloat162float(h));
}
__device__ __forceinline__ unsigned pack2u(bf16 a, bf16 b){
    __nv_bfloat162 t = __halves2bfloat162(a, b);
    return *(unsigned*)&t;
}
__device__ __forceinline__ void mma_bf16(float c[4], const unsigned a[4], const unsigned b[2]){
    asm volatile("mma.sync.aligned.m16n8k16.row.col.f32.bf16.bf16.f32 "
                 "{%0,%1,%2,%3}, {%4,%5,%6,%7}, {%8,%9}, {%0,%1,%2,%3};\n"
                 : "+f"(c[0]), "+f"(c[1]), "+f"(c[2]), "+f"(c[3])
                 : "r"(a[0]), "r"(a[1]), "r"(a[2]), "r"(a[3]),
                   "r"(b[0]), "r"(b[1]));
}
__device__ __forceinline__ void ldsm_x4(unsigned r[4], unsigned addr){
    asm volatile("ldmatrix.sync.aligned.m8n8.x4.shared.b16 {%0,%1,%2,%3}, [%4];\n"
                 : "=r"(r[0]), "=r"(r[1]), "=r"(r[2]), "=r"(r[3]) : "r"(addr));
}
__device__ __forceinline__ void ldsm_x4t(unsigned r[4], unsigned addr){
    asm volatile("ldmatrix.sync.aligned.m8n8.x4.trans.shared.b16 {%0,%1,%2,%3}, [%4];\n"
                 : "=r"(r[0]), "=r"(r[1]), "=r"(r[2]), "=r"(r[3]) : "r"(addr));
}
__device__ __forceinline__ void cp16(unsigned dst, const void* src, bool p){
    int sz = p ? 16 : 0;
    asm volatile("cp.async.cg.shared.global [%0], [%1], 16, %2;\n"
                 :: "r"(dst), "l"(src), "r"(sz));
}
__device__ __forceinline__ void cpcommit(){ asm volatile("cp.async.commit_group;\n"); }
template<int N> __device__ __forceinline__ void cpwait(){
    asm volatile("cp.async.wait_group %0;\n" :: "n"(N));
}
__device__ __forceinline__ float gelu_f(float x){
    return 0.5f*x*(1.f + erff(x*0.70710678118654752f));
}
__device__ __forceinline__ float sigmoid_f(float x){
    return 1.f/(1.f + expf(-x));
}

// ---------------- weight split (batched) ----------------
struct WSArgs { const float* s[10]; bf16* h[10]; bf16* l[10]; int n[10]; };
__global__ void wsplit_all(WSArgs w){
    int z = blockIdx.y;
    int n = w.n[z];
    const float* src = w.s[z];
    bf16* hh = w.h[z]; bf16* ll = w.l[z];
    for (int i = blockIdx.x*blockDim.x + threadIdx.x; i < n; i += gridDim.x*blockDim.x)
        splitv(src[i], hh[i], ll[i]);
}
__global__ void wsplit_pad(const float* __restrict__ s, bf16* __restrict__ h,
                           bf16* __restrict__ l, int rows, int K, int Kp){
    size_t i = (size_t)blockIdx.x*blockDim.x + threadIdx.x;
    size_t total = (size_t)rows*Kp;
    if (i >= total) return;
    int c = (int)(i % Kp); int r = (int)(i / Kp);
    float v = (c < K) ? s[(size_t)r*K + c] : 0.f;
    splitv(v, h[i], l[i]);
}

// ---------------- input standardization (both scales) ----------------
__global__ void stats_kernel(const float* __restrict__ mbx){
    int t = blockIdx.z, b = blockIdx.y;
    int n = blockIdx.x * blockDim.x + threadIdx.x;
    if (n >= ENC) return;
    const float* base = mbx + ((size_t)(b*TS + t)*SEQ)*ENC + n;
    float s = 0.f, ss = 0.f;
    for (int i = 0; i < SEQ; i++){
        float v = base[(size_t)i*ENC];
        s += v; ss += v*v;
    }
    float m = s * (1.f/SEQ);
    float var = ss * (1.f/SEQ) - m*m;
    g_mean[(t*B_ + b)*ENC + n] = m;
    g_std [(t*B_ + b)*ENC + n] = sqrtf(var + EPS);
}

// transposed tiled build of xin planes for both scales
__global__ __launch_bounds__(256) void xin_kernel(const float* __restrict__ mbx,
                                                  const float* __restrict__ mbxm){
    __shared__ float tile[32][33];
    const int zb = blockIdx.z;            // t*B_ + b
    const int t = zb / B_, b = zb % B_;
    const int s0 = blockIdx.x*32, n0 = blockIdx.y*32;
    const int tx = threadIdx.x & 31, ty = threadIdx.x >> 5;
    #pragma unroll
    for (int i = 0; i < 4; i++){
        int s = s0 + ty + i*8, n = n0 + tx;
        float v = 0.f;
        if (s < SEQ && n < NTOK){
            if (n < ENC){
                v = mbx[((size_t)(b*TS + t)*SEQ + s)*ENC + n];
                v = (v - g_mean[zb*ENC + n]) / g_std[zb*ENC + n];
            } else {
                v = mbxm[((size_t)(b*TS + t)*SEQ + s)*MARKD + (n - ENC)];
            }
        }
        tile[ty + i*8][tx] = v;
    }
    __syncthreads();
    #pragma unroll
    for (int i = 0; i < 4; i++){
        int n = n0 + ty + i*8, s = s0 + tx;
        if (n < NTOK && s < SEQP){
            size_t idx = ((size_t)zb*NTOK + n)*SEQP + s;
            splitv(tile[tx][ty + i*8], p_xin[idx], p_xin[TXN + idx]);
        }
    }
}

// =============== MMA GEMM: planes = A @ W^T + bias (bf16 planes) ==========
// ACT 0: plain; 1: gelu; 2: also emit (xsub - y) planes (xsub from planes)
struct GemmArgs {
    const bf16 *aH[3], *aL[3], *wH[3], *wL[3];
    const float* bias[3];
    bf16 *cH[3], *cL[3];
    const bf16 *xsH[3], *xsL[3];
    bf16 *c2H[3], *c2L[3];
};

template<int ACT>
__global__ __launch_bounds__(256, 3)
void mma_gemm(GemmArgs p, int M, int N, int K, int tilesN, int tpz, int nTiles){
    extern __shared__ __align__(16) char smraw[];
    bf16* sAh = (bf16*)smraw;            // [2][128][40]
    bf16* sAl = sAh + 2*128*40;
    bf16* sBh = sAl + 2*128*40;          // [2][64][40]
    bf16* sBl = sBh + 2*64*40;
    const unsigned aHiB = (unsigned)__cvta_generic_to_shared(sAh);
    const unsigned aLoB = (unsigned)__cvta_generic_to_shared(sAl);
    const unsigned bHiB = (unsigned)__cvta_generic_to_shared(sBh);
    const unsigned bLoB = (unsigned)__cvta_generic_to_shared(sBl);

    const int tid = threadIdx.x;
    const int lane = tid & 31, w = tid >> 5;
    const int wm = (w >> 1)*32, wn = (w & 1)*32;
    const int t4 = lane >> 3, lr = lane & 7;
    const int ldr = tid >> 2, ldc = (tid & 3)*8;

    for (int t = blockIdx.x; t < nTiles; t += gridDim.x){
        const int z  = t / tpz;
        const int rr = t - z*tpz;
        const int bm = (rr / tilesN)*128, bn = (rr % tilesN)*64;
        const bf16* __restrict__ aHp = p.aH[z];
        const bf16* __restrict__ aLp = p.aL[z];
        const bf16* __restrict__ wHp = p.wH[z];
        const bf16* __restrict__ wLp = p.wL[z];
        const float* __restrict__ bias = p.bias[z];
        bf16* cHp = p.cH[z];
        bf16* cLp = p.cL[z];

        float acc[2][4][4];
        #pragma unroll
        for (int i = 0; i < 2; i++)
            #pragma unroll
            for (int j = 0; j < 4; j++)
                #pragma unroll
                for (int q = 0; q < 4; q++) acc[i][j][q] = 0.f;

        auto loadst = [&](int s, int k0){
            #pragma unroll
            for (int rep = 0; rep < 2; rep++){
                int r = ldr + rep*64;
                int gm = bm + r;
                bool pr = gm < M;
                size_t so = (size_t)(pr ? gm : 0)*K + k0 + ldc;
                unsigned doff = (unsigned)(((s*128 + r)*40 + ldc)*2);
                cp16(aHiB + doff, aHp + so, pr);
                cp16(aLoB + doff, aLp + so, pr);
            }
            {
                int gn = bn + ldr;
                bool pn = gn < N;
                size_t so = (size_t)(pn ? gn : 0)*K + k0 + ldc;
                unsigned doff = (unsigned)(((s*64 + ldr)*40 + ldc)*2);
                cp16(bHiB + doff, wHp + so, pn);
                cp16(bLoB + doff, wLp + so, pn);
            }
            cpcommit();
        };

        loadst(0, 0);
        int buf = 0;
        const int KT = K >> 5;
        for (int kt = 0; kt < KT; kt++){
            if (kt + 1 < KT){ loadst(buf ^ 1, (kt+1)*32); cpwait<1>(); }
            else cpwait<0>();
            __syncthreads();

            #pragma unroll
            for (int kh = 0; kh < 32; kh += 16){
                unsigned ah[2][4], al[2][4], bh[4][2], bl[4][2];
                #pragma unroll
                for (int mt = 0; mt < 2; mt++){
                    int arow = wm + mt*16 + (t4 & 1)*8 + lr;
                    unsigned off = (unsigned)((((buf*128) + arow)*40 + kh + (t4 >> 1)*8)*2);
                    ldsm_x4(ah[mt], aHiB + off);
                    ldsm_x4(al[mt], aLoB + off);
                }
                #pragma unroll
                for (int pr2 = 0; pr2 < 2; pr2++){
                    int brow = wn + pr2*16 + (t4 >> 1)*8 + lr;
                    unsigned off = (unsigned)((((buf*64) + brow)*40 + kh + (t4 & 1)*8)*2);
                    unsigned th[4], tl[4];
                    ldsm_x4(th, bHiB + off);
                    ldsm_x4(tl, bLoB + off);
                    bh[pr2*2][0] = th[0]; bh[pr2*2][1] = th[1];
                    bh[pr2*2+1][0] = th[2]; bh[pr2*2+1][1] = th[3];
                    bl[pr2*2][0] = tl[0]; bl[pr2*2][1] = tl[1];
                    bl[pr2*2+1][0] = tl[2]; bl[pr2*2+1][1] = tl[3];
                }
                #pragma unroll
                for (int mt = 0; mt < 2; mt++)
                    #pragma unroll
                    for (int nt = 0; nt < 4; nt++){
                        mma_bf16(acc[mt][nt], ah[mt], bh[nt]);
                        mma_bf16(acc[mt][nt], ah[mt], bl[nt]);
                        mma_bf16(acc[mt][nt], al[mt], bh[nt]);
                    }
            }
            __syncthreads();
            buf ^= 1;
        }

        #pragma unroll
        for (int mt = 0; mt < 2; mt++)
            #pragma unroll
            for (int nt = 0; nt < 4; nt++){
                int row0 = bm + wm + mt*16 + (lane >> 2);
                int col  = bn + wn + nt*8 + (lane & 3)*2;
                if (col >= N) continue;
                float b0 = bias[col], b1 = bias[col + 1];
                float v0 = acc[mt][nt][0] + b0, v1 = acc[mt][nt][1] + b1;
                float v2 = acc[mt][nt][2] + b0, v3 = acc[mt][nt][3] + b1;
                if (ACT == 1){
                    v0 = gelu_f(v0); v1 = gelu_f(v1);
                    v2 = gelu_f(v2); v3 = gelu_f(v3);
                }
                if (row0 < M){
                    size_t ix = (size_t)row0*N + col;
                    bf16 h0,l0,h1,l1; splitv(v0,h0,l0); splitv(v1,h1,l1);
                    *(__nv_bfloat162*)(cHp + ix) = __halves2bfloat162(h0,h1);
                    *(__nv_bfloat162*)(cLp + ix) = __halves2bfloat162(l0,l1);
                    if (ACT == 2){
                        float x0 = __bfloat162float(p.xsH[z][ix]) + __bfloat162float(p.xsL[z][ix]);
                        float x1 = __bfloat162float(p.xsH[z][ix+1]) + __bfloat162float(p.xsL[z][ix+1]);
                        bf16 s0,t0,s1,t1; splitv(x0 - v0,s0,t0); splitv(x1 - v1,s1,t1);
                        *(__nv_bfloat162*)(p.c2H[z] + ix) = __halves2bfloat162(s0,s1);
                        *(__nv_bfloat162*)(p.c2L[z] + ix) = __halves2bfloat162(t0,t1);
                    }
                }
                if (row0 + 8 < M){
                    size_t ix = (size_t)(row0+8)*N + col;
                    bf16 h2,l2,h3,l3; splitv(v2,h2,l2); splitv(v3,h3,l3);
                    *(__nv_bfloat162*)(cHp + ix) = __halves2bfloat162(h2,h3);
                    *(__nv_bfloat162*)(cLp + ix) = __halves2bfloat162(l2,l3);
                    if (ACT == 2){
                        float x2 = __bfloat162float(p.xsH[z][ix]) + __bfloat162float(p.xsL[z][ix]);
                        float x3 = __bfloat162float(p.xsH[z][ix+1]) + __bfloat162float(p.xsL[z][ix+1]);
                        bf16 s2,t2,s3,t3; splitv(x2 - v2,s2,t2); splitv(x3 - v3,s3,t3);
                        *(__nv_bfloat162*)(p.c2H[z] + ix) = __halves2bfloat162(s2,s3);
                        *(__nv_bfloat162*)(p.c2L[z] + ix) = __halves2bfloat162(t2,t3);
                    }
                }
            }
    }
}

// =============== fused dual GEMM (BM=64): o = sig(A W1^T+b1)*(A W2^T+b2) ==
// MODE 0: write o as bf16 planes (cH/cL); MODE 1: fp32 Cout = sub ? o-C : o
struct Gemm2Args {
    const bf16 *a0H, *a0L, *a1H, *a1L;
    int kSplit, aStride;
    const bf16 *w1H, *w1L, *w2H, *w2L;
    const float *b1, *b2;
    float* Cout;
    bf16 *cH, *cL;
    int sub;
};

template<int MODE>
__global__ __launch_bounds__(256, 3)
void mma_gemm2(Gemm2Args p, int M, int N, int K, int tilesN, int nTiles){
    extern __shared__ __align__(16) char smraw[];
    bf16* sm = (bf16*)smraw;
    const unsigned smB = (unsigned)__cvta_generic_to_shared(sm);
    const int tid = threadIdx.x;
    const int lane = tid & 31, w = tid >> 5;
    const int wm = (w >> 1)*16, wn = (w & 1)*32;
    const int t4 = lane >> 3, lr = lane & 7;
    const int ldr = tid >> 2, ldc = (tid & 3)*8;

    for (int t = blockIdx.x; t < nTiles; t += gridDim.x){
        const int bm = (t / tilesN)*64, bn = (t % tilesN)*64;

        float acc[2][4][4];
        #pragma unroll
        for (int g = 0; g < 2; g++)
            #pragma unroll
            for (int j = 0; j < 4; j++)
                #pragma unroll
                for (int q = 0; q < 4; q++) acc[g][j][q] = 0.f;

        auto loadst = [&](int s, int k0){
            const bf16* aH = (k0 < p.kSplit) ? p.a0H : p.a1H;
            const bf16* aL = (k0 < p.kSplit) ? p.a0L : p.a1L;
            int kk = (k0 < p.kSplit) ? k0 : k0 - p.kSplit;
            int gm = bm + ldr;
            bool pr = gm < M;
            size_t soA = (size_t)(pr ? gm : 0)*p.aStride + kk + ldc;
            unsigned dA = (unsigned)((s*2*2560 + ldr*40 + ldc)*2);
            cp16(smB + dA,           aH + soA, pr);
            cp16(smB + dA + 2560*2,  aL + soA, pr);
            int gn = bn + ldr;
            bool pn = gn < N;
            size_t soB = (size_t)(pn ? gn : 0)*K + k0 + ldc;
            unsigned dB = (unsigned)((10240 + s*4*2560 + ldr*40 + ldc)*2);
            cp16(smB + dB,             p.w1H + soB, pn);
            cp16(smB + dB + 2560*2,    p.w1L + soB, pn);
            cp16(smB + dB + 2*2560*2,  p.w2H + soB, pn);
            cp16(smB + dB + 3*2560*2,  p.w2L + soB, pn);
            cpcommit();
        };

        loadst(0, 0);
        int buf = 0;
        const int KT = K >> 5;
        for (int kt = 0; kt < KT; kt++){
            if (kt + 1 < KT){ loadst(buf ^ 1, (kt+1)*32); cpwait<1>(); }
            else cpwait<0>();
            __syncthreads();

            #pragma unroll
            for (int kh = 0; kh < 32; kh += 16){
                unsigned ah[4], al[4];
                {
                    int arow = wm + (t4 & 1)*8 + lr;
                    unsigned off = (unsigned)((buf*2*2560 + arow*40 + kh + (t4 >> 1)*8)*2);
                    ldsm_x4(ah, smB + off);
                    ldsm_x4(al, smB + off + 2560*2);
                }
                #pragma unroll
                for (int g = 0; g < 2; g++){
                    #pragma unroll
                    for (int pr2 = 0; pr2 < 2; pr2++){
                        int brow = wn + pr2*16 + (t4 >> 1)*8 + lr;
                        unsigned off = (unsigned)((10240 + buf*4*2560 + g*2*2560
                                                   + brow*40 + kh + (t4 & 1)*8)*2);
                        unsigned th[4], tl[4];
                        ldsm_x4(th, smB + off);
                        ldsm_x4(tl, smB + off + 2560*2);
                        unsigned bh0[2] = {th[0], th[1]}, bh1[2] = {th[2], th[3]};
                        unsigned bl0[2] = {tl[0], tl[1]}, bl1[2] = {tl[2], tl[3]};
                        mma_bf16(acc[g][2*pr2],   ah, bh0);
                        mma_bf16(acc[g][2*pr2],   ah, bl0);
                        mma_bf16(acc[g][2*pr2],   al, bh0);
                        mma_bf16(acc[g][2*pr2+1], ah, bh1);
                        mma_bf16(acc[g][2*pr2+1], ah, bl1);
                        mma_bf16(acc[g][2*pr2+1], al, bh1);
                    }
                }
            }
            __syncthreads();
            buf ^= 1;
        }

        #pragma unroll
        for (int nt = 0; nt < 4; nt++){
            int row0 = bm + wm + (lane >> 2);
            int col  = bn + wn + nt*8 + (lane & 3)*2;
            if (col >= N) continue;
            float b10 = p.b1[col], b11 = p.b1[col + 1];
            float b20 = p.b2[col], b21 = p.b2[col + 1];
            float o0 = sigmoid_f(acc[0][nt][0] + b10)*(acc[1][nt][0] + b20);
            float o1 = sigmoid_f(acc[0][nt][1] + b11)*(acc[1][nt][1] + b21);
            float o2 = sigmoid_f(acc[0][nt][2] + b10)*(acc[1][nt][2] + b20);
            float o3 = sigmoid_f(acc[0][nt][3] + b11)*(acc[1][nt][3] + b21);
            if (row0 < M){
                size_t ix = (size_t)row0*N + col;
                if (MODE == 0){
                    bf16 h0,l0,h1,l1; splitv(o0,h0,l0); splitv(o1,h1,l1);
                    *(__nv_bfloat162*)(p.cH + ix) = __halves2bfloat162(h0,h1);
                    *(__nv_bfloat162*)(p.cL + ix) = __halves2bfloat162(l0,l1);
                } else if (p.sub){
                    p.Cout[ix]     = o0 - p.Cout[ix];
                    p.Cout[ix + 1] = o1 - p.Cout[ix + 1];
                } else {
                    p.Cout[ix] = o0; p.Cout[ix + 1] = o1;
                }
            }
            if (row0 + 8 < M){
                size_t ix = (size_t)(row0+8)*N + col;
                if (MODE == 0){
                    bf16 h2,l2,h3,l3; splitv(o2,h2,l2); splitv(o3,h3,l3);
                    *(__nv_bfloat162*)(p.cH + ix) = __halves2bfloat162(h2,h3);
                    *(__nv_bfloat162*)(p.cL + ix) = __halves2bfloat162(l2,l3);
                } else if (p.sub){
                    p.Cout[ix]     = o2 - p.Cout[ix];
                    p.Cout[ix + 1] = o3 - p.Cout[ix + 1];
                } else {
                    p.Cout[ix] = o2; p.Cout[ix + 1] = o3;
                }
            }
        }
    }
}

// =============== flash attention (both scales via batch index) ============
__global__ __launch_bounds__(256) void flash_attn(){
    __shared__ __align__(16) bf16 sm[20480];   // 40 KB
    const unsigned smB = (unsigned)__cvta_generic_to_shared(sm);
    const int bh = blockIdx.y;
    const int tb = bh >> 3, h = bh & 7;
    const int i0 = blockIdx.x * 128;
    const bf16* qH = p_qkv +            (size_t)tb*NTOK*D + h*EH;
    const bf16* qL = qH + 3*TMD;
    const bf16* kH = p_qkv +    TMD +   (size_t)tb*NTOK*D + h*EH;
    const bf16* kL = kH + 3*TMD;
    const bf16* vH = p_qkv +  2*TMD +   (size_t)tb*NTOK*D + h*EH;
    const bf16* vL = vH + 3*TMD;

    const int tid = threadIdx.x, lane = tid & 31, w = tid >> 5;
    const int t4 = lane >> 3, lr = lane & 7;

    {
        int row = tid >> 1, c = (tid & 1)*16;
        int gi = i0 + row;
        bool ok = gi < NTOK;
        size_t so = (size_t)(ok ? gi : 0)*D + c;
        const float4 z4 = make_float4(0.f,0.f,0.f,0.f);
        float4 f0 = ok ? *(const float4*)(qH + so)     : z4;
        float4 f1 = ok ? *(const float4*)(qH + so + 8) : z4;
        *(float4*)&sm[row*40 + c]     = f0;
        *(float4*)&sm[row*40 + c + 8] = f1;
        f0 = ok ? *(const float4*)(qL + so)     : z4;
        f1 = ok ? *(const float4*)(qL + so + 8) : z4;
        *(float4*)&sm[5120 + row*40 + c]     = f0;
        *(float4*)&sm[5120 + row*40 + c + 8] = f1;
    }
    __syncthreads();
    unsigned qh[2][4], ql[2][4];
    #pragma unroll
    for (int kc = 0; kc < 2; kc++){
        int row = w*16 + (t4 & 1)*8 + lr;
        int col = kc*16 + (t4 >> 1)*8;
        ldsm_x4(qh[kc], smB + (unsigned)((row*40 + col)*2));
        ldsm_x4(ql[kc], smB + (unsigned)((5120 + row*40 + col)*2));
    }
    __syncthreads();

    const int ldr = tid >> 2, ldc = (tid & 3)*8;
    auto loadkv = [&](int s, int j0){
        int gj = j0 + ldr;
        bool ok = gj < NTOK;
        size_t so = (size_t)(ok ? gj : 0)*D + ldc;
        unsigned doff = (unsigned)(s*5120 + (ldr*40 + ldc)*2);
        cp16(smB + doff,         kH + so, ok);
        cp16(smB + 10240 + doff, kL + so, ok);
        cp16(smB + 20480 + doff, vH + so, ok);
        cp16(smB + 30720 + doff, vL + so, ok);
        cpcommit();
    };

    float o[4][4];
    #pragma unroll
    for (int j = 0; j < 4; j++)
        #pragma unroll
        for (int q = 0; q < 4; q++) o[j][q] = 0.f;
    float m0 = -1e30f, m1 = -1e30f, l0 = 0.f, l1 = 0.f;
    const float scale = 0.17677669529663688f;

    loadkv(0, 0);
    int buf = 0;
    const int NJT = 14;
    for (int jt = 0; jt < NJT; jt++){
        const int j0 = jt*64;
        if (jt + 1 < NJT){ loadkv(buf ^ 1, (jt+1)*64); cpwait<1>(); }
        else cpwait<0>();
        __syncthreads();

        float s[8][4];
        #pragma unroll
        for (int nt = 0; nt < 8; nt++)
            #pragma unroll
            for (int q = 0; q < 4; q++) s[nt][q] = 0.f;

        #pragma unroll
        for (int kc = 0; kc < 2; kc++){
            #pragma unroll
            for (int pr = 0; pr < 4; pr++){
                int brow = pr*16 + (t4 >> 1)*8 + lr;
                int col  = kc*16 + (t4 & 1)*8;
                unsigned off = (unsigned)(buf*5120 + (brow*40 + col)*2);
                unsigned th[4], tl[4];
                ldsm_x4(th, smB + off);
                ldsm_x4(tl, smB + 10240 + off);
                unsigned bh0[2] = {th[0], th[1]}, bh1[2] = {th[2], th[3]};
                unsigned bl0[2] = {tl[0], tl[1]}, bl1[2] = {tl[2], tl[3]};
                mma_bf16(s[2*pr],   qh[kc], bh0);
                mma_bf16(s[2*pr],   qh[kc], bl0);
                mma_bf16(s[2*pr],   ql[kc], bh0);
                mma_bf16(s[2*pr+1], qh[kc], bh1);
                mma_bf16(s[2*pr+1], qh[kc], bl1);
                mma_bf16(s[2*pr+1], ql[kc], bh1);
            }
        }

        #pragma unroll
        for (int nt = 0; nt < 8; nt++)
            #pragma unroll
            for (int q = 0; q < 4; q++) s[nt][q] *= scale;
        if (j0 + 64 > NTOK){
            #pragma unroll
            for (int nt = 0; nt < 8; nt++){
                int c0 = j0 + nt*8 + (lane & 3)*2;
                if (c0     >= NTOK){ s[nt][0] = -1e30f; s[nt][2] = -1e30f; }
                if (c0 + 1 >= NTOK){ s[nt][1] = -1e30f; s[nt][3] = -1e30f; }
            }
        }

        float rm0 = -1e30f, rm1 = -1e30f;
        #pragma unroll
        for (int nt = 0; nt < 8; nt++){
            rm0 = fmaxf(rm0, fmaxf(s[nt][0], s[nt][1]));
            rm1 = fmaxf(rm1, fmaxf(s[nt][2], s[nt][3]));
        }
        rm0 = fmaxf(rm0, __shfl_xor_sync(0xffffffffu, rm0, 1));
        rm0 = fmaxf(rm0, __shfl_xor_sync(0xffffffffu, rm0, 2));
        rm1 = fmaxf(rm1, __shfl_xor_sync(0xffffffffu, rm1, 1));
        rm1 = fmaxf(rm1, __shfl_xor_sync(0xffffffffu, rm1, 2));
        float nm0 = fmaxf(m0, rm0), nm1 = fmaxf(m1, rm1);
        float a0 = __expf(m0 - nm0), a1 = __expf(m1 - nm1);
        float ps0 = 0.f, ps1 = 0.f;
        #pragma unroll
        for (int nt = 0; nt < 8; nt++){
            s[nt][0] = __expf(s[nt][0] - nm0);
            s[nt][1] = __expf(s[nt][1] - nm0);
            s[nt][2] = __expf(s[nt][2] - nm1);
            s[nt][3] = __expf(s[nt][3] - nm1);
            ps0 += s[nt][0] + s[nt][1];
            ps1 += s[nt][2] + s[nt][3];
        }
        ps0 += __shfl_xor_sync(0xffffffffu, ps0, 1);
        ps0 += __shfl_xor_sync(0xffffffffu, ps0, 2);
        ps1 += __shfl_xor_sync(0xffffffffu, ps1, 1);
        ps1 += __shfl_xor_sync(0xffffffffu, ps1, 2);
        l0 = l0*a0 + ps0; l1 = l1*a1 + ps1;
        m0 = nm0; m1 = nm1;
        #pragma unroll
        for (int nt = 0; nt < 4; nt++){
            o[nt][0] *= a0; o[nt][1] *= a0;
            o[nt][2] *= a1; o[nt][3] *= a1;
        }

        #pragma unroll
        for (int kc2 = 0; kc2 < 4; kc2++){
            unsigned pah[4], pal[4];
            {
                const float* u = s[2*kc2];
                const float* v2 = s[2*kc2 + 1];
                bf16 h0,lo0,h1,lo1;
                splitv(u[0], h0, lo0); splitv(u[1], h1, lo1);
                pah[0] = pack2u(h0, h1);   pal[0] = pack2u(lo0, lo1);
                splitv(u[2], h0, lo0); splitv(u[3], h1, lo1);
                pah[1] = pack2u(h0, h1);   pal[1] = pack2u(lo0, lo1);
                splitv(v2[0], h0, lo0); splitv(v2[1], h1, lo1);
                pah[2] = pack2u(h0, h1);   pal[2] = pack2u(lo0, lo1);
                splitv(v2[2], h0, lo0); splitv(v2[3], h1, lo1);
                pah[3] = pack2u(h0, h1);   pal[3] = pack2u(lo0, lo1);
            }
            #pragma unroll
            for (int pr2 = 0; pr2 < 2; pr2++){
                int krow = kc2*16 + (t4 & 1)*8 + lr;
                int ncol = pr2*16 + (t4 >> 1)*8;
                unsigned off = (unsigned)(buf*5120 + (krow*40 + ncol)*2);
                unsigned th[4], tl[4];
                ldsm_x4t(th, smB + 20480 + off);
                ldsm_x4t(tl, smB + 30720 + off);
                unsigned bh0[2] = {th[0], th[1]}, bh1[2] = {th[2], th[3]};
                unsigned bl0[2] = {tl[0], tl[1]}, bl1[2] = {tl[2], tl[3]};
                mma_bf16(o[2*pr2],   pah, bh0);
                mma_bf16(o[2*pr2],   pah, bl0);
                mma_bf16(o[2*pr2],   pal, bh0);
                mma_bf16(o[2*pr2+1], pah, bh1);
                mma_bf16(o[2*pr2+1], pah, bl1);
                mma_bf16(o[2*pr2+1], pal, bh1);
            }
        }
        __syncthreads();
        buf ^= 1;
    }

    float inv0 = 1.f / l0, inv1 = 1.f / l1;
    #pragma unroll
    for (int nt = 0; nt < 4; nt++){
        int row0 = i0 + w*16 + (lane >> 2);
        int col  = nt*8 + (lane & 3)*2;
        if (row0 < NTOK){
            size_t dst = ((size_t)tb*NTOK + row0)*D + h*EH + col;
            bf16 h0,lo0,h1,lo1;
            splitv(o[nt][0]*inv0, h0, lo0); splitv(o[nt][1]*inv0, h1, lo1);
            *(__nv_bfloat162*)(p_att + dst)       = __halves2bfloat162(h0, h1);
            *(__nv_bfloat162*)(p_att + TMD + dst) = __halves2bfloat162(lo0, lo1);
        }
        if (row0 + 8 < NTOK){
            size_t dst = ((size_t)tb*NTOK + row0 + 8)*D + h*EH + col;
            bf16 h2,lo2,h3,lo3;
            splitv(o[nt][2]*inv1, h2, lo2); splitv(o[nt][3]*inv1, h3, lo3);
            *(__nv_bfloat162*)(p_att + dst)       = __halves2bfloat162(h2, h3);
            *(__nv_bfloat162*)(p_att + TMD + dst) = __halves2bfloat162(lo2, lo3);
        }
    }
}

// ---------------- LayerNorm: one warp per row (D=256, 8 elems/lane) -------
// v = (xH+xL) [- (sH+sL)], out planes; no barriers, pure shfl reduction.
__global__ __launch_bounds__(256) void ln_kernel(const bf16* __restrict__ xH,
                                                 const bf16* __restrict__ xL,
                                                 const bf16* __restrict__ sH,
                                                 const bf16* __restrict__ sL,
                                                 const float* __restrict__ g,
                                                 const float* __restrict__ beta,
                                                 bf16* __restrict__ pH,
                                                 bf16* __restrict__ pL){
    const int row  = blockIdx.x*8 + (threadIdx.x >> 5);
    const int lane = threadIdx.x & 31;
    size_t base = (size_t)row*D + lane*8;

    float v[8];
    {
        uint4 vh = *(const uint4*)(xH + base);
        uint4 vl = *(const uint4*)(xL + base);
        const __nv_bfloat162* ph = (const __nv_bfloat162*)&vh;
        const __nv_bfloat162* pl = (const __nv_bfloat162*)&vl;
        #pragma unroll
        for (int j = 0; j < 4; j++){
            float2 a = __bfloat1622float2(ph[j]);
            float2 b = __bfloat1622float2(pl[j]);
            v[2*j]   = a.x + b.x;
            v[2*j+1] = a.y + b.y;
        }
    }
    if (sH){
        uint4 wh = *(const uint4*)(sH + base);
        uint4 wl = *(const uint4*)(sL + base);
        const __nv_bfloat162* ph = (const __nv_bfloat162*)&wh;
        const __nv_bfloat162* pl = (const __nv_bfloat162*)&wl;
        #pragma unroll
        for (int j = 0; j < 4; j++){
            float2 a = __bfloat1622float2(ph[j]);
            float2 b = __bfloat1622float2(pl[j]);
            v[2*j]   -= a.x + b.x;
            v[2*j+1] -= a.y + b.y;
        }
    }

    float s = 0.f, ss = 0.f;
    #pragma unroll
    for (int j = 0; j < 8; j++){ s += v[j]; ss += v[j]*v[j]; }
    #pragma unroll
    for (int o = 16; o; o >>= 1){
        s  += __shfl_xor_sync(0xffffffffu, s,  o);
        ss += __shfl_xor_sync(0xffffffffu, ss, o);
    }
    float mean = s * (1.f/D);
    float var  = ss * (1.f/D) - mean*mean;
    float inv  = rsqrtf(var + EPS);

    float4 gg0 = *(const float4*)(g + lane*8);
    float4 gg1 = *(const float4*)(g + lane*8 + 4);
    float4 bb0 = *(const float4*)(beta + lane*8);
    float4 bb1 = *(const float4*)(beta + lane*8 + 4);
    const float* gp = (const float*)&gg0;   // contiguous pair on stack
    const float* bp = (const float*)&bb0;
    float gv[8] = {gg0.x, gg0.y, gg0.z, gg0.w, gg1.x, gg1.y, gg1.z, gg1.w};
    float bv[8] = {bb0.x, bb0.y, bb0.z, bb0.w, bb1.x, bb1.y, bb1.z, bb1.w};
    (void)gp; (void)bp;

    uint4 oh, ol;
    __nv_bfloat162* qh = (__nv_bfloat162*)&oh;
    __nv_bfloat162* ql = (__nv_bfloat162*)&ol;
    #pragma unroll
    for (int j = 0; j < 4; j++){
        float o0 = (v[2*j]   - mean)*inv*gv[2*j]   + bv[2*j];
        float o1 = (v[2*j+1] - mean)*inv*gv[2*j+1] + bv[2*j+1];
        bf16 h0,l0,h1,l1; splitv(o0,h0,l0); splitv(o1,h1,l1);
        qh[j] = __halves2bfloat162(h0,h1);
        ql[j] = __halves2bfloat162(l0,l1);
    }
    *(uint4*)(pH + base) = oh;
    *(uint4*)(pL + base) = ol;
}

// ---------------- final: transpose + de-standardize + average scales ------
__global__ __launch_bounds__(256) void final_kernel(float* __restrict__ out){
    __shared__ float t0[32][33], t1[32][33];
    int b = blockIdx.z;
    int p0 = blockIdx.x*32, n0 = blockIdx.y*32;
    int tx = threadIdx.x & 31, ty = threadIdx.x >> 5;
    #pragma unroll
    for (int i = 0; i < 4; i++){
        int n = n0 + ty + i*8, pp = p0 + tx;
        if (n < ENC && pp < DB){
            t0[ty + i*8][tx] = g_out[((size_t)b*NTOK + n)*DB + pp];
            t1[ty + i*8][tx] = g_out[((size_t)(B_ + b)*NTOK + n)*DB + pp];
        }
    }
    __syncthreads();
    #pragma unroll
    for (int i = 0; i < 4; i++){
        int pp = p0 + ty + i*8, n = n0 + tx;
        if (pp < DB && n < ENC){
            float v0 = t0[tx][ty + i*8]*g_std[b*ENC + n]        + g_mean[b*ENC + n];
            float v1 = t1[tx][ty + i*8]*g_std[(B_ + b)*ENC + n] + g_mean[(B_ + b)*ENC + n];
            out[((size_t)b*DB + pp)*ENC + n] = 0.5f*(v0 + v1);
        }
    }
}

// ---------------- host ----------------
static inline int gsz(int nt){ return nt < 444 ? nt : 444; }
static void* sym(const void* s){ void* p; cudaGetSymbolAddress(&p, s); return p; }

extern "C" void kernel_launch(void* const* d_in, const int* in_sizes, int n_in,
                              void* d_out, int out_size){
    const float* mbx  = (const float*)d_in[0];
    const float* mbxm = (const float*)d_in[1];
    const float* embW = (const float*)d_in[4];
    const float* embB = (const float*)d_in[5];
    const float* Wq = (const float*)d_in[6];
    const float* Wk = (const float*)d_in[7];
    const float* Wv = (const float*)d_in[8];
    const float* Wo = (const float*)d_in[9];
    const float* W3 = (const float*)d_in[10];
    const float* W4 = (const float*)d_in[11];
    const float* bq = (const float*)d_in[12];
    const float* bk = (const float*)d_in[13];
    const float* bv = (const float*)d_in[14];
    const float* bo = (const float*)d_in[15];
    const float* b3 = (const float*)d_in[16];
    const float* b4 = (const float*)d_in[17];
    const float* W1 = (const float*)d_in[18];
    const float* b1 = (const float*)d_in[19];
    const float* W2 = (const float*)d_in[20];
    const float* b2 = (const float*)d_in[21];
    const float* W5 = (const float*)d_in[22];
    const float* b5 = (const float*)d_in[23];
    const float* W6 = (const float*)d_in[24];
    const float* b6 = (const float*)d_in[25];
    const float* ln1g = (const float*)d_in[26];
    const float* ln1b = (const float*)d_in[27];
    const float* ln2g = (const float*)d_in[28];
    const float* ln2b = (const float*)d_in[29];
    float* out = (float*)d_out;

    float* outF = (float*)sym(g_out);

    bf16* xinP = (bf16*)sym(p_xin);
    bf16* hP   = (bf16*)sym(p_h);
    bf16* qkvP = (bf16*)sym(p_qkv);
    bf16* attP = (bf16*)sym(p_att);
    bf16* xlnP = (bf16*)sym(p_xln);
    bf16* y1P  = (bf16*)sym(p_y1);
    bf16* xsP  = (bf16*)sym(p_xs);
    bf16* xattP = (bf16*)sym(p_xatt);
    bf16* yP   = (bf16*)sym(p_y);
    bf16* hhP  = (bf16*)sym(p_hh);
    bf16* embWP = (bf16*)sym(p_embW);
    bf16* WqP = (bf16*)sym(p_Wq); bf16* WkP = (bf16*)sym(p_Wk);
    bf16* WvP = (bf16*)sym(p_Wv); bf16* WoP = (bf16*)sym(p_Wo);
    bf16* W3P = (bf16*)sym(p_W3); bf16* W4P = (bf16*)sym(p_W4);
    bf16* W1P = (bf16*)sym(p_W1); bf16* W2P = (bf16*)sym(p_W2);
    bf16* W5P = (bf16*)sym(p_W5); bf16* W6P = (bf16*)sym(p_W6);

    const size_t EWN = (size_t)256*SEQP;
    const size_t WDD = (size_t)LAYERS*D*D;
    const size_t W1N = (size_t)LAYERS*DFF*D;
    const size_t W5N = (size_t)LAYERS*DB*2*D;
    const size_t Y1N = (size_t)TM*DFF;

    cudaFuncSetAttribute(mma_gemm<0>, cudaFuncAttributeMaxDynamicSharedMemorySize, 61440);
    cudaFuncSetAttribute(mma_gemm<1>, cudaFuncAttributeMaxDynamicSharedMemorySize, 61440);
    cudaFuncSetAttribute(mma_gemm<2>, cudaFuncAttributeMaxDynamicSharedMemorySize, 61440);
    cudaFuncSetAttribute(mma_gemm2<0>, cudaFuncAttributeMaxDynamicSharedMemorySize, 61440);
    cudaFuncSetAttribute(mma_gemm2<1>, cudaFuncAttributeMaxDynamicSharedMemorySize, 61440);

    // weight splits (one batched launch + embed pad)
    {
        WSArgs ws;
        const float* ss[10] = {Wq, Wk, Wv, Wo, W3, W4, W1, W2, W5, W6};
        bf16* hh[10] = {WqP, WkP, WvP, WoP, W3P, W4P, W1P, W2P, W5P, W6P};
        size_t nn[10] = {WDD, WDD, WDD, WDD, WDD, WDD, W1N, W1N, W5N, W5N};
        for (int i = 0; i < 10; i++){
            ws.s[i] = ss[i]; ws.h[i] = hh[i]; ws.l[i] = hh[i] + nn[i]; ws.n[i] = (int)nn[i];
        }
        wsplit_all<<<dim3(288, 10), 256>>>(ws);
        wsplit_pad<<<(unsigned)((EWN + 255)/256), 256>>>(embW, embWP, embWP + EWN, 256, SEQ, SEQP);
    }

    const int tm = 109;   // ceil(13856/128)
    const int tm64 = 217; // ceil(13856/64)

    stats_kernel<<<dim3((ENC + 255)/256, B_, TS), 256>>>(mbx);
    xin_kernel<<<dim3((SEQP + 31)/32, (NTOK + 31)/32, TS*B_), 256>>>(mbx, mbxm);

    {   // embed -> h planes
        GemmArgs a = {};
        a.aH[0] = xinP; a.aL[0] = xinP + TXN;
        a.wH[0] = embWP; a.wL[0] = embWP + EWN;
        a.bias[0] = embB;
        a.cH[0] = hP; a.cL[0] = hP + TMD;
        mma_gemm<0><<<gsz(tm*4), 256, 61440>>>(a, TM, D, SEQP, 4, tm*4, tm*4);
    }

    for (int l = 0; l < LAYERS; l++){
        {   // QKV -> planes
            GemmArgs a = {};
            for (int z = 0; z < 3; z++){
                a.aH[z] = hP; a.aL[z] = hP + TMD;
                a.cH[z] = qkvP + (size_t)z*TMD;
                a.cL[z] = qkvP + 3*TMD + (size_t)z*TMD;
            }
            a.wH[0] = WqP + (size_t)l*D*D; a.wL[0] = WqP + WDD + (size_t)l*D*D;
            a.wH[1] = WkP + (size_t)l*D*D; a.wL[1] = WkP + WDD + (size_t)l*D*D;
            a.wH[2] = WvP + (size_t)l*D*D; a.wL[2] = WvP + WDD + (size_t)l*D*D;
            a.bias[0] = bq + l*D; a.bias[1] = bk + l*D; a.bias[2] = bv + l*D;
            mma_gemm<0><<<gsz(tm*4*3), 256, 61440>>>(a, TM, D, D, 4, tm*4, tm*4*3);
        }

        flash_attn<<<dim3(7, TS*B_*NH), 256>>>();

        {   // Wo -> xatt planes
            GemmArgs a = {};
            a.aH[0] = attP; a.aL[0] = attP + TMD;
            a.wH[0] = WoP + (size_t)l*D*D; a.wL[0] = WoP + WDD + (size_t)l*D*D;
            a.bias[0] = bo + l*D;
            a.cH[0] = xattP; a.cL[0] = xattP + TMD;
            mma_gemm<0><<<gsz(tm*4), 256, 61440>>>(a, TM, D, D, 4, tm*4, tm*4);
        }

        // LN1: ln(h - xatt) -> xln planes  (warp-per-row)
        ln_kernel<<<TM/8, 256>>>(hP, hP + TMD, xattP, xattP + TMD,
                                 ln1g + l*D, ln1b + l*D, xlnP, xlnP + TMD);

        {   // W1 + GELU -> y1 planes
            GemmArgs a = {};
            a.aH[0] = xlnP; a.aL[0] = xlnP + TMD;
            a.wH[0] = W1P + (size_t)l*DFF*D; a.wL[0] = W1P + W1N + (size_t)l*DFF*D;
            a.bias[0] = b1 + l*DFF;
            a.cH[0] = y1P; a.cL[0] = y1P + Y1N;
            mma_gemm<1><<<gsz(tm*8), 256, 61440>>>(a, TM, DFF, D, 8, tm*8, tm*8);
        }
        {   // W2 -> y planes + xs=(xln-y) planes (sub fused, xln from planes)
            GemmArgs a = {};
            a.aH[0] = y1P; a.aL[0] = y1P + Y1N;
            a.wH[0] = W2P + (size_t)l*D*DFF; a.wL[0] = W2P + W1N + (size_t)l*D*DFF;
            a.bias[0] = b2 + l*D;
            a.cH[0] = yP; a.cL[0] = yP + TMD;
            a.xsH[0] = xlnP; a.xsL[0] = xlnP + TMD;
            a.c2H[0] = xsP; a.c2L[0] = xsP + TMD;
            mma_gemm<2><<<gsz(tm*4), 256, 61440>>>(a, TM, D, DFF, 4, tm*4, tm*4);
        }

        {   // fused W3/W4 -> hh planes = sigmoid(.)*(.)
            Gemm2Args a = {};
            a.a0H = xsP; a.a0L = xsP + TMD; a.a1H = xsP; a.a1L = xsP + TMD;
            a.kSplit = 1 << 30; a.aStride = D;
            a.w1H = W3P + (size_t)l*D*D; a.w1L = W3P + WDD + (size_t)l*D*D;
            a.w2H = W4P + (size_t)l*D*D; a.w2L = W4P + WDD + (size_t)l*D*D;
            a.b1 = b3 + l*D; a.b2 = b4 + l*D;
            a.cH = hhP; a.cL = hhP + TMD;
            mma_gemm2<0><<<gsz(tm64*4), 256, 61440>>>(a, TM, D, D, 4, tm64*4);
        }

        {   // fused W5/W6 over cat(xatt,y) -> g_out (with layer subtract)
            Gemm2Args a = {};
            a.a0H = xattP; a.a0L = xattP + TMD;
            a.a1H = yP;    a.a1L = yP + TMD;
            a.kSplit = D; a.aStride = D;
            a.w1H = W5P + (size_t)l*DB*2*D; a.w1L = W5P + W5N + (size_t)l*DB*2*D;
            a.w2H = W6P + (size_t)l*DB*2*D; a.w2L = W6P + W5N + (size_t)l*DB*2*D;
            a.b1 = b5 + l*DB; a.b2 = b6 + l*DB;
            a.Cout = outF; a.sub = l;
            mma_gemm2<1><<<gsz(tm64*12), 256, 61440>>>(a, TM, DB, 2*D, 12, tm64*12);
        }

        // LN2: ln(hh) -> h planes  (warp-per-row)
        ln_kernel<<<TM/8, 256>>>(hhP, hhP + TMD, (const bf16*)nullptr, (const bf16*)nullptr,
                                 ln2g + l*D, ln2b + l*D, hP, hP + TMD);
    }

    final_kernel<<<dim3((DB + 31)/32, (ENC + 31)/32, B_), 256>>>(out);
}

// round 16
// speedup vs baseline: 1.2967x; 1.0147x over previous
#include <cuda_runtime.h>
#include <cuda_bf16.h>
#include <math.h>

#define B_    8
#define TS    2
#define SEQ   720
#define SEQP  736
#define ENC   862
#define MARKD 4
#define NTOK  866
#define D     256
#define NH    8
#define EH    32
#define DFF   512
#define DB    720
#define LAYERS 2
#define EPS   1e-5f
#define MROWS (B_*NTOK)        // 6928 per scale
#define TM    (TS*MROWS)       // 13856 combined
#define TMD   ((size_t)TM*D)
#define TXN   ((size_t)TM*SEQP)
#define SCH   8                // SEQ chunks for stats (720 = 8*90)

typedef __nv_bfloat16 bf16;

// ---------------- fp32 scratch ----------------
__device__ float g_mean[TS*B_*ENC], g_std[TS*B_*ENC];
__device__ float g_ps[TS*B_*SCH*ENC], g_pq[TS*B_*SCH*ENC];
__device__ float g_out[(size_t)TM*DB];

// ---------------- bf16 hi/lo planes (lo at +n) ----------------
__device__ __align__(16) bf16 p_xin[2*TXN];
__device__ __align__(16) bf16 p_h  [2*TMD];
__device__ __align__(16) bf16 p_qkv[2*3*TMD];
__device__ __align__(16) bf16 p_att[2*TMD];
__device__ __align__(16) bf16 p_xln[2*TMD];
__device__ __align__(16) bf16 p_y1 [2*(size_t)TM*DFF];
__device__ __align__(16) bf16 p_xs [2*TMD];
__device__ __align__(16) bf16 p_xatt[2*TMD];
__device__ __align__(16) bf16 p_y  [2*TMD];
__device__ __align__(16) bf16 p_hh [2*TMD];
// weights
__device__ __align__(16) bf16 p_embW[2*256*SEQP];
__device__ __align__(16) bf16 p_Wq[2*LAYERS*D*D], p_Wk[2*LAYERS*D*D], p_Wv[2*LAYERS*D*D];
__device__ __align__(16) bf16 p_Wo[2*LAYERS*D*D], p_W3[2*LAYERS*D*D], p_W4[2*LAYERS*D*D];
__device__ __align__(16) bf16 p_W1[2*LAYERS*DFF*D], p_W2[2*LAYERS*D*DFF];
__device__ __align__(16) bf16 p_W5[2*LAYERS*DB*2*D], p_W6[2*LAYERS*DB*2*D];

// ---------------- helpers ----------------
__device__ __forceinline__ void splitv(float x, bf16& h, bf16& l){
    h = __float2bfloat16(x);
    l = __float2bfloat16(x - __bfloat162float(h));
}
__device__ __forceinline__ unsigned pack2u(bf16 a, bf16 b){
    __nv_bfloat162 t = __halves2bfloat162(a, b);
    return *(unsigned*)&t;
}
__device__ __forceinline__ void mma_bf16(float c[4], const unsigned a[4], const unsigned b[2]){
    asm volatile("mma.sync.aligned.m16n8k16.row.col.f32.bf16.bf16.f32 "
                 "{%0,%1,%2,%3}, {%4,%5,%6,%7}, {%8,%9}, {%0,%1,%2,%3};\n"
                 : "+f"(c[0]), "+f"(c[1]), "+f"(c[2]), "+f"(c[3])
                 : "r"(a[0]), "r"(a[1]), "r"(a[2]), "r"(a[3]),
                   "r"(b[0]), "r"(b[1]));
}
__device__ __forceinline__ void ldsm_x4(unsigned r[4], unsigned addr){
    asm volatile("ldmatrix.sync.aligned.m8n8.x4.shared.b16 {%0,%1,%2,%3}, [%4];\n"
                 : "=r"(r[0]), "=r"(r[1]), "=r"(r[2]), "=r"(r[3]) : "r"(addr));
}
__device__ __forceinline__ void ldsm_x4t(unsigned r[4], unsigned addr){
    asm volatile("ldmatrix.sync.aligned.m8n8.x4.trans.shared.b16 {%0,%1,%2,%3}, [%4];\n"
                 : "=r"(r[0]), "=r"(r[1]), "=r"(r[2]), "=r"(r[3]) : "r"(addr));
}
__device__ __forceinline__ void cp16(unsigned dst, const void* src, bool p){
    int sz = p ? 16 : 0;
    asm volatile("cp.async.cg.shared.global [%0], [%1], 16, %2;\n"
                 :: "r"(dst), "l"(src), "r"(sz));
}
__device__ __forceinline__ void cpcommit(){ asm volatile("cp.async.commit_group;\n"); }
template<int N> __device__ __forceinline__ void cpwait(){
    asm volatile("cp.async.wait_group %0;\n" :: "n"(N));
}
__device__ __forceinline__ float gelu_f(float x){
    return 0.5f*x*(1.f + erff(x*0.70710678118654752f));
}
__device__ __forceinline__ float sigmoid_f(float x){
    return 1.f/(1.f + expf(-x));
}

// ---------------- weight split (batched) ----------------
struct WSArgs { const float* s[10]; bf16* h[10]; bf16* l[10]; int n[10]; };
__global__ void wsplit_all(WSArgs w){
    int z = blockIdx.y;
    int n = w.n[z];
    const float* src = w.s[z];
    bf16* hh = w.h[z]; bf16* ll = w.l[z];
    for (int i = blockIdx.x*blockDim.x + threadIdx.x; i < n; i += gridDim.x*blockDim.x)
        splitv(src[i], hh[i], ll[i]);
}
__global__ void wsplit_pad(const float* __restrict__ s, bf16* __restrict__ h,
                           bf16* __restrict__ l, int rows, int K, int Kp){
    size_t i = (size_t)blockIdx.x*blockDim.x + threadIdx.x;
    size_t total = (size_t)rows*Kp;
    if (i >= total) return;
    int c = (int)(i % Kp); int r = (int)(i / Kp);
    float v = (c < K) ? s[(size_t)r*K + c] : 0.f;
    splitv(v, h[i], l[i]);
}

// ---------------- input standardization (two-stage, deterministic) -------
__global__ void stats_part(const float* __restrict__ mbx){
    int tb = blockIdx.z;                     // t*B_ + b
    int t = tb / B_, b = tb % B_;
    int sc = blockIdx.y;
    int n = blockIdx.x*blockDim.x + threadIdx.x;
    if (n >= ENC) return;
    const float* base = mbx + ((size_t)(b*TS + t)*SEQ + sc*(SEQ/SCH))*ENC + n;
    float s = 0.f, ss = 0.f;
    #pragma unroll 6
    for (int i = 0; i < SEQ/SCH; i++){
        float v = base[(size_t)i*ENC];
        s += v; ss += v*v;
    }
    g_ps[((size_t)tb*SCH + sc)*ENC + n] = s;
    g_pq[((size_t)tb*SCH + sc)*ENC + n] = ss;
}
__global__ void stats_fin(){
    int tb = blockIdx.y;
    int n = blockIdx.x*blockDim.x + threadIdx.x;
    if (n >= ENC) return;
    float s = 0.f, ss = 0.f;
    #pragma unroll
    for (int c = 0; c < SCH; c++){
        s  += g_ps[((size_t)tb*SCH + c)*ENC + n];
        ss += g_pq[((size_t)tb*SCH + c)*ENC + n];
    }
    float m = s * (1.f/SEQ);
    float var = ss * (1.f/SEQ) - m*m;
    g_mean[tb*ENC + n] = m;
    g_std [tb*ENC + n] = sqrtf(var + EPS);
}

// transposed tiled build of xin planes for both scales
__global__ __launch_bounds__(256) void xin_kernel(const float* __restrict__ mbx,
                                                  const float* __restrict__ mbxm){
    __shared__ float tile[32][33];
    const int zb = blockIdx.z;            // t*B_ + b
    const int t = zb / B_, b = zb % B_;
    const int s0 = blockIdx.x*32, n0 = blockIdx.y*32;
    const int tx = threadIdx.x & 31, ty = threadIdx.x >> 5;
    #pragma unroll
    for (int i = 0; i < 4; i++){
        int s = s0 + ty + i*8, n = n0 + tx;
        float v = 0.f;
        if (s < SEQ && n < NTOK){
            if (n < ENC){
                v = mbx[((size_t)(b*TS + t)*SEQ + s)*ENC + n];
                v = (v - g_mean[zb*ENC + n]) / g_std[zb*ENC + n];
            } else {
                v = mbxm[((size_t)(b*TS + t)*SEQ + s)*MARKD + (n - ENC)];
            }
        }
        tile[ty + i*8][tx] = v;
    }
    __syncthreads();
    #pragma unroll
    for (int i = 0; i < 4; i++){
        int n = n0 + ty + i*8, s = s0 + tx;
        if (n < NTOK && s < SEQP){
            size_t idx = ((size_t)zb*NTOK + n)*SEQP + s;
            splitv(tile[tx][ty + i*8], p_xin[idx], p_xin[TXN + idx]);
        }
    }
}

// =============== MMA GEMM: planes = A @ W^T + bias (bf16 planes) ==========
// ACT 0: plain; 1: gelu; 2: also emit (xsub - y) planes (xsub from planes)
struct GemmArgs {
    const bf16 *aH[3], *aL[3], *wH[3], *wL[3];
    const float* bias[3];
    bf16 *cH[3], *cL[3];
    const bf16 *xsH[3], *xsL[3];
    bf16 *c2H[3], *c2L[3];
};

template<int ACT>
__global__ __launch_bounds__(256, 3)
void mma_gemm(GemmArgs p, int M, int N, int K, int tilesN, int tpz, int nTiles){
    extern __shared__ __align__(16) char smraw[];
    bf16* sAh = (bf16*)smraw;            // [2][128][40]
    bf16* sAl = sAh + 2*128*40;
    bf16* sBh = sAl + 2*128*40;          // [2][64][40]
    bf16* sBl = sBh + 2*64*40;
    const unsigned aHiB = (unsigned)__cvta_generic_to_shared(sAh);
    const unsigned aLoB = (unsigned)__cvta_generic_to_shared(sAl);
    const unsigned bHiB = (unsigned)__cvta_generic_to_shared(sBh);
    const unsigned bLoB = (unsigned)__cvta_generic_to_shared(sBl);

    const int tid = threadIdx.x;
    const int lane = tid & 31, w = tid >> 5;
    const int wm = (w >> 1)*32, wn = (w & 1)*32;
    const int t4 = lane >> 3, lr = lane & 7;
    const int ldr = tid >> 2, ldc = (tid & 3)*8;

    for (int t = blockIdx.x; t < nTiles; t += gridDim.x){
        const int z  = t / tpz;
        const int rr = t - z*tpz;
        const int bm = (rr / tilesN)*128, bn = (rr % tilesN)*64;
        const bf16* __restrict__ aHp = p.aH[z];
        const bf16* __restrict__ aLp = p.aL[z];
        const bf16* __restrict__ wHp = p.wH[z];
        const bf16* __restrict__ wLp = p.wL[z];
        const float* __restrict__ bias = p.bias[z];
        bf16* cHp = p.cH[z];
        bf16* cLp = p.cL[z];

        float acc[2][4][4];
        #pragma unroll
        for (int i = 0; i < 2; i++)
            #pragma unroll
            for (int j = 0; j < 4; j++)
                #pragma unroll
                for (int q = 0; q < 4; q++) acc[i][j][q] = 0.f;

        auto loadst = [&](int s, int k0){
            #pragma unroll
            for (int rep = 0; rep < 2; rep++){
                int r = ldr + rep*64;
                int gm = bm + r;
                bool pr = gm < M;
                size_t so = (size_t)(pr ? gm : 0)*K + k0 + ldc;
                unsigned doff = (unsigned)(((s*128 + r)*40 + ldc)*2);
                cp16(aHiB + doff, aHp + so, pr);
                cp16(aLoB + doff, aLp + so, pr);
            }
            {
                int gn = bn + ldr;
                bool pn = gn < N;
                size_t so = (size_t)(pn ? gn : 0)*K + k0 + ldc;
                unsigned doff = (unsigned)(((s*64 + ldr)*40 + ldc)*2);
                cp16(bHiB + doff, wHp + so, pn);
                cp16(bLoB + doff, wLp + so, pn);
            }
            cpcommit();
        };

        loadst(0, 0);
        int buf = 0;
        const int KT = K >> 5;
        for (int kt = 0; kt < KT; kt++){
            if (kt + 1 < KT){ loadst(buf ^ 1, (kt+1)*32); cpwait<1>(); }
            else cpwait<0>();
            __syncthreads();

            #pragma unroll
            for (int kh = 0; kh < 32; kh += 16){
                unsigned ah[2][4], al[2][4], bh[4][2], bl[4][2];
                #pragma unroll
                for (int mt = 0; mt < 2; mt++){
                    int arow = wm + mt*16 + (t4 & 1)*8 + lr;
                    unsigned off = (unsigned)((((buf*128) + arow)*40 + kh + (t4 >> 1)*8)*2);
                    ldsm_x4(ah[mt], aHiB + off);
                    ldsm_x4(al[mt], aLoB + off);
                }
                #pragma unroll
                for (int pr2 = 0; pr2 < 2; pr2++){
                    int brow = wn + pr2*16 + (t4 >> 1)*8 + lr;
                    unsigned off = (unsigned)((((buf*64) + brow)*40 + kh + (t4 & 1)*8)*2);
                    unsigned th[4], tl[4];
                    ldsm_x4(th, bHiB + off);
                    ldsm_x4(tl, bLoB + off);
                    bh[pr2*2][0] = th[0]; bh[pr2*2][1] = th[1];
                    bh[pr2*2+1][0] = th[2]; bh[pr2*2+1][1] = th[3];
                    bl[pr2*2][0] = tl[0]; bl[pr2*2][1] = tl[1];
                    bl[pr2*2+1][0] = tl[2]; bl[pr2*2+1][1] = tl[3];
                }
                #pragma unroll
                for (int mt = 0; mt < 2; mt++)
                    #pragma unroll
                    for (int nt = 0; nt < 4; nt++){
                        mma_bf16(acc[mt][nt], ah[mt], bh[nt]);
                        mma_bf16(acc[mt][nt], ah[mt], bl[nt]);
                        mma_bf16(acc[mt][nt], al[mt], bh[nt]);
                    }
            }
            __syncthreads();
            buf ^= 1;
        }

        #pragma unroll
        for (int mt = 0; mt < 2; mt++)
            #pragma unroll
            for (int nt = 0; nt < 4; nt++){
                int row0 = bm + wm + mt*16 + (lane >> 2);
                int col  = bn + wn + nt*8 + (lane & 3)*2;
                if (col >= N) continue;
                float b0 = bias[col], b1 = bias[col + 1];
                float v0 = acc[mt][nt][0] + b0, v1 = acc[mt][nt][1] + b1;
                float v2 = acc[mt][nt][2] + b0, v3 = acc[mt][nt][3] + b1;
                if (ACT == 1){
                    v0 = gelu_f(v0); v1 = gelu_f(v1);
                    v2 = gelu_f(v2); v3 = gelu_f(v3);
                }
                if (row0 < M){
                    size_t ix = (size_t)row0*N + col;
                    bf16 h0,l0,h1,l1; splitv(v0,h0,l0); splitv(v1,h1,l1);
                    *(__nv_bfloat162*)(cHp + ix) = __halves2bfloat162(h0,h1);
                    *(__nv_bfloat162*)(cLp + ix) = __halves2bfloat162(l0,l1);
                    if (ACT == 2){
                        float x0 = __bfloat162float(p.xsH[z][ix]) + __bfloat162float(p.xsL[z][ix]);
                        float x1 = __bfloat162float(p.xsH[z][ix+1]) + __bfloat162float(p.xsL[z][ix+1]);
                        bf16 s0,t0,s1,t1; splitv(x0 - v0,s0,t0); splitv(x1 - v1,s1,t1);
                        *(__nv_bfloat162*)(p.c2H[z] + ix) = __halves2bfloat162(s0,s1);
                        *(__nv_bfloat162*)(p.c2L[z] + ix) = __halves2bfloat162(t0,t1);
                    }
                }
                if (row0 + 8 < M){
                    size_t ix = (size_t)(row0+8)*N + col;
                    bf16 h2,l2,h3,l3; splitv(v2,h2,l2); splitv(v3,h3,l3);
                    *(__nv_bfloat162*)(cHp + ix) = __halves2bfloat162(h2,h3);
                    *(__nv_bfloat162*)(cLp + ix) = __halves2bfloat162(l2,l3);
                    if (ACT == 2){
                        float x2 = __bfloat162float(p.xsH[z][ix]) + __bfloat162float(p.xsL[z][ix]);
                        float x3 = __bfloat162float(p.xsH[z][ix+1]) + __bfloat162float(p.xsL[z][ix+1]);
                        bf16 s2,t2,s3,t3; splitv(x2 - v2,s2,t2); splitv(x3 - v3,s3,t3);
                        *(__nv_bfloat162*)(p.c2H[z] + ix) = __halves2bfloat162(s2,s3);
                        *(__nv_bfloat162*)(p.c2L[z] + ix) = __halves2bfloat162(t2,t3);
                    }
                }
            }
    }
}

// =============== fused dual GEMM (BM=64): o = sig(A W1^T+b1)*(A W2^T+b2) ==
// MODE 0: write o as bf16 planes (cH/cL); MODE 1: fp32 Cout = sub ? o-C : o
struct Gemm2Args {
    const bf16 *a0H, *a0L, *a1H, *a1L;
    int kSplit, aStride;
    const bf16 *w1H, *w1L, *w2H, *w2L;
    const float *b1, *b2;
    float* Cout;
    bf16 *cH, *cL;
    int sub;
};

template<int MODE>
__global__ __launch_bounds__(256, 3)
void mma_gemm2(Gemm2Args p, int M, int N, int K, int tilesN, int nTiles){
    extern __shared__ __align__(16) char smraw[];
    bf16* sm = (bf16*)smraw;
    const unsigned smB = (unsigned)__cvta_generic_to_shared(sm);
    const int tid = threadIdx.x;
    const int lane = tid & 31, w = tid >> 5;
    const int wm = (w >> 1)*16, wn = (w & 1)*32;
    const int t4 = lane >> 3, lr = lane & 7;
    const int ldr = tid >> 2, ldc = (tid & 3)*8;

    for (int t = blockIdx.x; t < nTiles; t += gridDim.x){
        const int bm = (t / tilesN)*64, bn = (t % tilesN)*64;

        float acc[2][4][4];
        #pragma unroll
        for (int g = 0; g < 2; g++)
            #pragma unroll
            for (int j = 0; j < 4; j++)
                #pragma unroll
                for (int q = 0; q < 4; q++) acc[g][j][q] = 0.f;

        auto loadst = [&](int s, int k0){
            const bf16* aH = (k0 < p.kSplit) ? p.a0H : p.a1H;
            const bf16* aL = (k0 < p.kSplit) ? p.a0L : p.a1L;
            int kk = (k0 < p.kSplit) ? k0 : k0 - p.kSplit;
            int gm = bm + ldr;
            bool pr = gm < M;
            size_t soA = (size_t)(pr ? gm : 0)*p.aStride + kk + ldc;
            unsigned dA = (unsigned)((s*2*2560 + ldr*40 + ldc)*2);
            cp16(smB + dA,           aH + soA, pr);
            cp16(smB + dA + 2560*2,  aL + soA, pr);
            int gn = bn + ldr;
            bool pn = gn < N;
            size_t soB = (size_t)(pn ? gn : 0)*K + k0 + ldc;
            unsigned dB = (unsigned)((10240 + s*4*2560 + ldr*40 + ldc)*2);
            cp16(smB + dB,             p.w1H + soB, pn);
            cp16(smB + dB + 2560*2,    p.w1L + soB, pn);
            cp16(smB + dB + 2*2560*2,  p.w2H + soB, pn);
            cp16(smB + dB + 3*2560*2,  p.w2L + soB, pn);
            cpcommit();
        };

        loadst(0, 0);
        int buf = 0;
        const int KT = K >> 5;
        for (int kt = 0; kt < KT; kt++){
            if (kt + 1 < KT){ loadst(buf ^ 1, (kt+1)*32); cpwait<1>(); }
            else cpwait<0>();
            __syncthreads();

            #pragma unroll
            for (int kh = 0; kh < 32; kh += 16){
                unsigned ah[4], al[4];
                {
                    int arow = wm + (t4 & 1)*8 + lr;
                    unsigned off = (unsigned)((buf*2*2560 + arow*40 + kh + (t4 >> 1)*8)*2);
                    ldsm_x4(ah, smB + off);
                    ldsm_x4(al, smB + off + 2560*2);
                }
                #pragma unroll
                for (int g = 0; g < 2; g++){
                    #pragma unroll
                    for (int pr2 = 0; pr2 < 2; pr2++){
                        int brow = wn + pr2*16 + (t4 >> 1)*8 + lr;
                        unsigned off = (unsigned)((10240 + buf*4*2560 + g*2*2560
                                                   + brow*40 + kh + (t4 & 1)*8)*2);
                        unsigned th[4], tl[4];
                        ldsm_x4(th, smB + off);
                        ldsm_x4(tl, smB + off + 2560*2);
                        unsigned bh0[2] = {th[0], th[1]}, bh1[2] = {th[2], th[3]};
                        unsigned bl0[2] = {tl[0], tl[1]}, bl1[2] = {tl[2], tl[3]};
                        mma_bf16(acc[g][2*pr2],   ah, bh0);
                        mma_bf16(acc[g][2*pr2],   ah, bl0);
                        mma_bf16(acc[g][2*pr2],   al, bh0);
                        mma_bf16(acc[g][2*pr2+1], ah, bh1);
                        mma_bf16(acc[g][2*pr2+1], ah, bl1);
                        mma_bf16(acc[g][2*pr2+1], al, bh1);
                    }
                }
            }
            __syncthreads();
            buf ^= 1;
        }

        #pragma unroll
        for (int nt = 0; nt < 4; nt++){
            int row0 = bm + wm + (lane >> 2);
            int col  = bn + wn + nt*8 + (lane & 3)*2;
            if (col >= N) continue;
            float b10 = p.b1[col], b11 = p.b1[col + 1];
            float b20 = p.b2[col], b21 = p.b2[col + 1];
            float o0 = sigmoid_f(acc[0][nt][0] + b10)*(acc[1][nt][0] + b20);
            float o1 = sigmoid_f(acc[0][nt][1] + b11)*(acc[1][nt][1] + b21);
            float o2 = sigmoid_f(acc[0][nt][2] + b10)*(acc[1][nt][2] + b20);
            float o3 = sigmoid_f(acc[0][nt][3] + b11)*(acc[1][nt][3] + b21);
            if (row0 < M){
                size_t ix = (size_t)row0*N + col;
                if (MODE == 0){
                    bf16 h0,l0,h1,l1; splitv(o0,h0,l0); splitv(o1,h1,l1);
                    *(__nv_bfloat162*)(p.cH + ix) = __halves2bfloat162(h0,h1);
                    *(__nv_bfloat162*)(p.cL + ix) = __halves2bfloat162(l0,l1);
                } else if (p.sub){
                    p.Cout[ix]     = o0 - p.Cout[ix];
                    p.Cout[ix + 1] = o1 - p.Cout[ix + 1];
                } else {
                    p.Cout[ix] = o0; p.Cout[ix + 1] = o1;
                }
            }
            if (row0 + 8 < M){
                size_t ix = (size_t)(row0+8)*N + col;
                if (MODE == 0){
                    bf16 h2,l2,h3,l3; splitv(o2,h2,l2); splitv(o3,h3,l3);
                    *(__nv_bfloat162*)(p.cH + ix) = __halves2bfloat162(h2,h3);
                    *(__nv_bfloat162*)(p.cL + ix) = __halves2bfloat162(l2,l3);
                } else if (p.sub){
                    p.Cout[ix]     = o2 - p.Cout[ix];
                    p.Cout[ix + 1] = o3 - p.Cout[ix + 1];
                } else {
                    p.Cout[ix] = o2; p.Cout[ix + 1] = o3;
                }
            }
        }
    }
}

// =============== flash attention (both scales via batch index) ============
__global__ __launch_bounds__(256) void flash_attn(){
    __shared__ __align__(16) bf16 sm[20480];   // 40 KB
    const unsigned smB = (unsigned)__cvta_generic_to_shared(sm);
    const int bh = blockIdx.y;
    const int tb = bh >> 3, h = bh & 7;
    const int i0 = blockIdx.x * 128;
    const bf16* qH = p_qkv +            (size_t)tb*NTOK*D + h*EH;
    const bf16* qL = qH + 3*TMD;
    const bf16* kH = p_qkv +    TMD +   (size_t)tb*NTOK*D + h*EH;
    const bf16* kL = kH + 3*TMD;
    const bf16* vH = p_qkv +  2*TMD +   (size_t)tb*NTOK*D + h*EH;
    const bf16* vL = vH + 3*TMD;

    const int tid = threadIdx.x, lane = tid & 31, w = tid >> 5;
    const int t4 = lane >> 3, lr = lane & 7;

    {
        int row = tid >> 1, c = (tid & 1)*16;
        int gi = i0 + row;
        bool ok = gi < NTOK;
        size_t so = (size_t)(ok ? gi : 0)*D + c;
        const float4 z4 = make_float4(0.f,0.f,0.f,0.f);
        float4 f0 = ok ? *(const float4*)(qH + so)     : z4;
        float4 f1 = ok ? *(const float4*)(qH + so + 8) : z4;
        *(float4*)&sm[row*40 + c]     = f0;
        *(float4*)&sm[row*40 + c + 8] = f1;
        f0 = ok ? *(const float4*)(qL + so)     : z4;
        f1 = ok ? *(const float4*)(qL + so + 8) : z4;
        *(float4*)&sm[5120 + row*40 + c]     = f0;
        *(float4*)&sm[5120 + row*40 + c + 8] = f1;
    }
    __syncthreads();
    unsigned qh[2][4], ql[2][4];
    #pragma unroll
    for (int kc = 0; kc < 2; kc++){
        int row = w*16 + (t4 & 1)*8 + lr;
        int col = kc*16 + (t4 >> 1)*8;
        ldsm_x4(qh[kc], smB + (unsigned)((row*40 + col)*2));
        ldsm_x4(ql[kc], smB + (unsigned)((5120 + row*40 + col)*2));
    }
    __syncthreads();

    const int ldr = tid >> 2, ldc = (tid & 3)*8;
    auto loadkv = [&](int s, int j0){
        int gj = j0 + ldr;
        bool ok = gj < NTOK;
        size_t so = (size_t)(ok ? gj : 0)*D + ldc;
        unsigned doff = (unsigned)(s*5120 + (ldr*40 + ldc)*2);
        cp16(smB + doff,         kH + so, ok);
        cp16(smB + 10240 + doff, kL + so, ok);
        cp16(smB + 20480 + doff, vH + so, ok);
        cp16(smB + 30720 + doff, vL + so, ok);
        cpcommit();
    };

    float o[4][4];
    #pragma unroll
    for (int j = 0; j < 4; j++)
        #pragma unroll
        for (int q = 0; q < 4; q++) o[j][q] = 0.f;
    float m0 = -1e30f, m1 = -1e30f, l0 = 0.f, l1 = 0.f;
    const float scale = 0.17677669529663688f;

    loadkv(0, 0);
    int buf = 0;
    const int NJT = 14;
    for (int jt = 0; jt < NJT; jt++){
        const int j0 = jt*64;
        if (jt + 1 < NJT){ loadkv(buf ^ 1, (jt+1)*64); cpwait<1>(); }
        else cpwait<0>();
        __syncthreads();

        float s[8][4];
        #pragma unroll
        for (int nt = 0; nt < 8; nt++)
            #pragma unroll
            for (int q = 0; q < 4; q++) s[nt][q] = 0.f;

        #pragma unroll
        for (int kc = 0; kc < 2; kc++){
            #pragma unroll
            for (int pr = 0; pr < 4; pr++){
                int brow = pr*16 + (t4 >> 1)*8 + lr;
                int col  = kc*16 + (t4 & 1)*8;
                unsigned off = (unsigned)(buf*5120 + (brow*40 + col)*2);
                unsigned th[4], tl[4];
                ldsm_x4(th, smB + off);
                ldsm_x4(tl, smB + 10240 + off);
                unsigned bh0[2] = {th[0], th[1]}, bh1[2] = {th[2], th[3]};
                unsigned bl0[2] = {tl[0], tl[1]}, bl1[2] = {tl[2], tl[3]};
                mma_bf16(s[2*pr],   qh[kc], bh0);
                mma_bf16(s[2*pr],   qh[kc], bl0);
                mma_bf16(s[2*pr],   ql[kc], bh0);
                mma_bf16(s[2*pr+1], qh[kc], bh1);
                mma_bf16(s[2*pr+1], qh[kc], bl1);
                mma_bf16(s[2*pr+1], ql[kc], bh1);
            }
        }

        #pragma unroll
        for (int nt = 0; nt < 8; nt++)
            #pragma unroll
            for (int q = 0; q < 4; q++) s[nt][q] *= scale;
        if (j0 + 64 > NTOK){
            #pragma unroll
            for (int nt = 0; nt < 8; nt++){
                int c0 = j0 + nt*8 + (lane & 3)*2;
                if (c0     >= NTOK){ s[nt][0] = -1e30f; s[nt][2] = -1e30f; }
                if (c0 + 1 >= NTOK){ s[nt][1] = -1e30f; s[nt][3] = -1e30f; }
            }
        }

        float rm0 = -1e30f, rm1 = -1e30f;
        #pragma unroll
        for (int nt = 0; nt < 8; nt++){
            rm0 = fmaxf(rm0, fmaxf(s[nt][0], s[nt][1]));
            rm1 = fmaxf(rm1, fmaxf(s[nt][2], s[nt][3]));
        }
        rm0 = fmaxf(rm0, __shfl_xor_sync(0xffffffffu, rm0, 1));
        rm0 = fmaxf(rm0, __shfl_xor_sync(0xffffffffu, rm0, 2));
        rm1 = fmaxf(rm1, __shfl_xor_sync(0xffffffffu, rm1, 1));
        rm1 = fmaxf(rm1, __shfl_xor_sync(0xffffffffu, rm1, 2));
        float nm0 = fmaxf(m0, rm0), nm1 = fmaxf(m1, rm1);
        float a0 = __expf(m0 - nm0), a1 = __expf(m1 - nm1);
        float ps0 = 0.f, ps1 = 0.f;
        #pragma unroll
        for (int nt = 0; nt < 8; nt++){
            s[nt][0] = __expf(s[nt][0] - nm0);
            s[nt][1] = __expf(s[nt][1] - nm0);
            s[nt][2] = __expf(s[nt][2] - nm1);
            s[nt][3] = __expf(s[nt][3] - nm1);
            ps0 += s[nt][0] + s[nt][1];
            ps1 += s[nt][2] + s[nt][3];
        }
        ps0 += __shfl_xor_sync(0xffffffffu, ps0, 1);
        ps0 += __shfl_xor_sync(0xffffffffu, ps0, 2);
        ps1 += __shfl_xor_sync(0xffffffffu, ps1, 1);
        ps1 += __shfl_xor_sync(0xffffffffu, ps1, 2);
        l0 = l0*a0 + ps0; l1 = l1*a1 + ps1;
        m0 = nm0; m1 = nm1;
        #pragma unroll
        for (int nt = 0; nt < 4; nt++){
            o[nt][0] *= a0; o[nt][1] *= a0;
            o[nt][2] *= a1; o[nt][3] *= a1;
        }

        #pragma unroll
        for (int kc2 = 0; kc2 < 4; kc2++){
            unsigned pah[4], pal[4];
            {
                const float* u = s[2*kc2];
                const float* v2 = s[2*kc2 + 1];
                bf16 h0,lo0,h1,lo1;
                splitv(u[0], h0, lo0); splitv(u[1], h1, lo1);
                pah[0] = pack2u(h0, h1);   pal[0] = pack2u(lo0, lo1);
                splitv(u[2], h0, lo0); splitv(u[3], h1, lo1);
                pah[1] = pack2u(h0, h1);   pal[1] = pack2u(lo0, lo1);
                splitv(v2[0], h0, lo0); splitv(v2[1], h1, lo1);
                pah[2] = pack2u(h0, h1);   pal[2] = pack2u(lo0, lo1);
                splitv(v2[2], h0, lo0); splitv(v2[3], h1, lo1);
                pah[3] = pack2u(h0, h1);   pal[3] = pack2u(lo0, lo1);
            }
            #pragma unroll
            for (int pr2 = 0; pr2 < 2; pr2++){
                int krow = kc2*16 + (t4 & 1)*8 + lr;
                int ncol = pr2*16 + (t4 >> 1)*8;
                unsigned off = (unsigned)(buf*5120 + (krow*40 + ncol)*2);
                unsigned th[4], tl[4];
                ldsm_x4t(th, smB + 20480 + off);
                ldsm_x4t(tl, smB + 30720 + off);
                unsigned bh0[2] = {th[0], th[1]}, bh1[2] = {th[2], th[3]};
                unsigned bl0[2] = {tl[0], tl[1]}, bl1[2] = {tl[2], tl[3]};
                mma_bf16(o[2*pr2],   pah, bh0);
                mma_bf16(o[2*pr2],   pah, bl0);
                mma_bf16(o[2*pr2],   pal, bh0);
                mma_bf16(o[2*pr2+1], pah, bh1);
                mma_bf16(o[2*pr2+1], pah, bl1);
                mma_bf16(o[2*pr2+1], pal, bh1);
            }
        }
        __syncthreads();
        buf ^= 1;
    }

    float inv0 = 1.f / l0, inv1 = 1.f / l1;
    #pragma unroll
    for (int nt = 0; nt < 4; nt++){
        int row0 = i0 + w*16 + (lane >> 2);
        int col  = nt*8 + (lane & 3)*2;
        if (row0 < NTOK){
            size_t dst = ((size_t)tb*NTOK + row0)*D + h*EH + col;
            bf16 h0,lo0,h1,lo1;
            splitv(o[nt][0]*inv0, h0, lo0); splitv(o[nt][1]*inv0, h1, lo1);
            *(__nv_bfloat162*)(p_att + dst)       = __halves2bfloat162(h0, h1);
            *(__nv_bfloat162*)(p_att + TMD + dst) = __halves2bfloat162(lo0, lo1);
        }
        if (row0 + 8 < NTOK){
            size_t dst = ((size_t)tb*NTOK + row0 + 8)*D + h*EH + col;
            bf16 h2,lo2,h3,lo3;
            splitv(o[nt][2]*inv1, h2, lo2); splitv(o[nt][3]*inv1, h3, lo3);
            *(__nv_bfloat162*)(p_att + dst)       = __halves2bfloat162(h2, h3);
            *(__nv_bfloat162*)(p_att + TMD + dst) = __halves2bfloat162(lo2, lo3);
        }
    }
}

// ---------------- LayerNorm: one warp per row (D=256, 8 elems/lane) -------
__global__ __launch_bounds__(256) void ln_kernel(const bf16* __restrict__ xH,
                                                 const bf16* __restrict__ xL,
                                                 const bf16* __restrict__ sH,
                                                 const bf16* __restrict__ sL,
                                                 const float* __restrict__ g,
                                                 const float* __restrict__ beta,
                                                 bf16* __restrict__ pH,
                                                 bf16* __restrict__ pL){
    const int row  = blockIdx.x*8 + (threadIdx.x >> 5);
    const int lane = threadIdx.x & 31;
    size_t base = (size_t)row*D + lane*8;

    float v[8];
    {
        uint4 vh = *(const uint4*)(xH + base);
        uint4 vl = *(const uint4*)(xL + base);
        const __nv_bfloat162* ph = (const __nv_bfloat162*)&vh;
        const __nv_bfloat162* pl = (const __nv_bfloat162*)&vl;
        #pragma unroll
        for (int j = 0; j < 4; j++){
            float2 a = __bfloat1622float2(ph[j]);
            float2 b = __bfloat1622float2(pl[j]);
            v[2*j]   = a.x + b.x;
            v[2*j+1] = a.y + b.y;
        }
    }
    if (sH){
        uint4 wh = *(const uint4*)(sH + base);
        uint4 wl = *(const uint4*)(sL + base);
        const __nv_bfloat162* ph = (const __nv_bfloat162*)&wh;
        const __nv_bfloat162* pl = (const __nv_bfloat162*)&wl;
        #pragma unroll
        for (int j = 0; j < 4; j++){
            float2 a = __bfloat1622float2(ph[j]);
            float2 b = __bfloat1622float2(pl[j]);
            v[2*j]   -= a.x + b.x;
            v[2*j+1] -= a.y + b.y;
        }
    }

    float s = 0.f, ss = 0.f;
    #pragma unroll
    for (int j = 0; j < 8; j++){ s += v[j]; ss += v[j]*v[j]; }
    #pragma unroll
    for (int o = 16; o; o >>= 1){
        s  += __shfl_xor_sync(0xffffffffu, s,  o);
        ss += __shfl_xor_sync(0xffffffffu, ss, o);
    }
    float mean = s * (1.f/D);
    float var  = ss * (1.f/D) - mean*mean;
    float inv  = rsqrtf(var + EPS);

    float4 gg0 = *(const float4*)(g + lane*8);
    float4 gg1 = *(const float4*)(g + lane*8 + 4);
    float4 bb0 = *(const float4*)(beta + lane*8);
    float4 bb1 = *(const float4*)(beta + lane*8 + 4);
    float gv[8] = {gg0.x, gg0.y, gg0.z, gg0.w, gg1.x, gg1.y, gg1.z, gg1.w};
    float bv[8] = {bb0.x, bb0.y, bb0.z, bb0.w, bb1.x, bb1.y, bb1.z, bb1.w};

    uint4 oh, ol;
    __nv_bfloat162* qh = (__nv_bfloat162*)&oh;
    __nv_bfloat162* ql = (__nv_bfloat162*)&ol;
    #pragma unroll
    for (int j = 0; j < 4; j++){
        float o0 = (v[2*j]   - mean)*inv*gv[2*j]   + bv[2*j];
        float o1 = (v[2*j+1] - mean)*inv*gv[2*j+1] + bv[2*j+1];
        bf16 h0,l0,h1,l1; splitv(o0,h0,l0); splitv(o1,h1,l1);
        qh[j] = __halves2bfloat162(h0,h1);
        ql[j] = __halves2bfloat162(l0,l1);
    }
    *(uint4*)(pH + base) = oh;
    *(uint4*)(pL + base) = ol;
}

// ---------------- final: transpose + de-standardize + average scales ------
__global__ __launch_bounds__(256) void final_kernel(float* __restrict__ out){
    __shared__ float t0[32][33], t1[32][33];
    int b = blockIdx.z;
    int p0 = blockIdx.x*32, n0 = blockIdx.y*32;
    int tx = threadIdx.x & 31, ty = threadIdx.x >> 5;
    #pragma unroll
    for (int i = 0; i < 4; i++){
        int n = n0 + ty + i*8, pp = p0 + tx;
        if (n < ENC && pp < DB){
            t0[ty + i*8][tx] = g_out[((size_t)b*NTOK + n)*DB + pp];
            t1[ty + i*8][tx] = g_out[((size_t)(B_ + b)*NTOK + n)*DB + pp];
        }
    }
    __syncthreads();
    #pragma unroll
    for (int i = 0; i < 4; i++){
        int pp = p0 + ty + i*8, n = n0 + tx;
        if (pp < DB && n < ENC){
            float v0 = t0[tx][ty + i*8]*g_std[b*ENC + n]        + g_mean[b*ENC + n];
            float v1 = t1[tx][ty + i*8]*g_std[(B_ + b)*ENC + n] + g_mean[(B_ + b)*ENC + n];
            out[((size_t)b*DB + pp)*ENC + n] = 0.5f*(v0 + v1);
        }
    }
}

// ---------------- host ----------------
static inline int gsz(int nt){ return nt < 444 ? nt : 444; }
static void* sym(const void* s){ void* p; cudaGetSymbolAddress(&p, s); return p; }

extern "C" void kernel_launch(void* const* d_in, const int* in_sizes, int n_in,
                              void* d_out, int out_size){
    const float* mbx  = (const float*)d_in[0];
    const float* mbxm = (const float*)d_in[1];
    const float* embW = (const float*)d_in[4];
    const float* embB = (const float*)d_in[5];
    const float* Wq = (const float*)d_in[6];
    const float* Wk = (const float*)d_in[7];
    const float* Wv = (const float*)d_in[8];
    const float* Wo = (const float*)d_in[9];
    const float* W3 = (const float*)d_in[10];
    const float* W4 = (const float*)d_in[11];
    const float* bq = (const float*)d_in[12];
    const float* bk = (const float*)d_in[13];
    const float* bv = (const float*)d_in[14];
    const float* bo = (const float*)d_in[15];
    const float* b3 = (const float*)d_in[16];
    const float* b4 = (const float*)d_in[17];
    const float* W1 = (const float*)d_in[18];
    const float* b1 = (const float*)d_in[19];
    const float* W2 = (const float*)d_in[20];
    const float* b2 = (const float*)d_in[21];
    const float* W5 = (const float*)d_in[22];
    const float* b5 = (const float*)d_in[23];
    const float* W6 = (const float*)d_in[24];
    const float* b6 = (const float*)d_in[25];
    const float* ln1g = (const float*)d_in[26];
    const float* ln1b = (const float*)d_in[27];
    const float* ln2g = (const float*)d_in[28];
    const float* ln2b = (const float*)d_in[29];
    float* out = (float*)d_out;

    float* outF = (float*)sym(g_out);

    bf16* xinP = (bf16*)sym(p_xin);
    bf16* hP   = (bf16*)sym(p_h);
    bf16* qkvP = (bf16*)sym(p_qkv);
    bf16* attP = (bf16*)sym(p_att);
    bf16* xlnP = (bf16*)sym(p_xln);
    bf16* y1P  = (bf16*)sym(p_y1);
    bf16* xsP  = (bf16*)sym(p_xs);
    bf16* xattP = (bf16*)sym(p_xatt);
    bf16* yP   = (bf16*)sym(p_y);
    bf16* hhP  = (bf16*)sym(p_hh);
    bf16* embWP = (bf16*)sym(p_embW);
    bf16* WqP = (bf16*)sym(p_Wq); bf16* WkP = (bf16*)sym(p_Wk);
    bf16* WvP = (bf16*)sym(p_Wv); bf16* WoP = (bf16*)sym(p_Wo);
    bf16* W3P = (bf16*)sym(p_W3); bf16* W4P = (bf16*)sym(p_W4);
    bf16* W1P = (bf16*)sym(p_W1); bf16* W2P = (bf16*)sym(p_W2);
    bf16* W5P = (bf16*)sym(p_W5); bf16* W6P = (bf16*)sym(p_W6);

    const size_t EWN = (size_t)256*SEQP;
    const size_t WDD = (size_t)LAYERS*D*D;
    const size_t W1N = (size_t)LAYERS*DFF*D;
    const size_t W5N = (size_t)LAYERS*DB*2*D;
    const size_t Y1N = (size_t)TM*DFF;

    cudaFuncSetAttribute(mma_gemm<0>, cudaFuncAttributeMaxDynamicSharedMemorySize, 61440);
    cudaFuncSetAttribute(mma_gemm<1>, cudaFuncAttributeMaxDynamicSharedMemorySize, 61440);
    cudaFuncSetAttribute(mma_gemm<2>, cudaFuncAttributeMaxDynamicSharedMemorySize, 61440);
    cudaFuncSetAttribute(mma_gemm2<0>, cudaFuncAttributeMaxDynamicSharedMemorySize, 61440);
    cudaFuncSetAttribute(mma_gemm2<1>, cudaFuncAttributeMaxDynamicSharedMemorySize, 61440);

    // weight splits (one batched launch + embed pad)
    {
        WSArgs ws;
        const float* ss[10] = {Wq, Wk, Wv, Wo, W3, W4, W1, W2, W5, W6};
        bf16* hh[10] = {WqP, WkP, WvP, WoP, W3P, W4P, W1P, W2P, W5P, W6P};
        size_t nn[10] = {WDD, WDD, WDD, WDD, WDD, WDD, W1N, W1N, W5N, W5N};
        for (int i = 0; i < 10; i++){
            ws.s[i] = ss[i]; ws.h[i] = hh[i]; ws.l[i] = hh[i] + nn[i]; ws.n[i] = (int)nn[i];
        }
        wsplit_all<<<dim3(288, 10), 256>>>(ws);
        wsplit_pad<<<(unsigned)((EWN + 255)/256), 256>>>(embW, embWP, embWP + EWN, 256, SEQ, SEQP);
    }

    const int tm = 109;   // ceil(13856/128)
    const int tm64 = 217; // ceil(13856/64)

    stats_part<<<dim3((ENC + 255)/256, SCH, TS*B_), 256>>>(mbx);
    stats_fin<<<dim3((ENC + 255)/256, TS*B_), 256>>>();
    xin_kernel<<<dim3((SEQP + 31)/32, (NTOK + 31)/32, TS*B_), 256>>>(mbx, mbxm);

    {   // embed -> h planes
        GemmArgs a = {};
        a.aH[0] = xinP; a.aL[0] = xinP + TXN;
        a.wH[0] = embWP; a.wL[0] = embWP + EWN;
        a.bias[0] = embB;
        a.cH[0] = hP; a.cL[0] = hP + TMD;
        mma_gemm<0><<<gsz(tm*4), 256, 61440>>>(a, TM, D, SEQP, 4, tm*4, tm*4);
    }

    for (int l = 0; l < LAYERS; l++){
        {   // QKV -> planes
            GemmArgs a = {};
            for (int z = 0; z < 3; z++){
                a.aH[z] = hP; a.aL[z] = hP + TMD;
                a.cH[z] = qkvP + (size_t)z*TMD;
                a.cL[z] = qkvP + 3*TMD + (size_t)z*TMD;
            }
            a.wH[0] = WqP + (size_t)l*D*D; a.wL[0] = WqP + WDD + (size_t)l*D*D;
            a.wH[1] = WkP + (size_t)l*D*D; a.wL[1] = WkP + WDD + (size_t)l*D*D;
            a.wH[2] = WvP + (size_t)l*D*D; a.wL[2] = WvP + WDD + (size_t)l*D*D;
            a.bias[0] = bq + l*D; a.bias[1] = bk + l*D; a.bias[2] = bv + l*D;
            mma_gemm<0><<<gsz(tm*4*3), 256, 61440>>>(a, TM, D, D, 4, tm*4, tm*4*3);
        }

        flash_attn<<<dim3(7, TS*B_*NH), 256>>>();

        {   // Wo -> xatt planes
            GemmArgs a = {};
            a.aH[0] = attP; a.aL[0] = attP + TMD;
            a.wH[0] = WoP + (size_t)l*D*D; a.wL[0] = WoP + WDD + (size_t)l*D*D;
            a.bias[0] = bo + l*D;
            a.cH[0] = xattP; a.cL[0] = xattP + TMD;
            mma_gemm<0><<<gsz(tm*4), 256, 61440>>>(a, TM, D, D, 4, tm*4, tm*4);
        }

        // LN1: ln(h - xatt) -> xln planes  (warp-per-row)
        ln_kernel<<<TM/8, 256>>>(hP, hP + TMD, xattP, xattP + TMD,
                                 ln1g + l*D, ln1b + l*D, xlnP, xlnP + TMD);

        {   // W1 + GELU -> y1 planes
            GemmArgs a = {};
            a.aH[0] = xlnP; a.aL[0] = xlnP + TMD;
            a.wH[0] = W1P + (size_t)l*DFF*D; a.wL[0] = W1P + W1N + (size_t)l*DFF*D;
            a.bias[0] = b1 + l*DFF;
            a.cH[0] = y1P; a.cL[0] = y1P + Y1N;
            mma_gemm<1><<<gsz(tm*8), 256, 61440>>>(a, TM, DFF, D, 8, tm*8, tm*8);
        }
        {   // W2 -> y planes + xs=(xln-y) planes (sub fused, xln from planes)
            GemmArgs a = {};
            a.aH[0] = y1P; a.aL[0] = y1P + Y1N;
            a.wH[0] = W2P + (size_t)l*D*DFF; a.wL[0] = W2P + W1N + (size_t)l*D*DFF;
            a.bias[0] = b2 + l*D;
            a.cH[0] = yP; a.cL[0] = yP + TMD;
            a.xsH[0] = xlnP; a.xsL[0] = xlnP + TMD;
            a.c2H[0] = xsP; a.c2L[0] = xsP + TMD;
            mma_gemm<2><<<gsz(tm*4), 256, 61440>>>(a, TM, D, DFF, 4, tm*4, tm*4);
        }

        {   // fused W3/W4 -> hh planes = sigmoid(.)*(.)
            Gemm2Args a = {};
            a.a0H = xsP; a.a0L = xsP + TMD; a.a1H = xsP; a.a1L = xsP + TMD;
            a.kSplit = 1 << 30; a.aStride = D;
            a.w1H = W3P + (size_t)l*D*D; a.w1L = W3P + WDD + (size_t)l*D*D;
            a.w2H = W4P + (size_t)l*D*D; a.w2L = W4P + WDD + (size_t)l*D*D;
            a.b1 = b3 + l*D; a.b2 = b4 + l*D;
            a.cH = hhP; a.cL = hhP + TMD;
            mma_gemm2<0><<<gsz(tm64*4), 256, 61440>>>(a, TM, D, D, 4, tm64*4);
        }

        {   // fused W5/W6 over cat(xatt,y) -> g_out (with layer subtract)
            Gemm2Args a = {};
            a.a0H = xattP; a.a0L = xattP + TMD;
            a.a1H = yP;    a.a1L = yP + TMD;
            a.kSplit = D; a.aStride = D;
            a.w1H = W5P + (size_t)l*DB*2*D; a.w1L = W5P + W5N + (size_t)l*DB*2*D;
            a.w2H = W6P + (size_t)l*DB*2*D; a.w2L = W6P + W5N + (size_t)l*DB*2*D;
            a.b1 = b5 + l*DB; a.b2 = b6 + l*DB;
            a.Cout = outF; a.sub = l;
            mma_gemm2<1><<<gsz(tm64*12), 256, 61440>>>(a, TM, DB, 2*D, 12, tm64*12);
        }

        // LN2: ln(hh) -> h planes  (warp-per-row)
        ln_kernel<<<TM/8, 256>>>(hhP, hhP + TMD, (const bf16*)nullptr, (const bf16*)nullptr,
                                 ln2g + l*D, ln2b + l*D, hP, hP + TMD);
    }

    final_kernel<<<dim3((DB + 31)/32, (ENC + 31)/32, B_), 256>>>(out);
}